// round 1
// baseline (speedup 1.0000x reference)
#include <cuda_runtime.h>
#include <math.h>

#define D_EMBED 1024
#define N_HEADS 16
#define D_HEAD  64
#define N_B     2
#define N_S     2048
#define N_M     (N_B * N_S)   // 4096 rows

// ---------------- scratch (static device allocations; no cudaMalloc allowed) ----
__device__ float g_q[N_B * N_HEADS * N_S * D_HEAD];     // [BH, S, 64]
__device__ float g_k[N_B * N_HEADS * N_S * D_HEAD];
__device__ float g_v[N_B * N_HEADS * N_S * D_HEAD];
__device__ float g_ctx[(size_t)N_M * D_EMBED];          // merged-head ctx [M, D]
__device__ float g_x[(size_t)N_M * D_EMBED];            // pre-LN residual sum

// ---------------- GEMM: C[M,N] = A[M,K] @ W[N,K]^T + bias (+res), optional QKV remap
// M=4096, N=1024, K=1024. 128x128 tile, BK=16, 256 threads, 8x8 per thread.
__global__ __launch_bounds__(256, 2) void gemm128(
    const float* __restrict__ A, const float* __restrict__ W,
    const float* __restrict__ bias, const float* __restrict__ res,
    float* __restrict__ out, int qkv)
{
    __shared__ float As[16][132];
    __shared__ float Ws[16][132];
    const int K = D_EMBED;
    const int tid = threadIdx.x;
    const int bm = blockIdx.y * 128;
    const int bn = blockIdx.x * 128;

    const int lrow = tid >> 2;          // 0..63
    const int lcol = (tid & 3) << 2;    // 0,4,8,12
    const int tm = (tid >> 4) << 3;     // 0..120 step 8
    const int tn = (tid & 15) << 3;

    float acc[8][8];
#pragma unroll
    for (int i = 0; i < 8; i++)
#pragma unroll
        for (int j = 0; j < 8; j++) acc[i][j] = 0.0f;

    for (int k0 = 0; k0 < K; k0 += 16) {
#pragma unroll
        for (int t = 0; t < 2; t++) {
            int r = lrow + t * 64;
            float4 a = *(const float4*)(A + (size_t)(bm + r) * K + k0 + lcol);
            As[lcol + 0][r] = a.x; As[lcol + 1][r] = a.y;
            As[lcol + 2][r] = a.z; As[lcol + 3][r] = a.w;
            float4 w = *(const float4*)(W + (size_t)(bn + r) * K + k0 + lcol);
            Ws[lcol + 0][r] = w.x; Ws[lcol + 1][r] = w.y;
            Ws[lcol + 2][r] = w.z; Ws[lcol + 3][r] = w.w;
        }
        __syncthreads();
#pragma unroll
        for (int kk = 0; kk < 16; kk++) {
            float4 a0 = *(const float4*)&As[kk][tm];
            float4 a1 = *(const float4*)&As[kk][tm + 4];
            float4 b0 = *(const float4*)&Ws[kk][tn];
            float4 b1 = *(const float4*)&Ws[kk][tn + 4];
            float ra[8] = {a0.x, a0.y, a0.z, a0.w, a1.x, a1.y, a1.z, a1.w};
            float rb[8] = {b0.x, b0.y, b0.z, b0.w, b1.x, b1.y, b1.z, b1.w};
#pragma unroll
            for (int i = 0; i < 8; i++)
#pragma unroll
                for (int j = 0; j < 8; j++)
                    acc[i][j] = fmaf(ra[i], rb[j], acc[i][j]);
        }
        __syncthreads();
    }

#pragma unroll
    for (int i = 0; i < 8; i++) {
        int m = bm + tm + i;
        int b = m / N_S, s = m % N_S;
#pragma unroll
        for (int j = 0; j < 8; j++) {
            int n = bn + tn + j;
            float v = acc[i][j] + bias[n];
            if (res) v += res[(size_t)m * D_EMBED + n];
            if (qkv) {
                int h = n >> 6, d = n & 63;
                out[(((size_t)(b * N_HEADS + h)) * N_S + s) * D_HEAD + d] = v;
            } else {
                out[(size_t)m * D_EMBED + n] = v;
            }
        }
    }
}

// ---------------- flash attention, fp32, BQ=BK=64 -------------------------------
// Q/K/V: [BH, S, 64]. ctx out: merged [M, D_EMBED].
// Thread layout: 256 thr = 16(ty) x 16(tx). QK: rows ty*4+i, S-cols tx+16j
// (strided so Ks row reads hit 8 distinct 16B bank groups -> conflict-free).
// PV: rows ty*4+i, out-cols tx*4+c (Vs read row-shared -> conflict-free).
#define APAD 68
#define ATTN_SMEM ((3 * 64 * APAD + 64) * 4)

__global__ __launch_bounds__(256) void attn64(
    const float* __restrict__ Q, const float* __restrict__ Kg,
    const float* __restrict__ V, const float* __restrict__ mask,
    float* __restrict__ ctx)
{
    extern __shared__ float sm[];
    float* Qs = sm;                    // [64][APAD]
    float* Ks = Qs + 64 * APAD;        // [64][APAD]  (aliased as Ps after QK)
    float* Vs = Ks + 64 * APAD;        // [64][APAD]
    float* mt = Vs + 64 * APAD;        // [64]

    const int bh = blockIdx.x;             // 0..31
    const int qt = blockIdx.y;             // 0..31
    const int b = bh / N_HEADS;
    const int h = bh % N_HEADS;
    const int tid = threadIdx.x;
    const int tx = tid & 15;
    const int ty = tid >> 4;

    // load Q tile
    const float* Qp = Q + ((size_t)bh * N_S + qt * 64) * D_HEAD;
#pragma unroll
    for (int t = 0; t < 4; t++) {
        int idx = tid + t * 256;
        int r = idx >> 4, c = (idx & 15) << 2;
        *(float4*)&Qs[r * APAD + c] = *(const float4*)(Qp + r * D_HEAD + c);
    }

    float4 acc[4];
    float m_run[4], l_run[4];
#pragma unroll
    for (int i = 0; i < 4; i++) {
        acc[i] = make_float4(0.f, 0.f, 0.f, 0.f);
        m_run[i] = -3.0e38f;
        l_run[i] = 0.0f;
    }

    const float* Kbase = Kg + (size_t)bh * N_S * D_HEAD;
    const float* Vbase = V + (size_t)bh * N_S * D_HEAD;
    const float scale = 0.125f;  // 1/sqrt(64)

    for (int kt = 0; kt < N_S / 64; kt++) {
        const float* Kp = Kbase + kt * 64 * D_HEAD;
        const float* Vp = Vbase + kt * 64 * D_HEAD;
        __syncthreads();   // prior PV done before overwriting Ks/Vs
#pragma unroll
        for (int t = 0; t < 4; t++) {
            int idx = tid + t * 256;
            int r = idx >> 4, c = (idx & 15) << 2;
            *(float4*)&Ks[r * APAD + c] = *(const float4*)(Kp + r * D_HEAD + c);
            *(float4*)&Vs[r * APAD + c] = *(const float4*)(Vp + r * D_HEAD + c);
        }
        if (tid < 64)
            mt[tid] = (1.0f - mask[b * N_S + kt * 64 + tid]) * (-100000.0f);
        __syncthreads();

        // ---- S = Q @ K^T ---- (cols c_j = tx + 16j)
        float s[4][4];
#pragma unroll
        for (int i = 0; i < 4; i++)
#pragma unroll
            for (int j = 0; j < 4; j++) s[i][j] = 0.0f;

#pragma unroll
        for (int d = 0; d < 64; d += 4) {
            float4 q0 = *(const float4*)&Qs[(ty * 4 + 0) * APAD + d];
            float4 q1 = *(const float4*)&Qs[(ty * 4 + 1) * APAD + d];
            float4 q2 = *(const float4*)&Qs[(ty * 4 + 2) * APAD + d];
            float4 q3 = *(const float4*)&Qs[(ty * 4 + 3) * APAD + d];
            float4 k0 = *(const float4*)&Ks[(tx + 0) * APAD + d];
            float4 k1 = *(const float4*)&Ks[(tx + 16) * APAD + d];
            float4 k2 = *(const float4*)&Ks[(tx + 32) * APAD + d];
            float4 k3 = *(const float4*)&Ks[(tx + 48) * APAD + d];
            float4 qa[4] = {q0, q1, q2, q3};
            float4 ka[4] = {k0, k1, k2, k3};
#pragma unroll
            for (int i = 0; i < 4; i++)
#pragma unroll
                for (int j = 0; j < 4; j++) {
                    s[i][j] = fmaf(qa[i].x, ka[j].x, s[i][j]);
                    s[i][j] = fmaf(qa[i].y, ka[j].y, s[i][j]);
                    s[i][j] = fmaf(qa[i].z, ka[j].z, s[i][j]);
                    s[i][j] = fmaf(qa[i].w, ka[j].w, s[i][j]);
                }
        }

        float mtj[4];
#pragma unroll
        for (int j = 0; j < 4; j++) mtj[j] = mt[tx + 16 * j];

        // ---- online softmax ----
#pragma unroll
        for (int i = 0; i < 4; i++) {
            float mx = -3.0e38f;
#pragma unroll
            for (int j = 0; j < 4; j++) {
                s[i][j] = s[i][j] * scale + mtj[j];
                mx = fmaxf(mx, s[i][j]);
            }
#pragma unroll
            for (int o = 8; o >= 1; o >>= 1)
                mx = fmaxf(mx, __shfl_xor_sync(0xffffffffu, mx, o));
            float mnew = fmaxf(m_run[i], mx);
            float alpha = __expf(m_run[i] - mnew);
            float sum = 0.0f;
#pragma unroll
            for (int j = 0; j < 4; j++) {
                s[i][j] = __expf(s[i][j] - mnew);
                sum += s[i][j];
            }
#pragma unroll
            for (int o = 8; o >= 1; o >>= 1)
                sum += __shfl_xor_sync(0xffffffffu, sum, o);
            l_run[i] = l_run[i] * alpha + sum;
            m_run[i] = mnew;
            acc[i].x *= alpha; acc[i].y *= alpha;
            acc[i].z *= alpha; acc[i].w *= alpha;
        }

        __syncthreads();   // everyone done reading K tile
        // store P into Ks region (conflict-free scalar stores)
#pragma unroll
        for (int i = 0; i < 4; i++)
#pragma unroll
            for (int j = 0; j < 4; j++)
                Ks[(ty * 4 + i) * APAD + tx + 16 * j] = s[i][j];
        __syncthreads();

        // ---- O += P @ V ---- (out cols tx*4..tx*4+3)
#pragma unroll
        for (int j = 0; j < 64; j += 4) {
            float4 p0 = *(const float4*)&Ks[(ty * 4 + 0) * APAD + j];
            float4 p1 = *(const float4*)&Ks[(ty * 4 + 1) * APAD + j];
            float4 p2 = *(const float4*)&Ks[(ty * 4 + 2) * APAD + j];
            float4 p3 = *(const float4*)&Ks[(ty * 4 + 3) * APAD + j];
            float4 v0 = *(const float4*)&Vs[(j + 0) * APAD + tx * 4];
            float4 v1 = *(const float4*)&Vs[(j + 1) * APAD + tx * 4];
            float4 v2 = *(const float4*)&Vs[(j + 2) * APAD + tx * 4];
            float4 v3 = *(const float4*)&Vs[(j + 3) * APAD + tx * 4];
            float4 pa[4] = {p0, p1, p2, p3};
#pragma unroll
            for (int i = 0; i < 4; i++) {
                acc[i].x = fmaf(pa[i].x, v0.x, acc[i].x);
                acc[i].x = fmaf(pa[i].y, v1.x, acc[i].x);
                acc[i].x = fmaf(pa[i].z, v2.x, acc[i].x);
                acc[i].x = fmaf(pa[i].w, v3.x, acc[i].x);
                acc[i].y = fmaf(pa[i].x, v0.y, acc[i].y);
                acc[i].y = fmaf(pa[i].y, v1.y, acc[i].y);
                acc[i].y = fmaf(pa[i].z, v2.y, acc[i].y);
                acc[i].y = fmaf(pa[i].w, v3.y, acc[i].y);
                acc[i].z = fmaf(pa[i].x, v0.z, acc[i].z);
                acc[i].z = fmaf(pa[i].y, v1.z, acc[i].z);
                acc[i].z = fmaf(pa[i].z, v2.z, acc[i].z);
                acc[i].z = fmaf(pa[i].w, v3.z, acc[i].z);
                acc[i].w = fmaf(pa[i].x, v0.w, acc[i].w);
                acc[i].w = fmaf(pa[i].y, v1.w, acc[i].w);
                acc[i].w = fmaf(pa[i].z, v2.w, acc[i].w);
                acc[i].w = fmaf(pa[i].w, v3.w, acc[i].w);
            }
        }
    }

    // ---- epilogue: O /= l, write merged-head ctx ----
#pragma unroll
    for (int i = 0; i < 4; i++) {
        float inv = 1.0f / l_run[i];
        int row = qt * 64 + ty * 4 + i;
        size_t off = ((size_t)(b * N_S + row)) * D_EMBED + h * D_HEAD + tx * 4;
        float4 o = make_float4(acc[i].x * inv, acc[i].y * inv,
                               acc[i].z * inv, acc[i].w * inv);
        *(float4*)(ctx + off) = o;
    }
}

// ---------------- LayerNorm: one block per row ----------------------------------
__global__ __launch_bounds__(256) void ln_kernel(
    const float* __restrict__ X, const float* __restrict__ g,
    const float* __restrict__ be, float* __restrict__ out)
{
    __shared__ float red[8];
    const int row = blockIdx.x;
    const int tid = threadIdx.x;
    const float* xr = X + (size_t)row * D_EMBED;
    float4 v = *(const float4*)(xr + tid * 4);
    float s = (v.x + v.y) + (v.z + v.w);
#pragma unroll
    for (int o = 16; o >= 1; o >>= 1) s += __shfl_xor_sync(0xffffffffu, s, o);
    if ((tid & 31) == 0) red[tid >> 5] = s;
    __syncthreads();
    float tot = red[0] + red[1] + red[2] + red[3] +
                red[4] + red[5] + red[6] + red[7];
    float mu = tot * (1.0f / D_EMBED);
    float d0 = v.x - mu, d1 = v.y - mu, d2 = v.z - mu, d3 = v.w - mu;
    float sq = d0 * d0 + d1 * d1 + d2 * d2 + d3 * d3;
#pragma unroll
    for (int o = 16; o >= 1; o >>= 1) sq += __shfl_xor_sync(0xffffffffu, sq, o);
    __syncthreads();
    if ((tid & 31) == 0) red[tid >> 5] = sq;
    __syncthreads();
    float var = (red[0] + red[1] + red[2] + red[3] +
                 red[4] + red[5] + red[6] + red[7]) * (1.0f / D_EMBED);
    float r = rsqrtf(var + 1e-12f);
    float4 gv = *(const float4*)(g + tid * 4);
    float4 bv = *(const float4*)(be + tid * 4);
    float4 o;
    o.x = d0 * r * gv.x + bv.x;
    o.y = d1 * r * gv.y + bv.y;
    o.z = d2 * r * gv.z + bv.z;
    o.w = d3 * r * gv.w + bv.w;
    *(float4*)(out + (size_t)row * D_EMBED + tid * 4) = o;
}

// ---------------- launch ---------------------------------------------------------
extern "C" void kernel_launch(void* const* d_in, const int* in_sizes, int n_in,
                              void* d_out, int out_size)
{
    const float* X     = (const float*)d_in[0];
    const float* mask  = (const float*)d_in[1];
    const float* Wq    = (const float*)d_in[2];
    const float* bq    = (const float*)d_in[3];
    const float* Wk    = (const float*)d_in[4];
    const float* bk    = (const float*)d_in[5];
    const float* Wv    = (const float*)d_in[6];
    const float* bv    = (const float*)d_in[7];
    const float* Wo    = (const float*)d_in[8];
    const float* bo    = (const float*)d_in[9];
    const float* gamma = (const float*)d_in[10];
    const float* beta  = (const float*)d_in[11];
    float* out = (float*)d_out;

    float *q, *k, *v, *ctx, *x;
    cudaGetSymbolAddress((void**)&q, g_q);
    cudaGetSymbolAddress((void**)&k, g_k);
    cudaGetSymbolAddress((void**)&v, g_v);
    cudaGetSymbolAddress((void**)&ctx, g_ctx);
    cudaGetSymbolAddress((void**)&x, g_x);

    cudaFuncSetAttribute(attn64, cudaFuncAttributeMaxDynamicSharedMemorySize,
                         ATTN_SMEM);

    dim3 ggrid(D_EMBED / 128, N_M / 128);   // (8, 32)
    gemm128<<<ggrid, 256>>>(X, Wq, bq, nullptr, q, 1);
    gemm128<<<ggrid, 256>>>(X, Wk, bk, nullptr, k, 1);
    gemm128<<<ggrid, 256>>>(X, Wv, bv, nullptr, v, 1);
    attn64<<<dim3(N_B * N_HEADS, N_S / 64), 256, ATTN_SMEM>>>(q, k, v, mask, ctx);
    gemm128<<<ggrid, 256>>>(ctx, Wo, bo, X, x, 0);
    ln_kernel<<<N_M, 256>>>(x, gamma, beta, out);
}

// round 3
// speedup vs baseline: 1.3968x; 1.3968x over previous
#include <cuda_runtime.h>
#include <cuda_bf16.h>
#include <cstdint>
#include <math.h>

#define D_EMBED 1024
#define N_HEADS 16
#define D_HEAD  64
#define N_B     2
#define N_S     2048
#define N_M     (N_B * N_S)   // 4096 rows

// ---------------- scratch (16B-aligned for cp.async) -------------------------
__device__ __align__(16) float g_q[N_B * N_HEADS * N_S * D_HEAD];
__device__ __align__(16) float g_k[N_B * N_HEADS * N_S * D_HEAD];
__device__ __align__(16) float g_v[N_B * N_HEADS * N_S * D_HEAD];
__device__ __align__(16) float g_x[(size_t)N_M * D_EMBED];
__device__ __align__(16) __nv_bfloat16 g_xhi[(size_t)N_M * D_EMBED];
__device__ __align__(16) __nv_bfloat16 g_xlo[(size_t)N_M * D_EMBED];
__device__ __align__(16) __nv_bfloat16 g_chi[(size_t)N_M * D_EMBED];
__device__ __align__(16) __nv_bfloat16 g_clo[(size_t)N_M * D_EMBED];
__device__ __align__(16) __nv_bfloat16 g_whi[4 * D_EMBED * D_EMBED];
__device__ __align__(16) __nv_bfloat16 g_wlo[4 * D_EMBED * D_EMBED];

// ---------------- helpers -----------------------------------------------------
__device__ __forceinline__ uint32_t s2u(const void* p) {
    uint32_t a;
    asm("{ .reg .u64 t; cvta.to.shared.u64 t, %1; cvt.u32.u64 %0, t; }"
        : "=r"(a) : "l"(p));
    return a;
}
__device__ __forceinline__ void cp16(uint32_t dst, const void* src) {
    asm volatile("cp.async.cg.shared.global [%0], [%1], 16;"
                 :: "r"(dst), "l"(src) : "memory");
}
#define CP_COMMIT() asm volatile("cp.async.commit_group;" ::: "memory")
#define CP_WAIT2()  asm volatile("cp.async.wait_group 2;" ::: "memory")

#define LDM_X4(r0, r1, r2, r3, addr) \
    asm volatile("ldmatrix.sync.aligned.m8n8.x4.shared.b16 {%0,%1,%2,%3}, [%4];" \
                 : "=r"(r0), "=r"(r1), "=r"(r2), "=r"(r3) : "r"(addr))

#define MMA_BF16(c, a, b) \
    asm volatile( \
        "mma.sync.aligned.m16n8k16.row.col.f32.bf16.bf16.f32 " \
        "{%0,%1,%2,%3}, {%4,%5,%6,%7}, {%8,%9}, {%0,%1,%2,%3};" \
        : "+f"((c)[0]), "+f"((c)[1]), "+f"((c)[2]), "+f"((c)[3]) \
        : "r"((a)[0]), "r"((a)[1]), "r"((a)[2]), "r"((a)[3]), \
          "r"((b)[0]), "r"((b)[1]))

// ---------------- split: fp32 -> (bf16 hi, bf16 lo) ---------------------------
__global__ __launch_bounds__(256) void split_bf16(
    const float* __restrict__ src, __nv_bfloat16* __restrict__ hi,
    __nv_bfloat16* __restrict__ lo, int n4)
{
    int i = blockIdx.x * blockDim.x + threadIdx.x;
    if (i >= n4) return;
    float4 v = ((const float4*)src)[i];
    __nv_bfloat16 h0 = __float2bfloat16(v.x);
    __nv_bfloat16 h1 = __float2bfloat16(v.y);
    __nv_bfloat16 h2 = __float2bfloat16(v.z);
    __nv_bfloat16 h3 = __float2bfloat16(v.w);
    __nv_bfloat162 ph0, ph1, pl0, pl1;
    ph0.x = h0; ph0.y = h1; ph1.x = h2; ph1.y = h3;
    pl0.x = __float2bfloat16(v.x - __bfloat162float(h0));
    pl0.y = __float2bfloat16(v.y - __bfloat162float(h1));
    pl1.x = __float2bfloat16(v.z - __bfloat162float(h2));
    pl1.y = __float2bfloat16(v.w - __bfloat162float(h3));
    ((__nv_bfloat162*)hi)[2 * i + 0] = ph0;
    ((__nv_bfloat162*)hi)[2 * i + 1] = ph1;
    ((__nv_bfloat162*)lo)[2 * i + 0] = pl0;
    ((__nv_bfloat162*)lo)[2 * i + 1] = pl1;
}

// ---------------- bf16-split tensor GEMM ---------------------------------------
// C[M,N] = A[M,K] @ W[N,K]^T (+bias)(+res). A,W given as bf16 hi/lo pairs.
// 128x128 CTA tile, 8 warps (2x4), warp tile 64x32, BK=32, 3-stage cp.async.
// Smem rows padded to 80B so ldmatrix's 8 row-addresses hit 8 distinct 16B groups.
#define PADROW 40                       // bf16 elements per smem row (80B)
#define BUF_B  (128 * 80)               // one operand buffer: 10240B
#define STAGE_B (4 * BUF_B)             // Ahi,Alo,Bhi,Blo: 40960B
#define GSTAGES 3
#define GEMM_SMEM (GSTAGES * STAGE_B)   // 122880B

__device__ __forceinline__ void load_stage(
    uint32_t st, const __nv_bfloat16* Ahi, const __nv_bfloat16* Alo,
    const __nv_bfloat16* Bhi, const __nv_bfloat16* Blo,
    int bm, int bn, int kb, int tid)
{
    const __nv_bfloat16* srcs[4] = {Ahi, Alo, Bhi, Blo};
    const int rowoff[4] = {bm, bm, bn, bn};
#pragma unroll
    for (int bf = 0; bf < 4; bf++) {
        const __nv_bfloat16* sb = srcs[bf] + (size_t)rowoff[bf] * D_EMBED + kb * 32;
        uint32_t db = st + bf * BUF_B;
#pragma unroll
        for (int i = 0; i < 2; i++) {
            int c = tid + i * 256;          // 0..511
            int row = c >> 2, kc = c & 3;   // 4 x 16B chunks per 64B row
            cp16(db + row * 80 + kc * 16, sb + (size_t)row * D_EMBED + kc * 8);
        }
    }
}

__global__ __launch_bounds__(256, 1) void gemm_mma(
    const __nv_bfloat16* __restrict__ Ahi, const __nv_bfloat16* __restrict__ Alo,
    const __nv_bfloat16* __restrict__ Bhi, const __nv_bfloat16* __restrict__ Blo,
    const float* __restrict__ bias, const float* __restrict__ res,
    float* __restrict__ out, int qkv)
{
    extern __shared__ char smraw[];
    const uint32_t smb = s2u(smraw);
    const int tid = threadIdx.x;
    const int lane = tid & 31;
    const int wid = tid >> 5;
    const int warp_m = (wid >> 2) * 64;   // 0 or 64
    const int warp_n = (wid & 3) * 32;    // 0,32,64,96
    const int bm = blockIdx.y * 128;
    const int bn = blockIdx.x * 128;

    float c[4][4][4];
#pragma unroll
    for (int mi = 0; mi < 4; mi++)
#pragma unroll
        for (int ni = 0; ni < 4; ni++)
#pragma unroll
            for (int e = 0; e < 4; e++) c[mi][ni][e] = 0.0f;

    // prologue
#pragma unroll
    for (int p = 0; p < GSTAGES; p++) {
        load_stage(smb + p * STAGE_B, Ahi, Alo, Bhi, Blo, bm, bn, p, tid);
        CP_COMMIT();
    }

    // ldmatrix per-lane address components
    const uint32_t a_row = lane & 15;                 // + ((lane>>4)? col+8)
    const uint32_t a_coff = (lane >> 4) * 16;         // bytes: 8 elems * 2
    const uint32_t b_row = (lane & 7) + ((lane >> 4) << 3);
    const uint32_t b_coff = ((lane >> 3) & 1) * 16;

    int s = 0;
    for (int kb = 0; kb < D_EMBED / 32; kb++) {
        CP_WAIT2();
        __syncthreads();
        uint32_t st = smb + s * STAGE_B;
        uint32_t ah_b = st, al_b = st + BUF_B;
        uint32_t bh_b = st + 2 * BUF_B, bl_b = st + 3 * BUF_B;

#pragma unroll
        for (int k16 = 0; k16 < 2; k16++) {
            uint32_t akoff = k16 * 32 + a_coff;   // bytes
            uint32_t bkoff = k16 * 32 + b_coff;
            uint32_t ah[4][4], al[4][4], bh[4][2], bl[4][2];
#pragma unroll
            for (int mi = 0; mi < 4; mi++) {
                uint32_t ro = (warp_m + mi * 16 + a_row) * 80 + akoff;
                LDM_X4(ah[mi][0], ah[mi][1], ah[mi][2], ah[mi][3], ah_b + ro);
                LDM_X4(al[mi][0], al[mi][1], al[mi][2], al[mi][3], al_b + ro);
            }
#pragma unroll
            for (int ni2 = 0; ni2 < 2; ni2++) {
                uint32_t ro = (warp_n + ni2 * 16 + b_row) * 80 + bkoff;
                LDM_X4(bh[ni2 * 2][0], bh[ni2 * 2][1],
                       bh[ni2 * 2 + 1][0], bh[ni2 * 2 + 1][1], bh_b + ro);
                LDM_X4(bl[ni2 * 2][0], bl[ni2 * 2][1],
                       bl[ni2 * 2 + 1][0], bl[ni2 * 2 + 1][1], bl_b + ro);
            }
#pragma unroll
            for (int mi = 0; mi < 4; mi++)
#pragma unroll
                for (int ni = 0; ni < 4; ni++) {
                    MMA_BF16(c[mi][ni], ah[mi], bh[ni]);
                    MMA_BF16(c[mi][ni], ah[mi], bl[ni]);
                    MMA_BF16(c[mi][ni], al[mi], bh[ni]);
                }
        }
        __syncthreads();
        if (kb + GSTAGES < D_EMBED / 32)
            load_stage(st, Ahi, Alo, Bhi, Blo, bm, bn, kb + GSTAGES, tid);
        CP_COMMIT();
        s++; if (s == GSTAGES) s = 0;
    }

    // epilogue: c[mi][ni]: rows bm+warp_m+mi*16+(lane>>2)(+8), cols bn+warp_n+ni*8+2*(lane&3)
#pragma unroll
    for (int mi = 0; mi < 4; mi++) {
#pragma unroll
        for (int half = 0; half < 2; half++) {
            int m = bm + warp_m + mi * 16 + (lane >> 2) + half * 8;
            int bb = m >> 11, sdx = m & (N_S - 1);
#pragma unroll
            for (int ni = 0; ni < 4; ni++) {
                int n = bn + warp_n + ni * 8 + 2 * (lane & 3);
                float2 o;
                o.x = c[mi][ni][half * 2 + 0] + bias[n];
                o.y = c[mi][ni][half * 2 + 1] + bias[n + 1];
                if (res) {
                    float2 rv = *(const float2*)(res + (size_t)m * D_EMBED + n);
                    o.x += rv.x; o.y += rv.y;
                }
                if (qkv) {
                    int h = n >> 6, d = n & 63;
                    *(float2*)(out + (((size_t)(bb * N_HEADS + h)) * N_S + sdx) * D_HEAD + d) = o;
                } else {
                    *(float2*)(out + (size_t)m * D_EMBED + n) = o;
                }
            }
        }
    }
}

// ---------------- flash attention, fp32 SIMT (bf16 hi/lo epilogue) -------------
#define APAD 68
#define ATTN_SMEM ((3 * 64 * APAD + 64) * 4)

__global__ __launch_bounds__(256) void attn64(
    const float* __restrict__ Q, const float* __restrict__ Kg,
    const float* __restrict__ V, const float* __restrict__ mask,
    __nv_bfloat16* __restrict__ ctx_hi, __nv_bfloat16* __restrict__ ctx_lo)
{
    extern __shared__ float sm[];
    float* Qs = sm;
    float* Ks = Qs + 64 * APAD;
    float* Vs = Ks + 64 * APAD;
    float* mt = Vs + 64 * APAD;

    const int bh = blockIdx.x;
    const int qt = blockIdx.y;
    const int b = bh / N_HEADS;
    const int h = bh % N_HEADS;
    const int tid = threadIdx.x;
    const int tx = tid & 15;
    const int ty = tid >> 4;

    const float* Qp = Q + ((size_t)bh * N_S + qt * 64) * D_HEAD;
#pragma unroll
    for (int t = 0; t < 4; t++) {
        int idx = tid + t * 256;
        int r = idx >> 4, c = (idx & 15) << 2;
        *(float4*)&Qs[r * APAD + c] = *(const float4*)(Qp + r * D_HEAD + c);
    }

    float4 acc[4];
    float m_run[4], l_run[4];
#pragma unroll
    for (int i = 0; i < 4; i++) {
        acc[i] = make_float4(0.f, 0.f, 0.f, 0.f);
        m_run[i] = -3.0e38f;
        l_run[i] = 0.0f;
    }

    const float* Kbase = Kg + (size_t)bh * N_S * D_HEAD;
    const float* Vbase = V + (size_t)bh * N_S * D_HEAD;
    const float scale = 0.125f;

    for (int kt = 0; kt < N_S / 64; kt++) {
        const float* Kp = Kbase + kt * 64 * D_HEAD;
        const float* Vp = Vbase + kt * 64 * D_HEAD;
        __syncthreads();
#pragma unroll
        for (int t = 0; t < 4; t++) {
            int idx = tid + t * 256;
            int r = idx >> 4, c = (idx & 15) << 2;
            *(float4*)&Ks[r * APAD + c] = *(const float4*)(Kp + r * D_HEAD + c);
            *(float4*)&Vs[r * APAD + c] = *(const float4*)(Vp + r * D_HEAD + c);
        }
        if (tid < 64)
            mt[tid] = (1.0f - mask[b * N_S + kt * 64 + tid]) * (-100000.0f);
        __syncthreads();

        float s[4][4];
#pragma unroll
        for (int i = 0; i < 4; i++)
#pragma unroll
            for (int j = 0; j < 4; j++) s[i][j] = 0.0f;

#pragma unroll
        for (int d = 0; d < 64; d += 4) {
            float4 q0 = *(const float4*)&Qs[(ty * 4 + 0) * APAD + d];
            float4 q1 = *(const float4*)&Qs[(ty * 4 + 1) * APAD + d];
            float4 q2 = *(const float4*)&Qs[(ty * 4 + 2) * APAD + d];
            float4 q3 = *(const float4*)&Qs[(ty * 4 + 3) * APAD + d];
            float4 k0 = *(const float4*)&Ks[(tx + 0) * APAD + d];
            float4 k1 = *(const float4*)&Ks[(tx + 16) * APAD + d];
            float4 k2 = *(const float4*)&Ks[(tx + 32) * APAD + d];
            float4 k3 = *(const float4*)&Ks[(tx + 48) * APAD + d];
            float4 qa[4] = {q0, q1, q2, q3};
            float4 ka[4] = {k0, k1, k2, k3};
#pragma unroll
            for (int i = 0; i < 4; i++)
#pragma unroll
                for (int j = 0; j < 4; j++) {
                    s[i][j] = fmaf(qa[i].x, ka[j].x, s[i][j]);
                    s[i][j] = fmaf(qa[i].y, ka[j].y, s[i][j]);
                    s[i][j] = fmaf(qa[i].z, ka[j].z, s[i][j]);
                    s[i][j] = fmaf(qa[i].w, ka[j].w, s[i][j]);
                }
        }

        float mtj[4];
#pragma unroll
        for (int j = 0; j < 4; j++) mtj[j] = mt[tx + 16 * j];

#pragma unroll
        for (int i = 0; i < 4; i++) {
            float mx = -3.0e38f;
#pragma unroll
            for (int j = 0; j < 4; j++) {
                s[i][j] = s[i][j] * scale + mtj[j];
                mx = fmaxf(mx, s[i][j]);
            }
#pragma unroll
            for (int o = 8; o >= 1; o >>= 1)
                mx = fmaxf(mx, __shfl_xor_sync(0xffffffffu, mx, o));
            float mnew = fmaxf(m_run[i], mx);
            float alpha = __expf(m_run[i] - mnew);
            float sum = 0.0f;
#pragma unroll
            for (int j = 0; j < 4; j++) {
                s[i][j] = __expf(s[i][j] - mnew);
                sum += s[i][j];
            }
#pragma unroll
            for (int o = 8; o >= 1; o >>= 1)
                sum += __shfl_xor_sync(0xffffffffu, sum, o);
            l_run[i] = l_run[i] * alpha + sum;
            m_run[i] = mnew;
            acc[i].x *= alpha; acc[i].y *= alpha;
            acc[i].z *= alpha; acc[i].w *= alpha;
        }

        __syncthreads();
#pragma unroll
        for (int i = 0; i < 4; i++)
#pragma unroll
            for (int j = 0; j < 4; j++)
                Ks[(ty * 4 + i) * APAD + tx + 16 * j] = s[i][j];
        __syncthreads();

#pragma unroll
        for (int j = 0; j < 64; j += 4) {
            float4 p0 = *(const float4*)&Ks[(ty * 4 + 0) * APAD + j];
            float4 p1 = *(const float4*)&Ks[(ty * 4 + 1) * APAD + j];
            float4 p2 = *(const float4*)&Ks[(ty * 4 + 2) * APAD + j];
            float4 p3 = *(const float4*)&Ks[(ty * 4 + 3) * APAD + j];
            float4 v0 = *(const float4*)&Vs[(j + 0) * APAD + tx * 4];
            float4 v1 = *(const float4*)&Vs[(j + 1) * APAD + tx * 4];
            float4 v2 = *(const float4*)&Vs[(j + 2) * APAD + tx * 4];
            float4 v3 = *(const float4*)&Vs[(j + 3) * APAD + tx * 4];
            float4 pa[4] = {p0, p1, p2, p3};
#pragma unroll
            for (int i = 0; i < 4; i++) {
                acc[i].x = fmaf(pa[i].x, v0.x, acc[i].x);
                acc[i].x = fmaf(pa[i].y, v1.x, acc[i].x);
                acc[i].x = fmaf(pa[i].z, v2.x, acc[i].x);
                acc[i].x = fmaf(pa[i].w, v3.x, acc[i].x);
                acc[i].y = fmaf(pa[i].x, v0.y, acc[i].y);
                acc[i].y = fmaf(pa[i].y, v1.y, acc[i].y);
                acc[i].y = fmaf(pa[i].z, v2.y, acc[i].y);
                acc[i].y = fmaf(pa[i].w, v3.y, acc[i].y);
                acc[i].z = fmaf(pa[i].x, v0.z, acc[i].z);
                acc[i].z = fmaf(pa[i].y, v1.z, acc[i].z);
                acc[i].z = fmaf(pa[i].z, v2.z, acc[i].z);
                acc[i].z = fmaf(pa[i].w, v3.z, acc[i].z);
                acc[i].w = fmaf(pa[i].x, v0.w, acc[i].w);
                acc[i].w = fmaf(pa[i].y, v1.w, acc[i].w);
                acc[i].w = fmaf(pa[i].z, v2.w, acc[i].w);
                acc[i].w = fmaf(pa[i].w, v3.w, acc[i].w);
            }
        }
    }

#pragma unroll
    for (int i = 0; i < 4; i++) {
        float inv = 1.0f / l_run[i];
        int row = qt * 64 + ty * 4 + i;
        size_t off = ((size_t)(b * N_S + row)) * D_EMBED + h * D_HEAD + tx * 4;
        float o0 = acc[i].x * inv, o1 = acc[i].y * inv;
        float o2 = acc[i].z * inv, o3 = acc[i].w * inv;
        __nv_bfloat162 ph0, ph1, pl0, pl1;
        ph0.x = __float2bfloat16(o0); ph0.y = __float2bfloat16(o1);
        ph1.x = __float2bfloat16(o2); ph1.y = __float2bfloat16(o3);
        pl0.x = __float2bfloat16(o0 - __bfloat162float(ph0.x));
        pl0.y = __float2bfloat16(o1 - __bfloat162float(ph0.y));
        pl1.x = __float2bfloat16(o2 - __bfloat162float(ph1.x));
        pl1.y = __float2bfloat16(o3 - __bfloat162float(ph1.y));
        ((__nv_bfloat162*)(ctx_hi + off))[0] = ph0;
        ((__nv_bfloat162*)(ctx_hi + off))[1] = ph1;
        ((__nv_bfloat162*)(ctx_lo + off))[0] = pl0;
        ((__nv_bfloat162*)(ctx_lo + off))[1] = pl1;
    }
}

// ---------------- LayerNorm ----------------------------------------------------
__global__ __launch_bounds__(256) void ln_kernel(
    const float* __restrict__ X, const float* __restrict__ g,
    const float* __restrict__ be, float* __restrict__ out)
{
    __shared__ float red[8];
    const int row = blockIdx.x;
    const int tid = threadIdx.x;
    const float* xr = X + (size_t)row * D_EMBED;
    float4 v = *(const float4*)(xr + tid * 4);
    float s = (v.x + v.y) + (v.z + v.w);
#pragma unroll
    for (int o = 16; o >= 1; o >>= 1) s += __shfl_xor_sync(0xffffffffu, s, o);
    if ((tid & 31) == 0) red[tid >> 5] = s;
    __syncthreads();
    float tot = red[0] + red[1] + red[2] + red[3] +
                red[4] + red[5] + red[6] + red[7];
    float mu = tot * (1.0f / D_EMBED);
    float d0 = v.x - mu, d1 = v.y - mu, d2 = v.z - mu, d3 = v.w - mu;
    float sq = d0 * d0 + d1 * d1 + d2 * d2 + d3 * d3;
#pragma unroll
    for (int o = 16; o >= 1; o >>= 1) sq += __shfl_xor_sync(0xffffffffu, sq, o);
    __syncthreads();
    if ((tid & 31) == 0) red[tid >> 5] = sq;
    __syncthreads();
    float var = (red[0] + red[1] + red[2] + red[3] +
                 red[4] + red[5] + red[6] + red[7]) * (1.0f / D_EMBED);
    float r = rsqrtf(var + 1e-12f);
    float4 gv = *(const float4*)(g + tid * 4);
    float4 bv = *(const float4*)(be + tid * 4);
    float4 o;
    o.x = d0 * r * gv.x + bv.x;
    o.y = d1 * r * gv.y + bv.y;
    o.z = d2 * r * gv.z + bv.z;
    o.w = d3 * r * gv.w + bv.w;
    *(float4*)(out + (size_t)row * D_EMBED + tid * 4) = o;
}

// ---------------- launch --------------------------------------------------------
extern "C" void kernel_launch(void* const* d_in, const int* in_sizes, int n_in,
                              void* d_out, int out_size)
{
    const float* X     = (const float*)d_in[0];
    const float* mask  = (const float*)d_in[1];
    const float* Wq    = (const float*)d_in[2];
    const float* bq    = (const float*)d_in[3];
    const float* Wk    = (const float*)d_in[4];
    const float* bk    = (const float*)d_in[5];
    const float* Wv    = (const float*)d_in[6];
    const float* bv    = (const float*)d_in[7];
    const float* Wo    = (const float*)d_in[8];
    const float* bo    = (const float*)d_in[9];
    const float* gamma = (const float*)d_in[10];
    const float* beta  = (const float*)d_in[11];
    float* out = (float*)d_out;

    float *q, *k, *v, *x;
    __nv_bfloat16 *xhi, *xlo, *chi, *clo, *whi, *wlo;
    cudaGetSymbolAddress((void**)&q, g_q);
    cudaGetSymbolAddress((void**)&k, g_k);
    cudaGetSymbolAddress((void**)&v, g_v);
    cudaGetSymbolAddress((void**)&x, g_x);
    cudaGetSymbolAddress((void**)&xhi, g_xhi);
    cudaGetSymbolAddress((void**)&xlo, g_xlo);
    cudaGetSymbolAddress((void**)&chi, g_chi);
    cudaGetSymbolAddress((void**)&clo, g_clo);
    cudaGetSymbolAddress((void**)&whi, g_whi);
    cudaGetSymbolAddress((void**)&wlo, g_wlo);

    cudaFuncSetAttribute(attn64, cudaFuncAttributeMaxDynamicSharedMemorySize,
                         ATTN_SMEM);
    cudaFuncSetAttribute(gemm_mma, cudaFuncAttributeMaxDynamicSharedMemorySize,
                         GEMM_SMEM);

    const int WSZ = D_EMBED * D_EMBED;   // 1M elements
    split_bf16<<<(N_M * D_EMBED / 4 + 255) / 256, 256>>>(X, xhi, xlo, N_M * D_EMBED / 4);
    split_bf16<<<(WSZ / 4 + 255) / 256, 256>>>(Wq, whi + 0 * (size_t)WSZ, wlo + 0 * (size_t)WSZ, WSZ / 4);
    split_bf16<<<(WSZ / 4 + 255) / 256, 256>>>(Wk, whi + 1 * (size_t)WSZ, wlo + 1 * (size_t)WSZ, WSZ / 4);
    split_bf16<<<(WSZ / 4 + 255) / 256, 256>>>(Wv, whi + 2 * (size_t)WSZ, wlo + 2 * (size_t)WSZ, WSZ / 4);
    split_bf16<<<(WSZ / 4 + 255) / 256, 256>>>(Wo, whi + 3 * (size_t)WSZ, wlo + 3 * (size_t)WSZ, WSZ / 4);

    dim3 ggrid(D_EMBED / 128, N_M / 128);   // (8, 32)
    gemm_mma<<<ggrid, 256, GEMM_SMEM>>>(xhi, xlo, whi + 0 * (size_t)WSZ, wlo + 0 * (size_t)WSZ, bq, nullptr, q, 1);
    gemm_mma<<<ggrid, 256, GEMM_SMEM>>>(xhi, xlo, whi + 1 * (size_t)WSZ, wlo + 1 * (size_t)WSZ, bk, nullptr, k, 1);
    gemm_mma<<<ggrid, 256, GEMM_SMEM>>>(xhi, xlo, whi + 2 * (size_t)WSZ, wlo + 2 * (size_t)WSZ, bv, nullptr, v, 1);
    attn64<<<dim3(N_B * N_HEADS, N_S / 64), 256, ATTN_SMEM>>>(q, k, v, mask, chi, clo);
    gemm_mma<<<ggrid, 256, GEMM_SMEM>>>(chi, clo, whi + 3 * (size_t)WSZ, wlo + 3 * (size_t)WSZ, bo, X, x, 0);
    ln_kernel<<<N_M, 256>>>(x, gamma, beta, out);
}

// round 4
// speedup vs baseline: 2.3396x; 1.6750x over previous
#include <cuda_runtime.h>
#include <cuda_bf16.h>
#include <cstdint>
#include <math.h>

#define D_EMBED 1024
#define N_HEADS 16
#define D_HEAD  64
#define N_B     2
#define N_S     2048
#define N_M     (N_B * N_S)   // 4096 rows

// ---------------- scratch -----------------------------------------------------
__device__ __align__(16) float g_x[(size_t)N_M * D_EMBED];
__device__ __align__(16) __nv_bfloat16 g_xhi[(size_t)N_M * D_EMBED];
__device__ __align__(16) __nv_bfloat16 g_xlo[(size_t)N_M * D_EMBED];
__device__ __align__(16) __nv_bfloat16 g_chi[(size_t)N_M * D_EMBED];
__device__ __align__(16) __nv_bfloat16 g_clo[(size_t)N_M * D_EMBED];
__device__ __align__(16) __nv_bfloat16 g_whi[4 * D_EMBED * D_EMBED];
__device__ __align__(16) __nv_bfloat16 g_wlo[4 * D_EMBED * D_EMBED];
__device__ __align__(16) __nv_bfloat16 g_qhi[N_B * N_HEADS * N_S * D_HEAD];
__device__ __align__(16) __nv_bfloat16 g_qlo[N_B * N_HEADS * N_S * D_HEAD];
__device__ __align__(16) __nv_bfloat16 g_khi[N_B * N_HEADS * N_S * D_HEAD];
__device__ __align__(16) __nv_bfloat16 g_klo[N_B * N_HEADS * N_S * D_HEAD];
__device__ __align__(16) __nv_bfloat16 g_vhi[N_B * N_HEADS * N_S * D_HEAD];
__device__ __align__(16) __nv_bfloat16 g_vlo[N_B * N_HEADS * N_S * D_HEAD];

// ---------------- helpers -----------------------------------------------------
__device__ __forceinline__ uint32_t s2u(const void* p) {
    uint32_t a;
    asm("{ .reg .u64 t; cvta.to.shared.u64 t, %1; cvt.u32.u64 %0, t; }"
        : "=r"(a) : "l"(p));
    return a;
}
__device__ __forceinline__ void cp16(uint32_t dst, const void* src) {
    asm volatile("cp.async.cg.shared.global [%0], [%1], 16;"
                 :: "r"(dst), "l"(src) : "memory");
}
#define CP_COMMIT() asm volatile("cp.async.commit_group;" ::: "memory")
#define CP_WAIT1()  asm volatile("cp.async.wait_group 1;" ::: "memory")
#define CP_WAIT2()  asm volatile("cp.async.wait_group 2;" ::: "memory")

#define LDM_X4(r0, r1, r2, r3, addr) \
    asm volatile("ldmatrix.sync.aligned.m8n8.x4.shared.b16 {%0,%1,%2,%3}, [%4];" \
                 : "=r"(r0), "=r"(r1), "=r"(r2), "=r"(r3) : "r"(addr))
#define LDM_X4_T(r0, r1, r2, r3, addr) \
    asm volatile("ldmatrix.sync.aligned.m8n8.x4.trans.shared.b16 {%0,%1,%2,%3}, [%4];" \
                 : "=r"(r0), "=r"(r1), "=r"(r2), "=r"(r3) : "r"(addr))

#define MMA_BF16(c, a, b) \
    asm volatile( \
        "mma.sync.aligned.m16n8k16.row.col.f32.bf16.bf16.f32 " \
        "{%0,%1,%2,%3}, {%4,%5,%6,%7}, {%8,%9}, {%0,%1,%2,%3};" \
        : "+f"((c)[0]), "+f"((c)[1]), "+f"((c)[2]), "+f"((c)[3]) \
        : "r"((a)[0]), "r"((a)[1]), "r"((a)[2]), "r"((a)[3]), \
          "r"((b)[0]), "r"((b)[1]))

__device__ __forceinline__ uint32_t pk2(float a, float b) {
    __nv_bfloat162 t;
    t.x = __float2bfloat16(a);
    t.y = __float2bfloat16(b);
    return *(uint32_t*)&t;
}
__device__ __forceinline__ uint32_t pk2lo(float a, float b, uint32_t hi) {
    __nv_bfloat162 t = *(__nv_bfloat162*)&hi;
    return pk2(a - __bfloat162float(t.x), b - __bfloat162float(t.y));
}

// ---------------- split: fp32 -> (bf16 hi, bf16 lo) ---------------------------
__global__ __launch_bounds__(256) void split_bf16(
    const float* __restrict__ src, __nv_bfloat16* __restrict__ hi,
    __nv_bfloat16* __restrict__ lo, int n4)
{
    int i = blockIdx.x * blockDim.x + threadIdx.x;
    if (i >= n4) return;
    float4 v = ((const float4*)src)[i];
    uint32_t h0 = pk2(v.x, v.y), h1 = pk2(v.z, v.w);
    uint32_t l0 = pk2lo(v.x, v.y, h0), l1 = pk2lo(v.z, v.w, h1);
    ((uint32_t*)hi)[2 * i + 0] = h0;
    ((uint32_t*)hi)[2 * i + 1] = h1;
    ((uint32_t*)lo)[2 * i + 0] = l0;
    ((uint32_t*)lo)[2 * i + 1] = l1;
}

// ---------------- bf16-split tensor GEMM ---------------------------------------
#define BUF_B  (128 * 80)
#define STAGE_B (4 * BUF_B)
#define GSTAGES 3
#define GEMM_SMEM (GSTAGES * STAGE_B)

__device__ __forceinline__ void load_stage(
    uint32_t st, const __nv_bfloat16* Ahi, const __nv_bfloat16* Alo,
    const __nv_bfloat16* Bhi, const __nv_bfloat16* Blo,
    int bm, int bn, int kb, int tid)
{
    const __nv_bfloat16* srcs[4] = {Ahi, Alo, Bhi, Blo};
    const int rowoff[4] = {bm, bm, bn, bn};
#pragma unroll
    for (int bf = 0; bf < 4; bf++) {
        const __nv_bfloat16* sb = srcs[bf] + (size_t)rowoff[bf] * D_EMBED + kb * 32;
        uint32_t db = st + bf * BUF_B;
#pragma unroll
        for (int i = 0; i < 2; i++) {
            int c = tid + i * 256;
            int row = c >> 2, kc = c & 3;
            cp16(db + row * 80 + kc * 16, sb + (size_t)row * D_EMBED + kc * 8);
        }
    }
}

__global__ __launch_bounds__(256, 1) void gemm_mma(
    const __nv_bfloat16* __restrict__ Ahi, const __nv_bfloat16* __restrict__ Alo,
    const __nv_bfloat16* __restrict__ Bhi, const __nv_bfloat16* __restrict__ Blo,
    const float* __restrict__ bias, const float* __restrict__ res,
    float* __restrict__ out, __nv_bfloat16* __restrict__ out_hi,
    __nv_bfloat16* __restrict__ out_lo, int qkv)
{
    extern __shared__ char smraw[];
    const uint32_t smb = s2u(smraw);
    const int tid = threadIdx.x;
    const int lane = tid & 31;
    const int wid = tid >> 5;
    const int warp_m = (wid >> 2) * 64;
    const int warp_n = (wid & 3) * 32;
    const int bm = blockIdx.y * 128;
    const int bn = blockIdx.x * 128;

    float c[4][4][4];
#pragma unroll
    for (int mi = 0; mi < 4; mi++)
#pragma unroll
        for (int ni = 0; ni < 4; ni++)
#pragma unroll
            for (int e = 0; e < 4; e++) c[mi][ni][e] = 0.0f;

#pragma unroll
    for (int p = 0; p < GSTAGES; p++) {
        load_stage(smb + p * STAGE_B, Ahi, Alo, Bhi, Blo, bm, bn, p, tid);
        CP_COMMIT();
    }

    const uint32_t a_row = lane & 15;
    const uint32_t a_coff = (lane >> 4) * 16;
    const uint32_t b_row = (lane & 7) + ((lane >> 4) << 3);
    const uint32_t b_coff = ((lane >> 3) & 1) * 16;

    int s = 0;
    for (int kb = 0; kb < D_EMBED / 32; kb++) {
        CP_WAIT2();
        __syncthreads();
        uint32_t st = smb + s * STAGE_B;
        uint32_t ah_b = st, al_b = st + BUF_B;
        uint32_t bh_b = st + 2 * BUF_B, bl_b = st + 3 * BUF_B;

#pragma unroll
        for (int k16 = 0; k16 < 2; k16++) {
            uint32_t akoff = k16 * 32 + a_coff;
            uint32_t bkoff = k16 * 32 + b_coff;
            uint32_t ah[4][4], al[4][4], bh[4][2], bl[4][2];
#pragma unroll
            for (int mi = 0; mi < 4; mi++) {
                uint32_t ro = (warp_m + mi * 16 + a_row) * 80 + akoff;
                LDM_X4(ah[mi][0], ah[mi][1], ah[mi][2], ah[mi][3], ah_b + ro);
                LDM_X4(al[mi][0], al[mi][1], al[mi][2], al[mi][3], al_b + ro);
            }
#pragma unroll
            for (int ni2 = 0; ni2 < 2; ni2++) {
                uint32_t ro = (warp_n + ni2 * 16 + b_row) * 80 + bkoff;
                LDM_X4(bh[ni2 * 2][0], bh[ni2 * 2][1],
                       bh[ni2 * 2 + 1][0], bh[ni2 * 2 + 1][1], bh_b + ro);
                LDM_X4(bl[ni2 * 2][0], bl[ni2 * 2][1],
                       bl[ni2 * 2 + 1][0], bl[ni2 * 2 + 1][1], bl_b + ro);
            }
#pragma unroll
            for (int mi = 0; mi < 4; mi++)
#pragma unroll
                for (int ni = 0; ni < 4; ni++) {
                    MMA_BF16(c[mi][ni], ah[mi], bh[ni]);
                    MMA_BF16(c[mi][ni], ah[mi], bl[ni]);
                    MMA_BF16(c[mi][ni], al[mi], bh[ni]);
                }
        }
        __syncthreads();
        if (kb + GSTAGES < D_EMBED / 32)
            load_stage(st, Ahi, Alo, Bhi, Blo, bm, bn, kb + GSTAGES, tid);
        CP_COMMIT();
        s++; if (s == GSTAGES) s = 0;
    }

#pragma unroll
    for (int mi = 0; mi < 4; mi++) {
#pragma unroll
        for (int half = 0; half < 2; half++) {
            int m = bm + warp_m + mi * 16 + (lane >> 2) + half * 8;
            int bb = m >> 11, sdx = m & (N_S - 1);
#pragma unroll
            for (int ni = 0; ni < 4; ni++) {
                int n = bn + warp_n + ni * 8 + 2 * (lane & 3);
                float2 o;
                o.x = c[mi][ni][half * 2 + 0] + bias[n];
                o.y = c[mi][ni][half * 2 + 1] + bias[n + 1];
                if (res) {
                    float2 rv = *(const float2*)(res + (size_t)m * D_EMBED + n);
                    o.x += rv.x; o.y += rv.y;
                }
                if (qkv) {
                    int h = n >> 6, d = n & 63;
                    size_t off = (((size_t)(bb * N_HEADS + h)) * N_S + sdx) * D_HEAD + d;
                    uint32_t h2 = pk2(o.x, o.y);
                    uint32_t l2 = pk2lo(o.x, o.y, h2);
                    *(uint32_t*)(out_hi + off) = h2;
                    *(uint32_t*)(out_lo + off) = l2;
                } else {
                    *(float2*)(out + (size_t)m * D_EMBED + n) = o;
                }
            }
        }
    }
}

// ---------------- tensor-core flash attention ----------------------------------
// BQ=128, BK=64, 8 warps, warp owns 16 rows. hi/lo 3-mma on QK^T and PV.
#define ROWB 144                    // 64 bf16 (128B) + 16B pad per smem row
#define AQ_OFF 0                    // qhi 128*144, qlo 128*144
#define AKV_OFF (2 * 128 * ROWB)    // 36864
#define AKV_STAGE (4 * 64 * ROWB)   // khi,klo,vhi,vlo = 36864
#define AMSK_OFF (AKV_OFF + 2 * AKV_STAGE)  // 110592
#define ATTN_SMEM (AMSK_OFF + 512)

__device__ __forceinline__ void attn_load_kv(
    uint32_t smb, const __nv_bfloat16* khi, const __nv_bfloat16* klo,
    const __nv_bfloat16* vhi, const __nv_bfloat16* vlo,
    const float* mask, int bh, int b, int kt, int st, int tid)
{
    const __nv_bfloat16* srcs[4] = {khi, klo, vhi, vlo};
    uint32_t base = smb + AKV_OFF + st * AKV_STAGE;
#pragma unroll
    for (int bf = 0; bf < 4; bf++) {
        const __nv_bfloat16* sp = srcs[bf] + ((size_t)bh * N_S + kt * 64) * D_HEAD;
        uint32_t db = base + bf * (64 * ROWB);
#pragma unroll
        for (int rep = 0; rep < 2; rep++) {
            int idx = tid + rep * 256;
            int r = idx >> 3, cq = idx & 7;
            cp16(db + r * ROWB + cq * 16, sp + (size_t)r * D_HEAD + cq * 8);
        }
    }
    if (tid < 16)
        cp16(smb + AMSK_OFF + st * 256 + tid * 16, mask + (size_t)b * N_S + kt * 64 + tid * 4);
}

__global__ __launch_bounds__(256) void attn_mma(
    const __nv_bfloat16* __restrict__ qhi, const __nv_bfloat16* __restrict__ qlo,
    const __nv_bfloat16* __restrict__ khi, const __nv_bfloat16* __restrict__ klo,
    const __nv_bfloat16* __restrict__ vhi, const __nv_bfloat16* __restrict__ vlo,
    const float* __restrict__ mask,
    __nv_bfloat16* __restrict__ chi, __nv_bfloat16* __restrict__ clo)
{
    extern __shared__ char smraw[];
    const uint32_t smb = s2u(smraw);
    const int bh = blockIdx.x;
    const int qt = blockIdx.y;
    const int b = bh >> 4;
    const int h = bh & 15;
    const int tid = threadIdx.x;
    const int lane = tid & 31;
    const int wid = tid >> 5;
    const int wrow = wid * 16;

    // prologue: Q (both bufs) + KV stage0 -> group0; KV stage1 -> group1
    {
        const __nv_bfloat16* qs[2] = {qhi, qlo};
#pragma unroll
        for (int buf = 0; buf < 2; buf++) {
            const __nv_bfloat16* sp = qs[buf] + ((size_t)bh * N_S + qt * 128) * D_HEAD;
            uint32_t db = smb + buf * (128 * ROWB);
#pragma unroll
            for (int rep = 0; rep < 4; rep++) {
                int idx = tid + rep * 256;
                int r = idx >> 3, cq = idx & 7;
                cp16(db + r * ROWB + cq * 16, sp + (size_t)r * D_HEAD + cq * 8);
            }
        }
        attn_load_kv(smb, khi, klo, vhi, vlo, mask, bh, b, 0, 0, tid);
        CP_COMMIT();
        attn_load_kv(smb, khi, klo, vhi, vlo, mask, bh, b, 1, 1, tid);
        CP_COMMIT();
    }

    float o[8][4];
#pragma unroll
    for (int ni = 0; ni < 8; ni++)
#pragma unroll
        for (int e = 0; e < 4; e++) o[ni][e] = 0.0f;
    float m_run[2] = {-3.0e38f, -3.0e38f};
    float l_run[2] = {0.0f, 0.0f};

    uint32_t qh[4][4], ql[4][4];
    const uint32_t a_row = lane & 15;
    const uint32_t a_coff = (lane >> 4) * 16;
    const uint32_t b_row = (lane & 7) + ((lane >> 4) << 3);
    const uint32_t b_coff = ((lane >> 3) & 1) * 16;
    const uint32_t v_row = (lane & 7) + ((lane >> 3) & 1) * 8;
    const uint32_t v_coff = (lane >> 4) * 16;
    const float scale = 0.125f;

    int st = 0;
    for (int kt = 0; kt < N_S / 64; kt++) {
        CP_WAIT1();
        __syncthreads();
        if (kt == 0) {
#pragma unroll
            for (int kk = 0; kk < 4; kk++) {
                uint32_t ad = smb + (wrow + a_row) * ROWB + kk * 32 + a_coff;
                LDM_X4(qh[kk][0], qh[kk][1], qh[kk][2], qh[kk][3], ad);
                LDM_X4(ql[kk][0], ql[kk][1], ql[kk][2], ql[kk][3], ad + 128 * ROWB);
            }
        }
        uint32_t kvb = smb + AKV_OFF + st * AKV_STAGE;

        // ---- S = Q K^T (hi/lo 3-term) ----
        float s[8][4];
#pragma unroll
        for (int ni = 0; ni < 8; ni++)
#pragma unroll
            for (int e = 0; e < 4; e++) s[ni][e] = 0.0f;

#pragma unroll
        for (int kk = 0; kk < 4; kk++) {
#pragma unroll
            for (int ni2 = 0; ni2 < 4; ni2++) {
                uint32_t ro = (ni2 * 16 + b_row) * ROWB + kk * 32 + b_coff;
                uint32_t kh[4], kl[4];
                LDM_X4(kh[0], kh[1], kh[2], kh[3], kvb + ro);
                LDM_X4(kl[0], kl[1], kl[2], kl[3], kvb + 64 * ROWB + ro);
                MMA_BF16(s[2 * ni2], qh[kk], kh);
                MMA_BF16(s[2 * ni2], qh[kk], kl);
                MMA_BF16(s[2 * ni2], ql[kk], kh);
                MMA_BF16(s[2 * ni2 + 1], qh[kk], kh + 2);
                MMA_BF16(s[2 * ni2 + 1], qh[kk], kl + 2);
                MMA_BF16(s[2 * ni2 + 1], ql[kk], kh + 2);
            }
        }

        // ---- online softmax (rows owned entirely by this warp) ----
        float2 mv[8];
#pragma unroll
        for (int ni = 0; ni < 8; ni++)
            mv[ni] = *(float2*)(smraw + AMSK_OFF + st * 256 +
                                (ni * 8 + 2 * (lane & 3)) * 4);
#pragma unroll
        for (int hf = 0; hf < 2; hf++) {
            float mx = -3.0e38f;
#pragma unroll
            for (int ni = 0; ni < 8; ni++) {
                float v0 = s[ni][2 * hf] * scale + mv[ni].x;
                float v1 = s[ni][2 * hf + 1] * scale + mv[ni].y;
                s[ni][2 * hf] = v0; s[ni][2 * hf + 1] = v1;
                mx = fmaxf(mx, fmaxf(v0, v1));
            }
            mx = fmaxf(mx, __shfl_xor_sync(0xffffffffu, mx, 1));
            mx = fmaxf(mx, __shfl_xor_sync(0xffffffffu, mx, 2));
            float mnew = fmaxf(m_run[hf], mx);
            float alpha = __expf(m_run[hf] - mnew);
            float sum = 0.0f;
#pragma unroll
            for (int ni = 0; ni < 8; ni++) {
                float p0 = __expf(s[ni][2 * hf] - mnew);
                float p1 = __expf(s[ni][2 * hf + 1] - mnew);
                s[ni][2 * hf] = p0; s[ni][2 * hf + 1] = p1;
                sum += p0 + p1;
            }
            sum += __shfl_xor_sync(0xffffffffu, sum, 1);
            sum += __shfl_xor_sync(0xffffffffu, sum, 2);
            l_run[hf] = l_run[hf] * alpha + sum;
            m_run[hf] = mnew;
#pragma unroll
            for (int ni = 0; ni < 8; ni++) {
                o[ni][2 * hf] *= alpha;
                o[ni][2 * hf + 1] *= alpha;
            }
        }

        // ---- O += P V (hi/lo 3-term); P A-frags built from S accumulators ----
        uint32_t vbb = kvb + 2 * 64 * ROWB;
#pragma unroll
        for (int kk = 0; kk < 4; kk++) {
            uint32_t pah[4], pal[4];
            pah[0] = pk2(s[2 * kk][0], s[2 * kk][1]);
            pah[1] = pk2(s[2 * kk][2], s[2 * kk][3]);
            pah[2] = pk2(s[2 * kk + 1][0], s[2 * kk + 1][1]);
            pah[3] = pk2(s[2 * kk + 1][2], s[2 * kk + 1][3]);
            pal[0] = pk2lo(s[2 * kk][0], s[2 * kk][1], pah[0]);
            pal[1] = pk2lo(s[2 * kk][2], s[2 * kk][3], pah[1]);
            pal[2] = pk2lo(s[2 * kk + 1][0], s[2 * kk + 1][1], pah[2]);
            pal[3] = pk2lo(s[2 * kk + 1][2], s[2 * kk + 1][3], pah[3]);
#pragma unroll
            for (int ni2 = 0; ni2 < 4; ni2++) {
                uint32_t ro = (kk * 16 + v_row) * ROWB + ni2 * 32 + v_coff;
                uint32_t vh[4], vl[4];
                LDM_X4_T(vh[0], vh[1], vh[2], vh[3], vbb + ro);
                LDM_X4_T(vl[0], vl[1], vl[2], vl[3], vbb + 64 * ROWB + ro);
                MMA_BF16(o[2 * ni2], pah, vh);
                MMA_BF16(o[2 * ni2], pah, vl);
                MMA_BF16(o[2 * ni2], pal, vh);
                MMA_BF16(o[2 * ni2 + 1], pah, vh + 2);
                MMA_BF16(o[2 * ni2 + 1], pah, vl + 2);
                MMA_BF16(o[2 * ni2 + 1], pal, vh + 2);
            }
        }

        __syncthreads();
        if (kt + 2 < N_S / 64)
            attn_load_kv(smb, khi, klo, vhi, vlo, mask, bh, b, kt + 2, st, tid);
        CP_COMMIT();
        st ^= 1;
    }

    // ---- epilogue: O /= l, write bf16 hi/lo ctx ----
#pragma unroll
    for (int hf = 0; hf < 2; hf++) {
        float inv = 1.0f / l_run[hf];
        int row = qt * 128 + wrow + (lane >> 2) + hf * 8;
        size_t mrow = ((size_t)(b * N_S + row)) * D_EMBED + h * D_HEAD;
#pragma unroll
        for (int ni = 0; ni < 8; ni++) {
            int d = ni * 8 + 2 * (lane & 3);
            float a = o[ni][2 * hf] * inv;
            float bb2 = o[ni][2 * hf + 1] * inv;
            uint32_t h2 = pk2(a, bb2);
            uint32_t l2 = pk2lo(a, bb2, h2);
            *(uint32_t*)(chi + mrow + d) = h2;
            *(uint32_t*)(clo + mrow + d) = l2;
        }
    }
}

// ---------------- LayerNorm ----------------------------------------------------
__global__ __launch_bounds__(256) void ln_kernel(
    const float* __restrict__ X, const float* __restrict__ g,
    const float* __restrict__ be, float* __restrict__ out)
{
    __shared__ float red[8];
    const int row = blockIdx.x;
    const int tid = threadIdx.x;
    const float* xr = X + (size_t)row * D_EMBED;
    float4 v = *(const float4*)(xr + tid * 4);
    float s = (v.x + v.y) + (v.z + v.w);
#pragma unroll
    for (int o = 16; o >= 1; o >>= 1) s += __shfl_xor_sync(0xffffffffu, s, o);
    if ((tid & 31) == 0) red[tid >> 5] = s;
    __syncthreads();
    float tot = red[0] + red[1] + red[2] + red[3] +
                red[4] + red[5] + red[6] + red[7];
    float mu = tot * (1.0f / D_EMBED);
    float d0 = v.x - mu, d1 = v.y - mu, d2 = v.z - mu, d3 = v.w - mu;
    float sq = d0 * d0 + d1 * d1 + d2 * d2 + d3 * d3;
#pragma unroll
    for (int o = 16; o >= 1; o >>= 1) sq += __shfl_xor_sync(0xffffffffu, sq, o);
    __syncthreads();
    if ((tid & 31) == 0) red[tid >> 5] = sq;
    __syncthreads();
    float var = (red[0] + red[1] + red[2] + red[3] +
                 red[4] + red[5] + red[6] + red[7]) * (1.0f / D_EMBED);
    float r = rsqrtf(var + 1e-12f);
    float4 gv = *(const float4*)(g + tid * 4);
    float4 bv = *(const float4*)(be + tid * 4);
    float4 o;
    o.x = d0 * r * gv.x + bv.x;
    o.y = d1 * r * gv.y + bv.y;
    o.z = d2 * r * gv.z + bv.z;
    o.w = d3 * r * gv.w + bv.w;
    *(float4*)(out + (size_t)row * D_EMBED + tid * 4) = o;
}

// ---------------- launch --------------------------------------------------------
extern "C" void kernel_launch(void* const* d_in, const int* in_sizes, int n_in,
                              void* d_out, int out_size)
{
    const float* X     = (const float*)d_in[0];
    const float* mask  = (const float*)d_in[1];
    const float* Wq    = (const float*)d_in[2];
    const float* bq    = (const float*)d_in[3];
    const float* Wk    = (const float*)d_in[4];
    const float* bk    = (const float*)d_in[5];
    const float* Wv    = (const float*)d_in[6];
    const float* bv    = (const float*)d_in[7];
    const float* Wo    = (const float*)d_in[8];
    const float* bo    = (const float*)d_in[9];
    const float* gamma = (const float*)d_in[10];
    const float* beta  = (const float*)d_in[11];
    float* out = (float*)d_out;

    float *x;
    __nv_bfloat16 *xhi, *xlo, *chi, *clo, *whi, *wlo;
    __nv_bfloat16 *qhi, *qlo, *khi, *klo, *vhi, *vlo;
    cudaGetSymbolAddress((void**)&x, g_x);
    cudaGetSymbolAddress((void**)&xhi, g_xhi);
    cudaGetSymbolAddress((void**)&xlo, g_xlo);
    cudaGetSymbolAddress((void**)&chi, g_chi);
    cudaGetSymbolAddress((void**)&clo, g_clo);
    cudaGetSymbolAddress((void**)&whi, g_whi);
    cudaGetSymbolAddress((void**)&wlo, g_wlo);
    cudaGetSymbolAddress((void**)&qhi, g_qhi);
    cudaGetSymbolAddress((void**)&qlo, g_qlo);
    cudaGetSymbolAddress((void**)&khi, g_khi);
    cudaGetSymbolAddress((void**)&klo, g_klo);
    cudaGetSymbolAddress((void**)&vhi, g_vhi);
    cudaGetSymbolAddress((void**)&vlo, g_vlo);

    cudaFuncSetAttribute(attn_mma, cudaFuncAttributeMaxDynamicSharedMemorySize,
                         ATTN_SMEM);
    cudaFuncSetAttribute(gemm_mma, cudaFuncAttributeMaxDynamicSharedMemorySize,
                         GEMM_SMEM);

    const size_t WSZ = (size_t)D_EMBED * D_EMBED;
    split_bf16<<<(N_M * D_EMBED / 4 + 255) / 256, 256>>>(X, xhi, xlo, N_M * D_EMBED / 4);
    split_bf16<<<(WSZ / 4 + 255) / 256, 256>>>(Wq, whi + 0 * WSZ, wlo + 0 * WSZ, WSZ / 4);
    split_bf16<<<(WSZ / 4 + 255) / 256, 256>>>(Wk, whi + 1 * WSZ, wlo + 1 * WSZ, WSZ / 4);
    split_bf16<<<(WSZ / 4 + 255) / 256, 256>>>(Wv, whi + 2 * WSZ, wlo + 2 * WSZ, WSZ / 4);
    split_bf16<<<(WSZ / 4 + 255) / 256, 256>>>(Wo, whi + 3 * WSZ, wlo + 3 * WSZ, WSZ / 4);

    dim3 ggrid(D_EMBED / 128, N_M / 128);   // (8, 32)
    gemm_mma<<<ggrid, 256, GEMM_SMEM>>>(xhi, xlo, whi + 0 * WSZ, wlo + 0 * WSZ, bq,
                                        nullptr, nullptr, qhi, qlo, 1);
    gemm_mma<<<ggrid, 256, GEMM_SMEM>>>(xhi, xlo, whi + 1 * WSZ, wlo + 1 * WSZ, bk,
                                        nullptr, nullptr, khi, klo, 1);
    gemm_mma<<<ggrid, 256, GEMM_SMEM>>>(xhi, xlo, whi + 2 * WSZ, wlo + 2 * WSZ, bv,
                                        nullptr, nullptr, vhi, vlo, 1);
    attn_mma<<<dim3(N_B * N_HEADS, N_S / 128), 256, ATTN_SMEM>>>(
        qhi, qlo, khi, klo, vhi, vlo, mask, chi, clo);
    gemm_mma<<<ggrid, 256, GEMM_SMEM>>>(chi, clo, whi + 3 * WSZ, wlo + 3 * WSZ, bo,
                                        X, x, nullptr, nullptr, 0);
    ln_kernel<<<N_M, 256>>>(x, gamma, beta, out);
}

// round 5
// speedup vs baseline: 2.5256x; 1.0795x over previous
#include <cuda_runtime.h>
#include <cuda_bf16.h>
#include <cstdint>
#include <math.h>

#define D_EMBED 1024
#define N_HEADS 16
#define D_HEAD  64
#define N_B     2
#define N_S     2048
#define N_M     (N_B * N_S)   // 4096 rows

// ---------------- scratch -----------------------------------------------------
__device__ __align__(16) float g_x[(size_t)N_M * D_EMBED];
__device__ __align__(16) __nv_bfloat16 g_xhi[(size_t)N_M * D_EMBED];
__device__ __align__(16) __nv_bfloat16 g_xlo[(size_t)N_M * D_EMBED];
__device__ __align__(16) __nv_bfloat16 g_chi[(size_t)N_M * D_EMBED];
__device__ __align__(16) __nv_bfloat16 g_clo[(size_t)N_M * D_EMBED];
__device__ __align__(16) __nv_bfloat16 g_whi[4 * D_EMBED * D_EMBED];
__device__ __align__(16) __nv_bfloat16 g_wlo[4 * D_EMBED * D_EMBED];
__device__ __align__(16) __nv_bfloat16 g_qhi[N_B * N_HEADS * N_S * D_HEAD];
__device__ __align__(16) __nv_bfloat16 g_qlo[N_B * N_HEADS * N_S * D_HEAD];
__device__ __align__(16) __nv_bfloat16 g_khi[N_B * N_HEADS * N_S * D_HEAD];
__device__ __align__(16) __nv_bfloat16 g_klo[N_B * N_HEADS * N_S * D_HEAD];
__device__ __align__(16) __nv_bfloat16 g_vhi[N_B * N_HEADS * N_S * D_HEAD];
__device__ __align__(16) __nv_bfloat16 g_vlo[N_B * N_HEADS * N_S * D_HEAD];

// ---------------- helpers -----------------------------------------------------
__device__ __forceinline__ uint32_t s2u(const void* p) {
    uint32_t a;
    asm("{ .reg .u64 t; cvta.to.shared.u64 t, %1; cvt.u32.u64 %0, t; }"
        : "=r"(a) : "l"(p));
    return a;
}
__device__ __forceinline__ void cp16(uint32_t dst, const void* src) {
    asm volatile("cp.async.cg.shared.global [%0], [%1], 16;"
                 :: "r"(dst), "l"(src) : "memory");
}
#define CP_COMMIT() asm volatile("cp.async.commit_group;" ::: "memory")
#define CP_WAIT1()  asm volatile("cp.async.wait_group 1;" ::: "memory")

#define LDM_X4(r0, r1, r2, r3, addr) \
    asm volatile("ldmatrix.sync.aligned.m8n8.x4.shared.b16 {%0,%1,%2,%3}, [%4];" \
                 : "=r"(r0), "=r"(r1), "=r"(r2), "=r"(r3) : "r"(addr))
#define LDM_X4_T(r0, r1, r2, r3, addr) \
    asm volatile("ldmatrix.sync.aligned.m8n8.x4.trans.shared.b16 {%0,%1,%2,%3}, [%4];" \
                 : "=r"(r0), "=r"(r1), "=r"(r2), "=r"(r3) : "r"(addr))

#define MMA_BF16(c, a, b) \
    asm volatile( \
        "mma.sync.aligned.m16n8k16.row.col.f32.bf16.bf16.f32 " \
        "{%0,%1,%2,%3}, {%4,%5,%6,%7}, {%8,%9}, {%0,%1,%2,%3};" \
        : "+f"((c)[0]), "+f"((c)[1]), "+f"((c)[2]), "+f"((c)[3]) \
        : "r"((a)[0]), "r"((a)[1]), "r"((a)[2]), "r"((a)[3]), \
          "r"((b)[0]), "r"((b)[1]))

__device__ __forceinline__ uint32_t pk2(float a, float b) {
    __nv_bfloat162 t;
    t.x = __float2bfloat16(a);
    t.y = __float2bfloat16(b);
    return *(uint32_t*)&t;
}
__device__ __forceinline__ uint32_t pk2lo(float a, float b, uint32_t hi) {
    __nv_bfloat162 t = *(__nv_bfloat162*)&hi;
    return pk2(a - __bfloat162float(t.x), b - __bfloat162float(t.y));
}

// ---------------- splits --------------------------------------------------------
__global__ __launch_bounds__(256) void split_bf16(
    const float* __restrict__ src, __nv_bfloat16* __restrict__ hi,
    __nv_bfloat16* __restrict__ lo, int n4)
{
    int i = blockIdx.x * blockDim.x + threadIdx.x;
    if (i >= n4) return;
    float4 v = ((const float4*)src)[i];
    uint32_t h0 = pk2(v.x, v.y), h1 = pk2(v.z, v.w);
    uint32_t l0 = pk2lo(v.x, v.y, h0), l1 = pk2lo(v.z, v.w, h1);
    ((uint32_t*)hi)[2 * i + 0] = h0;
    ((uint32_t*)hi)[2 * i + 1] = h1;
    ((uint32_t*)lo)[2 * i + 0] = l0;
    ((uint32_t*)lo)[2 * i + 1] = l1;
}

// 4 weights in one launch; blockIdx.y selects src, dst offset = y*WSZ
__global__ __launch_bounds__(256) void split_w4(
    const float* __restrict__ w0, const float* __restrict__ w1,
    const float* __restrict__ w2, const float* __restrict__ w3,
    __nv_bfloat16* __restrict__ hi, __nv_bfloat16* __restrict__ lo)
{
    const int z = blockIdx.y;
    const float* src = (z == 0) ? w0 : (z == 1) ? w1 : (z == 2) ? w2 : w3;
    size_t off = (size_t)z * D_EMBED * D_EMBED;
    int i = blockIdx.x * blockDim.x + threadIdx.x;   // < WSZ/4
    float4 v = ((const float4*)src)[i];
    uint32_t h0 = pk2(v.x, v.y), h1 = pk2(v.z, v.w);
    uint32_t l0 = pk2lo(v.x, v.y, h0), l1 = pk2lo(v.z, v.w, h1);
    ((uint32_t*)(hi + off))[2 * i + 0] = h0;
    ((uint32_t*)(hi + off))[2 * i + 1] = h1;
    ((uint32_t*)(lo + off))[2 * i + 0] = l0;
    ((uint32_t*)(lo + off))[2 * i + 1] = l1;
}

// ---------------- bf16-split tensor GEMM core ------------------------------------
// 2-stage pipeline, 80KB smem, 2 CTAs/SM.
#define BUF_B  (128 * 80)
#define STAGE_B (4 * BUF_B)
#define GSTAGES 2
#define GEMM_SMEM (GSTAGES * STAGE_B)   // 81920

__device__ __forceinline__ void load_stage(
    uint32_t st, const __nv_bfloat16* Ahi, const __nv_bfloat16* Alo,
    const __nv_bfloat16* Bhi, const __nv_bfloat16* Blo,
    int bm, int bn, int kb, int tid)
{
    const __nv_bfloat16* srcs[4] = {Ahi, Alo, Bhi, Blo};
    const int rowoff[4] = {bm, bm, bn, bn};
#pragma unroll
    for (int bf = 0; bf < 4; bf++) {
        const __nv_bfloat16* sb = srcs[bf] + (size_t)rowoff[bf] * D_EMBED + kb * 32;
        uint32_t db = st + bf * BUF_B;
#pragma unroll
        for (int i = 0; i < 2; i++) {
            int c = tid + i * 256;
            int row = c >> 2, kc = c & 3;
            cp16(db + row * 80 + kc * 16, sb + (size_t)row * D_EMBED + kc * 8);
        }
    }
}

__device__ __forceinline__ void gemm_core(
    const __nv_bfloat16* Ahi, const __nv_bfloat16* Alo,
    const __nv_bfloat16* Bhi, const __nv_bfloat16* Blo,
    const float* bias, const float* res, float* out,
    __nv_bfloat16* out_hi, __nv_bfloat16* out_lo, int qkv, int bm, int bn)
{
    extern __shared__ char smraw[];
    const uint32_t smb = s2u(smraw);
    const int tid = threadIdx.x;
    const int lane = tid & 31;
    const int wid = tid >> 5;
    const int warp_m = (wid >> 2) * 64;
    const int warp_n = (wid & 3) * 32;

    float c[4][4][4];
#pragma unroll
    for (int mi = 0; mi < 4; mi++)
#pragma unroll
        for (int ni = 0; ni < 4; ni++)
#pragma unroll
            for (int e = 0; e < 4; e++) c[mi][ni][e] = 0.0f;

#pragma unroll
    for (int p = 0; p < GSTAGES; p++) {
        load_stage(smb + p * STAGE_B, Ahi, Alo, Bhi, Blo, bm, bn, p, tid);
        CP_COMMIT();
    }

    const uint32_t a_row = lane & 15;
    const uint32_t a_coff = (lane >> 4) * 16;
    const uint32_t b_row = (lane & 7) + ((lane >> 4) << 3);
    const uint32_t b_coff = ((lane >> 3) & 1) * 16;

    int s = 0;
    for (int kb = 0; kb < D_EMBED / 32; kb++) {
        CP_WAIT1();
        __syncthreads();
        uint32_t st = smb + s * STAGE_B;
        uint32_t ah_b = st, al_b = st + BUF_B;
        uint32_t bh_b = st + 2 * BUF_B, bl_b = st + 3 * BUF_B;

#pragma unroll
        for (int k16 = 0; k16 < 2; k16++) {
            uint32_t akoff = k16 * 32 + a_coff;
            uint32_t bkoff = k16 * 32 + b_coff;
            uint32_t ah[4][4], al[4][4], bh[4][2], bl[4][2];
#pragma unroll
            for (int mi = 0; mi < 4; mi++) {
                uint32_t ro = (warp_m + mi * 16 + a_row) * 80 + akoff;
                LDM_X4(ah[mi][0], ah[mi][1], ah[mi][2], ah[mi][3], ah_b + ro);
                LDM_X4(al[mi][0], al[mi][1], al[mi][2], al[mi][3], al_b + ro);
            }
#pragma unroll
            for (int ni2 = 0; ni2 < 2; ni2++) {
                uint32_t ro = (warp_n + ni2 * 16 + b_row) * 80 + bkoff;
                LDM_X4(bh[ni2 * 2][0], bh[ni2 * 2][1],
                       bh[ni2 * 2 + 1][0], bh[ni2 * 2 + 1][1], bh_b + ro);
                LDM_X4(bl[ni2 * 2][0], bl[ni2 * 2][1],
                       bl[ni2 * 2 + 1][0], bl[ni2 * 2 + 1][1], bl_b + ro);
            }
#pragma unroll
            for (int mi = 0; mi < 4; mi++)
#pragma unroll
                for (int ni = 0; ni < 4; ni++) {
                    MMA_BF16(c[mi][ni], ah[mi], bh[ni]);
                    MMA_BF16(c[mi][ni], ah[mi], bl[ni]);
                    MMA_BF16(c[mi][ni], al[mi], bh[ni]);
                }
        }
        __syncthreads();
        if (kb + GSTAGES < D_EMBED / 32)
            load_stage(st, Ahi, Alo, Bhi, Blo, bm, bn, kb + GSTAGES, tid);
        CP_COMMIT();
        s ^= 1;
    }

#pragma unroll
    for (int mi = 0; mi < 4; mi++) {
#pragma unroll
        for (int half = 0; half < 2; half++) {
            int m = bm + warp_m + mi * 16 + (lane >> 2) + half * 8;
            int bb = m >> 11, sdx = m & (N_S - 1);
#pragma unroll
            for (int ni = 0; ni < 4; ni++) {
                int n = bn + warp_n + ni * 8 + 2 * (lane & 3);
                float2 o;
                o.x = c[mi][ni][half * 2 + 0] + bias[n];
                o.y = c[mi][ni][half * 2 + 1] + bias[n + 1];
                if (res) {
                    float2 rv = *(const float2*)(res + (size_t)m * D_EMBED + n);
                    o.x += rv.x; o.y += rv.y;
                }
                if (qkv) {
                    int h = n >> 6, d = n & 63;
                    size_t off = (((size_t)(bb * N_HEADS + h)) * N_S + sdx) * D_HEAD + d;
                    uint32_t h2 = pk2(o.x, o.y);
                    uint32_t l2 = pk2lo(o.x, o.y, h2);
                    *(uint32_t*)(out_hi + off) = h2;
                    *(uint32_t*)(out_lo + off) = l2;
                } else {
                    *(float2*)(out + (size_t)m * D_EMBED + n) = o;
                }
            }
        }
    }
}

// merged QKV: grid (8, 32, 3); z selects weight/bias/output
__global__ __launch_bounds__(256, 2) void gemm_qkv(
    const __nv_bfloat16* __restrict__ Ahi, const __nv_bfloat16* __restrict__ Alo,
    const __nv_bfloat16* __restrict__ whi, const __nv_bfloat16* __restrict__ wlo,
    const float* __restrict__ bq, const float* __restrict__ bk,
    const float* __restrict__ bv,
    __nv_bfloat16* __restrict__ qhi, __nv_bfloat16* __restrict__ qlo,
    __nv_bfloat16* __restrict__ khi, __nv_bfloat16* __restrict__ klo,
    __nv_bfloat16* __restrict__ vhi, __nv_bfloat16* __restrict__ vlo)
{
    const int z = blockIdx.z;
    const size_t WSZ = (size_t)D_EMBED * D_EMBED;
    const float* bias = (z == 0) ? bq : (z == 1) ? bk : bv;
    __nv_bfloat16* ohi = (z == 0) ? qhi : (z == 1) ? khi : vhi;
    __nv_bfloat16* olo = (z == 0) ? qlo : (z == 1) ? klo : vlo;
    gemm_core(Ahi, Alo, whi + z * WSZ, wlo + z * WSZ, bias, nullptr,
              nullptr, ohi, olo, 1, blockIdx.y * 128, blockIdx.x * 128);
}

// O-projection + residual
__global__ __launch_bounds__(256, 2) void gemm_oproj(
    const __nv_bfloat16* __restrict__ Ahi, const __nv_bfloat16* __restrict__ Alo,
    const __nv_bfloat16* __restrict__ Bhi, const __nv_bfloat16* __restrict__ Blo,
    const float* __restrict__ bias, const float* __restrict__ res,
    float* __restrict__ out)
{
    gemm_core(Ahi, Alo, Bhi, Blo, bias, res, out, nullptr, nullptr, 0,
              blockIdx.y * 128, blockIdx.x * 128);
}

// ---------------- tensor-core flash attention ----------------------------------
#define ROWB 144
#define AKV_OFF (2 * 128 * ROWB)
#define AKV_STAGE (4 * 64 * ROWB)
#define AMSK_OFF (AKV_OFF + 2 * AKV_STAGE)
#define ATTN_SMEM (AMSK_OFF + 512)

__device__ __forceinline__ void attn_load_kv(
    uint32_t smb, const __nv_bfloat16* khi, const __nv_bfloat16* klo,
    const __nv_bfloat16* vhi, const __nv_bfloat16* vlo,
    const float* mask, int bh, int b, int kt, int st, int tid)
{
    const __nv_bfloat16* srcs[4] = {khi, klo, vhi, vlo};
    uint32_t base = smb + AKV_OFF + st * AKV_STAGE;
#pragma unroll
    for (int bf = 0; bf < 4; bf++) {
        const __nv_bfloat16* sp = srcs[bf] + ((size_t)bh * N_S + kt * 64) * D_HEAD;
        uint32_t db = base + bf * (64 * ROWB);
#pragma unroll
        for (int rep = 0; rep < 2; rep++) {
            int idx = tid + rep * 256;
            int r = idx >> 3, cq = idx & 7;
            cp16(db + r * ROWB + cq * 16, sp + (size_t)r * D_HEAD + cq * 8);
        }
    }
    if (tid < 16)
        cp16(smb + AMSK_OFF + st * 256 + tid * 16, mask + (size_t)b * N_S + kt * 64 + tid * 4);
}

__global__ __launch_bounds__(256) void attn_mma(
    const __nv_bfloat16* __restrict__ qhi, const __nv_bfloat16* __restrict__ qlo,
    const __nv_bfloat16* __restrict__ khi, const __nv_bfloat16* __restrict__ klo,
    const __nv_bfloat16* __restrict__ vhi, const __nv_bfloat16* __restrict__ vlo,
    const float* __restrict__ mask,
    __nv_bfloat16* __restrict__ chi, __nv_bfloat16* __restrict__ clo)
{
    extern __shared__ char smraw[];
    const uint32_t smb = s2u(smraw);
    const int bh = blockIdx.x;
    const int qt = blockIdx.y;
    const int b = bh >> 4;
    const int h = bh & 15;
    const int tid = threadIdx.x;
    const int lane = tid & 31;
    const int wid = tid >> 5;
    const int wrow = wid * 16;

    {
        const __nv_bfloat16* qs[2] = {qhi, qlo};
#pragma unroll
        for (int buf = 0; buf < 2; buf++) {
            const __nv_bfloat16* sp = qs[buf] + ((size_t)bh * N_S + qt * 128) * D_HEAD;
            uint32_t db = smb + buf * (128 * ROWB);
#pragma unroll
            for (int rep = 0; rep < 4; rep++) {
                int idx = tid + rep * 256;
                int r = idx >> 3, cq = idx & 7;
                cp16(db + r * ROWB + cq * 16, sp + (size_t)r * D_HEAD + cq * 8);
            }
        }
        attn_load_kv(smb, khi, klo, vhi, vlo, mask, bh, b, 0, 0, tid);
        CP_COMMIT();
        attn_load_kv(smb, khi, klo, vhi, vlo, mask, bh, b, 1, 1, tid);
        CP_COMMIT();
    }

    float o[8][4];
#pragma unroll
    for (int ni = 0; ni < 8; ni++)
#pragma unroll
        for (int e = 0; e < 4; e++) o[ni][e] = 0.0f;
    float m_run[2] = {-3.0e38f, -3.0e38f};
    float l_run[2] = {0.0f, 0.0f};

    uint32_t qh[4][4], ql[4][4];
    const uint32_t a_row = lane & 15;
    const uint32_t a_coff = (lane >> 4) * 16;
    const uint32_t b_row = (lane & 7) + ((lane >> 4) << 3);
    const uint32_t b_coff = ((lane >> 3) & 1) * 16;
    const uint32_t v_row = (lane & 7) + ((lane >> 3) & 1) * 8;
    const uint32_t v_coff = (lane >> 4) * 16;
    const float scale = 0.125f;

    int st = 0;
    for (int kt = 0; kt < N_S / 64; kt++) {
        CP_WAIT1();
        __syncthreads();
        if (kt == 0) {
#pragma unroll
            for (int kk = 0; kk < 4; kk++) {
                uint32_t ad = smb + (wrow + a_row) * ROWB + kk * 32 + a_coff;
                LDM_X4(qh[kk][0], qh[kk][1], qh[kk][2], qh[kk][3], ad);
                LDM_X4(ql[kk][0], ql[kk][1], ql[kk][2], ql[kk][3], ad + 128 * ROWB);
            }
        }
        uint32_t kvb = smb + AKV_OFF + st * AKV_STAGE;

        float s[8][4];
#pragma unroll
        for (int ni = 0; ni < 8; ni++)
#pragma unroll
            for (int e = 0; e < 4; e++) s[ni][e] = 0.0f;

#pragma unroll
        for (int kk = 0; kk < 4; kk++) {
#pragma unroll
            for (int ni2 = 0; ni2 < 4; ni2++) {
                uint32_t ro = (ni2 * 16 + b_row) * ROWB + kk * 32 + b_coff;
                uint32_t kh[4], kl[4];
                LDM_X4(kh[0], kh[1], kh[2], kh[3], kvb + ro);
                LDM_X4(kl[0], kl[1], kl[2], kl[3], kvb + 64 * ROWB + ro);
                MMA_BF16(s[2 * ni2], qh[kk], kh);
                MMA_BF16(s[2 * ni2], qh[kk], kl);
                MMA_BF16(s[2 * ni2], ql[kk], kh);
                MMA_BF16(s[2 * ni2 + 1], qh[kk], kh + 2);
                MMA_BF16(s[2 * ni2 + 1], qh[kk], kl + 2);
                MMA_BF16(s[2 * ni2 + 1], ql[kk], kh + 2);
            }
        }

        float2 mv[8];
#pragma unroll
        for (int ni = 0; ni < 8; ni++)
            mv[ni] = *(float2*)(smraw + AMSK_OFF + st * 256 +
                                (ni * 8 + 2 * (lane & 3)) * 4);
#pragma unroll
        for (int hf = 0; hf < 2; hf++) {
            float mx = -3.0e38f;
#pragma unroll
            for (int ni = 0; ni < 8; ni++) {
                float v0 = s[ni][2 * hf] * scale + mv[ni].x;
                float v1 = s[ni][2 * hf + 1] * scale + mv[ni].y;
                s[ni][2 * hf] = v0; s[ni][2 * hf + 1] = v1;
                mx = fmaxf(mx, fmaxf(v0, v1));
            }
            mx = fmaxf(mx, __shfl_xor_sync(0xffffffffu, mx, 1));
            mx = fmaxf(mx, __shfl_xor_sync(0xffffffffu, mx, 2));
            float mnew = fmaxf(m_run[hf], mx);
            float alpha = __expf(m_run[hf] - mnew);
            float sum = 0.0f;
#pragma unroll
            for (int ni = 0; ni < 8; ni++) {
                float p0 = __expf(s[ni][2 * hf] - mnew);
                float p1 = __expf(s[ni][2 * hf + 1] - mnew);
                s[ni][2 * hf] = p0; s[ni][2 * hf + 1] = p1;
                sum += p0 + p1;
            }
            sum += __shfl_xor_sync(0xffffffffu, sum, 1);
            sum += __shfl_xor_sync(0xffffffffu, sum, 2);
            l_run[hf] = l_run[hf] * alpha + sum;
            m_run[hf] = mnew;
#pragma unroll
            for (int ni = 0; ni < 8; ni++) {
                o[ni][2 * hf] *= alpha;
                o[ni][2 * hf + 1] *= alpha;
            }
        }

        uint32_t vbb = kvb + 2 * 64 * ROWB;
#pragma unroll
        for (int kk = 0; kk < 4; kk++) {
            uint32_t pah[4], pal[4];
            pah[0] = pk2(s[2 * kk][0], s[2 * kk][1]);
            pah[1] = pk2(s[2 * kk][2], s[2 * kk][3]);
            pah[2] = pk2(s[2 * kk + 1][0], s[2 * kk + 1][1]);
            pah[3] = pk2(s[2 * kk + 1][2], s[2 * kk + 1][3]);
            pal[0] = pk2lo(s[2 * kk][0], s[2 * kk][1], pah[0]);
            pal[1] = pk2lo(s[2 * kk][2], s[2 * kk][3], pah[1]);
            pal[2] = pk2lo(s[2 * kk + 1][0], s[2 * kk + 1][1], pah[2]);
            pal[3] = pk2lo(s[2 * kk + 1][2], s[2 * kk + 1][3], pah[3]);
#pragma unroll
            for (int ni2 = 0; ni2 < 4; ni2++) {
                uint32_t ro = (kk * 16 + v_row) * ROWB + ni2 * 32 + v_coff;
                uint32_t vh[4], vl[4];
                LDM_X4_T(vh[0], vh[1], vh[2], vh[3], vbb + ro);
                LDM_X4_T(vl[0], vl[1], vl[2], vl[3], vbb + 64 * ROWB + ro);
                MMA_BF16(o[2 * ni2], pah, vh);
                MMA_BF16(o[2 * ni2], pah, vl);
                MMA_BF16(o[2 * ni2], pal, vh);
                MMA_BF16(o[2 * ni2 + 1], pah, vh + 2);
                MMA_BF16(o[2 * ni2 + 1], pah, vl + 2);
                MMA_BF16(o[2 * ni2 + 1], pal, vh + 2);
            }
        }

        __syncthreads();
        if (kt + 2 < N_S / 64)
            attn_load_kv(smb, khi, klo, vhi, vlo, mask, bh, b, kt + 2, st, tid);
        CP_COMMIT();
        st ^= 1;
    }

#pragma unroll
    for (int hf = 0; hf < 2; hf++) {
        float inv = 1.0f / l_run[hf];
        int row = qt * 128 + wrow + (lane >> 2) + hf * 8;
        size_t mrow = ((size_t)(b * N_S + row)) * D_EMBED + h * D_HEAD;
#pragma unroll
        for (int ni = 0; ni < 8; ni++) {
            int d = ni * 8 + 2 * (lane & 3);
            float a = o[ni][2 * hf] * inv;
            float bb2 = o[ni][2 * hf + 1] * inv;
            uint32_t h2 = pk2(a, bb2);
            uint32_t l2 = pk2lo(a, bb2, h2);
            *(uint32_t*)(chi + mrow + d) = h2;
            *(uint32_t*)(clo + mrow + d) = l2;
        }
    }
}

// ---------------- LayerNorm ----------------------------------------------------
__global__ __launch_bounds__(256) void ln_kernel(
    const float* __restrict__ X, const float* __restrict__ g,
    const float* __restrict__ be, float* __restrict__ out)
{
    __shared__ float red[8];
    const int row = blockIdx.x;
    const int tid = threadIdx.x;
    const float* xr = X + (size_t)row * D_EMBED;
    float4 v = *(const float4*)(xr + tid * 4);
    float s = (v.x + v.y) + (v.z + v.w);
#pragma unroll
    for (int o = 16; o >= 1; o >>= 1) s += __shfl_xor_sync(0xffffffffu, s, o);
    if ((tid & 31) == 0) red[tid >> 5] = s;
    __syncthreads();
    float tot = red[0] + red[1] + red[2] + red[3] +
                red[4] + red[5] + red[6] + red[7];
    float mu = tot * (1.0f / D_EMBED);
    float d0 = v.x - mu, d1 = v.y - mu, d2 = v.z - mu, d3 = v.w - mu;
    float sq = d0 * d0 + d1 * d1 + d2 * d2 + d3 * d3;
#pragma unroll
    for (int o = 16; o >= 1; o >>= 1) sq += __shfl_xor_sync(0xffffffffu, sq, o);
    __syncthreads();
    if ((tid & 31) == 0) red[tid >> 5] = sq;
    __syncthreads();
    float var = (red[0] + red[1] + red[2] + red[3] +
                 red[4] + red[5] + red[6] + red[7]) * (1.0f / D_EMBED);
    float r = rsqrtf(var + 1e-12f);
    float4 gv = *(const float4*)(g + tid * 4);
    float4 bv = *(const float4*)(be + tid * 4);
    float4 o;
    o.x = d0 * r * gv.x + bv.x;
    o.y = d1 * r * gv.y + bv.y;
    o.z = d2 * r * gv.z + bv.z;
    o.w = d3 * r * gv.w + bv.w;
    *(float4*)(out + (size_t)row * D_EMBED + tid * 4) = o;
}

// ---------------- launch --------------------------------------------------------
extern "C" void kernel_launch(void* const* d_in, const int* in_sizes, int n_in,
                              void* d_out, int out_size)
{
    const float* X     = (const float*)d_in[0];
    const float* mask  = (const float*)d_in[1];
    const float* Wq    = (const float*)d_in[2];
    const float* bq    = (const float*)d_in[3];
    const float* Wk    = (const float*)d_in[4];
    const float* bk    = (const float*)d_in[5];
    const float* Wv    = (const float*)d_in[6];
    const float* bv    = (const float*)d_in[7];
    const float* Wo    = (const float*)d_in[8];
    const float* bo    = (const float*)d_in[9];
    const float* gamma = (const float*)d_in[10];
    const float* beta  = (const float*)d_in[11];
    float* out = (float*)d_out;

    float *x;
    __nv_bfloat16 *xhi, *xlo, *chi, *clo, *whi, *wlo;
    __nv_bfloat16 *qhi, *qlo, *khi, *klo, *vhi, *vlo;
    cudaGetSymbolAddress((void**)&x, g_x);
    cudaGetSymbolAddress((void**)&xhi, g_xhi);
    cudaGetSymbolAddress((void**)&xlo, g_xlo);
    cudaGetSymbolAddress((void**)&chi, g_chi);
    cudaGetSymbolAddress((void**)&clo, g_clo);
    cudaGetSymbolAddress((void**)&whi, g_whi);
    cudaGetSymbolAddress((void**)&wlo, g_wlo);
    cudaGetSymbolAddress((void**)&qhi, g_qhi);
    cudaGetSymbolAddress((void**)&qlo, g_qlo);
    cudaGetSymbolAddress((void**)&khi, g_khi);
    cudaGetSymbolAddress((void**)&klo, g_klo);
    cudaGetSymbolAddress((void**)&vhi, g_vhi);
    cudaGetSymbolAddress((void**)&vlo, g_vlo);

    cudaFuncSetAttribute(attn_mma, cudaFuncAttributeMaxDynamicSharedMemorySize,
                         ATTN_SMEM);
    cudaFuncSetAttribute(gemm_qkv, cudaFuncAttributeMaxDynamicSharedMemorySize,
                         GEMM_SMEM);
    cudaFuncSetAttribute(gemm_oproj, cudaFuncAttributeMaxDynamicSharedMemorySize,
                         GEMM_SMEM);

    const size_t WSZ = (size_t)D_EMBED * D_EMBED;
    split_bf16<<<(N_M * D_EMBED / 4 + 255) / 256, 256>>>(X, xhi, xlo, N_M * D_EMBED / 4);
    split_w4<<<dim3(WSZ / 4 / 256, 4), 256>>>(Wq, Wk, Wv, Wo, whi, wlo);

    gemm_qkv<<<dim3(D_EMBED / 128, N_M / 128, 3), 256, GEMM_SMEM>>>(
        xhi, xlo, whi, wlo, bq, bk, bv, qhi, qlo, khi, klo, vhi, vlo);
    attn_mma<<<dim3(N_B * N_HEADS, N_S / 128), 256, ATTN_SMEM>>>(
        qhi, qlo, khi, klo, vhi, vlo, mask, chi, clo);
    gemm_oproj<<<dim3(D_EMBED / 128, N_M / 128), 256, GEMM_SMEM>>>(
        chi, clo, whi + 3 * WSZ, wlo + 3 * WSZ, bo, X, x);
    ln_kernel<<<N_M, 256>>>(x, gamma, beta, out);
}

// round 6
// speedup vs baseline: 2.6266x; 1.0400x over previous
#include <cuda_runtime.h>
#include <cuda_bf16.h>
#include <cstdint>
#include <math.h>

#define D_EMBED 1024
#define N_HEADS 16
#define D_HEAD  64
#define N_B     2
#define N_S     2048
#define N_M     (N_B * N_S)   // 4096 rows
#define SZ      ((size_t)N_B * N_HEADS * N_S * D_HEAD)   // 4M elems per buffer

// ---------------- scratch -----------------------------------------------------
__device__ __align__(16) float g_x[(size_t)N_M * D_EMBED];
__device__ __align__(16) __nv_bfloat16 g_xhi[(size_t)N_M * D_EMBED];
__device__ __align__(16) __nv_bfloat16 g_xlo[(size_t)N_M * D_EMBED];
__device__ __align__(16) __nv_bfloat16 g_chi[(size_t)N_M * D_EMBED];
__device__ __align__(16) __nv_bfloat16 g_clo[(size_t)N_M * D_EMBED];
__device__ __align__(16) __nv_bfloat16 g_whi[4 * D_EMBED * D_EMBED];
__device__ __align__(16) __nv_bfloat16 g_wlo[4 * D_EMBED * D_EMBED];
// [qhi | qlo | khi | klo | vhi | vlo], each SZ elements
__device__ __align__(16) __nv_bfloat16 g_qkv[6 * SZ];

// ---------------- helpers -----------------------------------------------------
__device__ __forceinline__ uint32_t s2u(const void* p) {
    uint32_t a;
    asm("{ .reg .u64 t; cvta.to.shared.u64 t, %1; cvt.u32.u64 %0, t; }"
        : "=r"(a) : "l"(p));
    return a;
}
__device__ __forceinline__ void cp16(uint32_t dst, const void* src) {
    asm volatile("cp.async.cg.shared.global [%0], [%1], 16;"
                 :: "r"(dst), "l"(src) : "memory");
}
#define CP_COMMIT() asm volatile("cp.async.commit_group;" ::: "memory")
#define CP_WAIT1()  asm volatile("cp.async.wait_group 1;" ::: "memory")

#define LDM_X4(r0, r1, r2, r3, addr) \
    asm volatile("ldmatrix.sync.aligned.m8n8.x4.shared.b16 {%0,%1,%2,%3}, [%4];" \
                 : "=r"(r0), "=r"(r1), "=r"(r2), "=r"(r3) : "r"(addr))
#define LDM_X4_T(r0, r1, r2, r3, addr) \
    asm volatile("ldmatrix.sync.aligned.m8n8.x4.trans.shared.b16 {%0,%1,%2,%3}, [%4];" \
                 : "=r"(r0), "=r"(r1), "=r"(r2), "=r"(r3) : "r"(addr))

#define MMA_BF16(c, a, b) \
    asm volatile( \
        "mma.sync.aligned.m16n8k16.row.col.f32.bf16.bf16.f32 " \
        "{%0,%1,%2,%3}, {%4,%5,%6,%7}, {%8,%9}, {%0,%1,%2,%3};" \
        : "+f"((c)[0]), "+f"((c)[1]), "+f"((c)[2]), "+f"((c)[3]) \
        : "r"((a)[0]), "r"((a)[1]), "r"((a)[2]), "r"((a)[3]), \
          "r"((b)[0]), "r"((b)[1]))

__device__ __forceinline__ uint32_t pk2(float a, float b) {
    __nv_bfloat162 t;
    t.x = __float2bfloat16(a);
    t.y = __float2bfloat16(b);
    return *(uint32_t*)&t;
}
__device__ __forceinline__ uint32_t pk2lo(float a, float b, uint32_t hi) {
    __nv_bfloat162 t = *(__nv_bfloat162*)&hi;
    return pk2(a - __bfloat162float(t.x), b - __bfloat162float(t.y));
}

// ---------------- splits --------------------------------------------------------
__global__ __launch_bounds__(256) void split_bf16(
    const float* __restrict__ src, __nv_bfloat16* __restrict__ hi,
    __nv_bfloat16* __restrict__ lo, int n4)
{
    int i = blockIdx.x * blockDim.x + threadIdx.x;
    if (i >= n4) return;
    float4 v = ((const float4*)src)[i];
    uint32_t h0 = pk2(v.x, v.y), h1 = pk2(v.z, v.w);
    uint32_t l0 = pk2lo(v.x, v.y, h0), l1 = pk2lo(v.z, v.w, h1);
    ((uint32_t*)hi)[2 * i + 0] = h0;
    ((uint32_t*)hi)[2 * i + 1] = h1;
    ((uint32_t*)lo)[2 * i + 0] = l0;
    ((uint32_t*)lo)[2 * i + 1] = l1;
}

__global__ __launch_bounds__(256) void split_w4(
    const float* __restrict__ w0, const float* __restrict__ w1,
    const float* __restrict__ w2, const float* __restrict__ w3,
    __nv_bfloat16* __restrict__ hi, __nv_bfloat16* __restrict__ lo)
{
    const int z = blockIdx.y;
    const float* src = (z == 0) ? w0 : (z == 1) ? w1 : (z == 2) ? w2 : w3;
    size_t off = (size_t)z * D_EMBED * D_EMBED;
    int i = blockIdx.x * blockDim.x + threadIdx.x;
    float4 v = ((const float4*)src)[i];
    uint32_t h0 = pk2(v.x, v.y), h1 = pk2(v.z, v.w);
    uint32_t l0 = pk2lo(v.x, v.y, h0), l1 = pk2lo(v.z, v.w, h1);
    ((uint32_t*)(hi + off))[2 * i + 0] = h0;
    ((uint32_t*)(hi + off))[2 * i + 1] = h1;
    ((uint32_t*)(lo + off))[2 * i + 0] = l0;
    ((uint32_t*)(lo + off))[2 * i + 1] = l1;
}

// ---------------- bf16-split tensor GEMM core ------------------------------------
#define BUF_B  (128 * 80)
#define STAGE_B (4 * BUF_B)
#define GSTAGES 2
#define GEMM_SMEM (GSTAGES * STAGE_B)   // 81920

__device__ __forceinline__ void load_stage(
    uint32_t st, const __nv_bfloat16* Ahi, const __nv_bfloat16* Alo,
    const __nv_bfloat16* Bhi, const __nv_bfloat16* Blo,
    int bm, int bn, int kb, int tid)
{
    const __nv_bfloat16* srcs[4] = {Ahi, Alo, Bhi, Blo};
    const int rowoff[4] = {bm, bm, bn, bn};
#pragma unroll
    for (int bf = 0; bf < 4; bf++) {
        const __nv_bfloat16* sb = srcs[bf] + (size_t)rowoff[bf] * D_EMBED + kb * 32;
        uint32_t db = st + bf * BUF_B;
#pragma unroll
        for (int i = 0; i < 2; i++) {
            int c = tid + i * 256;
            int row = c >> 2, kc = c & 3;
            cp16(db + row * 80 + kc * 16, sb + (size_t)row * D_EMBED + kc * 8);
        }
    }
}

__device__ __forceinline__ void gemm_core(
    const __nv_bfloat16* Ahi, const __nv_bfloat16* Alo,
    const __nv_bfloat16* Bhi, const __nv_bfloat16* Blo,
    const float* bias, const float* res, float* out,
    __nv_bfloat16* out_hi, int qkv, int bm, int bn)
{
    extern __shared__ char smraw[];
    const uint32_t smb = s2u(smraw);
    const int tid = threadIdx.x;
    const int lane = tid & 31;
    const int wid = tid >> 5;
    const int warp_m = (wid >> 2) * 64;
    const int warp_n = (wid & 3) * 32;

    float c[4][4][4];
#pragma unroll
    for (int mi = 0; mi < 4; mi++)
#pragma unroll
        for (int ni = 0; ni < 4; ni++)
#pragma unroll
            for (int e = 0; e < 4; e++) c[mi][ni][e] = 0.0f;

#pragma unroll
    for (int p = 0; p < GSTAGES; p++) {
        load_stage(smb + p * STAGE_B, Ahi, Alo, Bhi, Blo, bm, bn, p, tid);
        CP_COMMIT();
    }

    const uint32_t a_row = lane & 15;
    const uint32_t a_coff = (lane >> 4) * 16;
    const uint32_t b_row = (lane & 7) + ((lane >> 4) << 3);
    const uint32_t b_coff = ((lane >> 3) & 1) * 16;

    int s = 0;
    for (int kb = 0; kb < D_EMBED / 32; kb++) {
        CP_WAIT1();
        __syncthreads();
        uint32_t st = smb + s * STAGE_B;
        uint32_t ah_b = st, al_b = st + BUF_B;
        uint32_t bh_b = st + 2 * BUF_B, bl_b = st + 3 * BUF_B;

#pragma unroll
        for (int k16 = 0; k16 < 2; k16++) {
            uint32_t akoff = k16 * 32 + a_coff;
            uint32_t bkoff = k16 * 32 + b_coff;
            uint32_t ah[4][4], al[4][4], bh[4][2], bl[4][2];
#pragma unroll
            for (int mi = 0; mi < 4; mi++) {
                uint32_t ro = (warp_m + mi * 16 + a_row) * 80 + akoff;
                LDM_X4(ah[mi][0], ah[mi][1], ah[mi][2], ah[mi][3], ah_b + ro);
                LDM_X4(al[mi][0], al[mi][1], al[mi][2], al[mi][3], al_b + ro);
            }
#pragma unroll
            for (int ni2 = 0; ni2 < 2; ni2++) {
                uint32_t ro = (warp_n + ni2 * 16 + b_row) * 80 + bkoff;
                LDM_X4(bh[ni2 * 2][0], bh[ni2 * 2][1],
                       bh[ni2 * 2 + 1][0], bh[ni2 * 2 + 1][1], bh_b + ro);
                LDM_X4(bl[ni2 * 2][0], bl[ni2 * 2][1],
                       bl[ni2 * 2 + 1][0], bl[ni2 * 2 + 1][1], bl_b + ro);
            }
#pragma unroll
            for (int mi = 0; mi < 4; mi++)
#pragma unroll
                for (int ni = 0; ni < 4; ni++) {
                    MMA_BF16(c[mi][ni], ah[mi], bh[ni]);
                    MMA_BF16(c[mi][ni], ah[mi], bl[ni]);
                    MMA_BF16(c[mi][ni], al[mi], bh[ni]);
                }
        }
        __syncthreads();
        if (kb + GSTAGES < D_EMBED / 32)
            load_stage(st, Ahi, Alo, Bhi, Blo, bm, bn, kb + GSTAGES, tid);
        CP_COMMIT();
        s ^= 1;
    }

#pragma unroll
    for (int mi = 0; mi < 4; mi++) {
#pragma unroll
        for (int half = 0; half < 2; half++) {
            int m = bm + warp_m + mi * 16 + (lane >> 2) + half * 8;
            int bb = m >> 11, sdx = m & (N_S - 1);
#pragma unroll
            for (int ni = 0; ni < 4; ni++) {
                int n = bn + warp_n + ni * 8 + 2 * (lane & 3);
                float2 o;
                o.x = c[mi][ni][half * 2 + 0] + bias[n];
                o.y = c[mi][ni][half * 2 + 1] + bias[n + 1];
                if (res) {
                    float2 rv = *(const float2*)(res + (size_t)m * D_EMBED + n);
                    o.x += rv.x; o.y += rv.y;
                }
                if (qkv) {
                    int h = n >> 6, d = n & 63;
                    size_t off = (((size_t)(bb * N_HEADS + h)) * N_S + sdx) * D_HEAD + d;
                    uint32_t h2 = pk2(o.x, o.y);
                    uint32_t l2 = pk2lo(o.x, o.y, h2);
                    *(uint32_t*)(out_hi + off) = h2;
                    *(uint32_t*)(out_hi + SZ + off) = l2;
                } else {
                    *(float2*)(out + (size_t)m * D_EMBED + n) = o;
                }
            }
        }
    }
}

// merged QKV: grid (8, 32, 3); z selects weight/bias/output pair
__global__ __launch_bounds__(256, 2) void gemm_qkv(
    const __nv_bfloat16* __restrict__ Ahi, const __nv_bfloat16* __restrict__ Alo,
    const __nv_bfloat16* __restrict__ whi, const __nv_bfloat16* __restrict__ wlo,
    const float* __restrict__ bq, const float* __restrict__ bk,
    const float* __restrict__ bv, __nv_bfloat16* __restrict__ qkv)
{
    const int z = blockIdx.z;
    const size_t WSZ = (size_t)D_EMBED * D_EMBED;
    const float* bias = (z == 0) ? bq : (z == 1) ? bk : bv;
    gemm_core(Ahi, Alo, whi + z * WSZ, wlo + z * WSZ, bias, nullptr,
              nullptr, qkv + (size_t)(2 * z) * SZ, 1,
              blockIdx.y * 128, blockIdx.x * 128);
}

__global__ __launch_bounds__(256, 2) void gemm_oproj(
    const __nv_bfloat16* __restrict__ Ahi, const __nv_bfloat16* __restrict__ Alo,
    const __nv_bfloat16* __restrict__ Bhi, const __nv_bfloat16* __restrict__ Blo,
    const float* __restrict__ bias, const float* __restrict__ res,
    float* __restrict__ out)
{
    gemm_core(Ahi, Alo, Bhi, Blo, bias, res, out, nullptr, 0,
              blockIdx.y * 128, blockIdx.x * 128);
}

// ---------------- tensor-core flash attention ----------------------------------
#define ROWB 144
#define AKV_OFF (2 * 128 * ROWB)
#define AKV_STAGE (4 * 64 * ROWB)
#define AMSK_OFF (AKV_OFF + 2 * AKV_STAGE)
#define ATTN_SMEM (AMSK_OFF + 512)

__device__ __forceinline__ void attn_load_kv(
    uint32_t smb, const __nv_bfloat16* qkv,
    const float* mask, int bh, int b, int kt, int st, int tid)
{
    size_t goff = ((size_t)bh * N_S + kt * 64) * D_HEAD;
    uint32_t base = smb + AKV_OFF + st * AKV_STAGE;
#pragma unroll
    for (int bf = 0; bf < 4; bf++) {
        const __nv_bfloat16* sp = qkv + (size_t)(2 + bf) * SZ + goff;
        uint32_t db = base + bf * (64 * ROWB);
#pragma unroll
        for (int rep = 0; rep < 2; rep++) {
            int idx = tid + rep * 256;
            int r = idx >> 3, cq = idx & 7;
            cp16(db + r * ROWB + cq * 16, sp + (size_t)r * D_HEAD + cq * 8);
        }
    }
    if (tid < 16)
        cp16(smb + AMSK_OFF + st * 256 + tid * 16, mask + (size_t)b * N_S + kt * 64 + tid * 4);
}

__global__ __launch_bounds__(256, 2) void attn_mma(
    const __nv_bfloat16* __restrict__ qkv, const float* __restrict__ mask,
    __nv_bfloat16* __restrict__ chi, __nv_bfloat16* __restrict__ clo)
{
    extern __shared__ char smraw[];
    const uint32_t smb = s2u(smraw);
    const int bh = blockIdx.x;
    const int qt = blockIdx.y;
    const int b = bh >> 4;
    const int h = bh & 15;
    const int tid = threadIdx.x;
    const int lane = tid & 31;
    const int wid = tid >> 5;
    const int wrow = wid * 16;

    {
        size_t qoff = ((size_t)bh * N_S + qt * 128) * D_HEAD;
#pragma unroll
        for (int buf = 0; buf < 2; buf++) {
            const __nv_bfloat16* sp = qkv + (size_t)buf * SZ + qoff;
            uint32_t db = smb + buf * (128 * ROWB);
#pragma unroll
            for (int rep = 0; rep < 4; rep++) {
                int idx = tid + rep * 256;
                int r = idx >> 3, cq = idx & 7;
                cp16(db + r * ROWB + cq * 16, sp + (size_t)r * D_HEAD + cq * 8);
            }
        }
        attn_load_kv(smb, qkv, mask, bh, b, 0, 0, tid);
        CP_COMMIT();
        attn_load_kv(smb, qkv, mask, bh, b, 1, 1, tid);
        CP_COMMIT();
    }

    float o[8][4];
#pragma unroll
    for (int ni = 0; ni < 8; ni++)
#pragma unroll
        for (int e = 0; e < 4; e++) o[ni][e] = 0.0f;
    float m_run[2] = {-3.0e38f, -3.0e38f};
    float l_run[2] = {0.0f, 0.0f};

    uint32_t qh[4][4], ql[4][4];
    const uint32_t a_row = lane & 15;
    const uint32_t a_coff = (lane >> 4) * 16;
    const uint32_t b_row = (lane & 7) + ((lane >> 4) << 3);
    const uint32_t b_coff = ((lane >> 3) & 1) * 16;
    const uint32_t v_row = (lane & 7) + ((lane >> 3) & 1) * 8;
    const uint32_t v_coff = (lane >> 4) * 16;
    const float scale = 0.125f;

    int st = 0;
    for (int kt = 0; kt < N_S / 64; kt++) {
        CP_WAIT1();
        __syncthreads();
        if (kt == 0) {
#pragma unroll
            for (int kk = 0; kk < 4; kk++) {
                uint32_t ad = smb + (wrow + a_row) * ROWB + kk * 32 + a_coff;
                LDM_X4(qh[kk][0], qh[kk][1], qh[kk][2], qh[kk][3], ad);
                LDM_X4(ql[kk][0], ql[kk][1], ql[kk][2], ql[kk][3], ad + 128 * ROWB);
            }
        }
        uint32_t kvb = smb + AKV_OFF + st * AKV_STAGE;

        float s[8][4];
#pragma unroll
        for (int ni = 0; ni < 8; ni++)
#pragma unroll
            for (int e = 0; e < 4; e++) s[ni][e] = 0.0f;

#pragma unroll
        for (int kk = 0; kk < 4; kk++) {
#pragma unroll
            for (int ni2 = 0; ni2 < 4; ni2++) {
                uint32_t ro = (ni2 * 16 + b_row) * ROWB + kk * 32 + b_coff;
                uint32_t kh[4], kl[4];
                LDM_X4(kh[0], kh[1], kh[2], kh[3], kvb + ro);
                LDM_X4(kl[0], kl[1], kl[2], kl[3], kvb + 64 * ROWB + ro);
                MMA_BF16(s[2 * ni2], qh[kk], kh);
                MMA_BF16(s[2 * ni2], qh[kk], kl);
                MMA_BF16(s[2 * ni2], ql[kk], kh);
                MMA_BF16(s[2 * ni2 + 1], qh[kk], kh + 2);
                MMA_BF16(s[2 * ni2 + 1], qh[kk], kl + 2);
                MMA_BF16(s[2 * ni2 + 1], ql[kk], kh + 2);
            }
        }

        float2 mv[8];
#pragma unroll
        for (int ni = 0; ni < 8; ni++)
            mv[ni] = *(float2*)(smraw + AMSK_OFF + st * 256 +
                                (ni * 8 + 2 * (lane & 3)) * 4);
#pragma unroll
        for (int hf = 0; hf < 2; hf++) {
            float mx = -3.0e38f;
#pragma unroll
            for (int ni = 0; ni < 8; ni++) {
                float v0 = s[ni][2 * hf] * scale + mv[ni].x;
                float v1 = s[ni][2 * hf + 1] * scale + mv[ni].y;
                s[ni][2 * hf] = v0; s[ni][2 * hf + 1] = v1;
                mx = fmaxf(mx, fmaxf(v0, v1));
            }
            mx = fmaxf(mx, __shfl_xor_sync(0xffffffffu, mx, 1));
            mx = fmaxf(mx, __shfl_xor_sync(0xffffffffu, mx, 2));
            float mnew = fmaxf(m_run[hf], mx);
            float alpha = __expf(m_run[hf] - mnew);
            float sum = 0.0f;
#pragma unroll
            for (int ni = 0; ni < 8; ni++) {
                float p0 = __expf(s[ni][2 * hf] - mnew);
                float p1 = __expf(s[ni][2 * hf + 1] - mnew);
                s[ni][2 * hf] = p0; s[ni][2 * hf + 1] = p1;
                sum += p0 + p1;
            }
            sum += __shfl_xor_sync(0xffffffffu, sum, 1);
            sum += __shfl_xor_sync(0xffffffffu, sum, 2);
            l_run[hf] = l_run[hf] * alpha + sum;
            m_run[hf] = mnew;
#pragma unroll
            for (int ni = 0; ni < 8; ni++) {
                o[ni][2 * hf] *= alpha;
                o[ni][2 * hf + 1] *= alpha;
            }
        }

        uint32_t vbb = kvb + 2 * 64 * ROWB;
#pragma unroll
        for (int kk = 0; kk < 4; kk++) {
            uint32_t pah[4], pal[4];
            pah[0] = pk2(s[2 * kk][0], s[2 * kk][1]);
            pah[1] = pk2(s[2 * kk][2], s[2 * kk][3]);
            pah[2] = pk2(s[2 * kk + 1][0], s[2 * kk + 1][1]);
            pah[3] = pk2(s[2 * kk + 1][2], s[2 * kk + 1][3]);
            pal[0] = pk2lo(s[2 * kk][0], s[2 * kk][1], pah[0]);
            pal[1] = pk2lo(s[2 * kk][2], s[2 * kk][3], pah[1]);
            pal[2] = pk2lo(s[2 * kk + 1][0], s[2 * kk + 1][1], pah[2]);
            pal[3] = pk2lo(s[2 * kk + 1][2], s[2 * kk + 1][3], pah[3]);
#pragma unroll
            for (int ni2 = 0; ni2 < 4; ni2++) {
                uint32_t ro = (kk * 16 + v_row) * ROWB + ni2 * 32 + v_coff;
                uint32_t vh[4], vl[4];
                LDM_X4_T(vh[0], vh[1], vh[2], vh[3], vbb + ro);
                LDM_X4_T(vl[0], vl[1], vl[2], vl[3], vbb + 64 * ROWB + ro);
                MMA_BF16(o[2 * ni2], pah, vh);
                MMA_BF16(o[2 * ni2], pah, vl);
                MMA_BF16(o[2 * ni2], pal, vh);
                MMA_BF16(o[2 * ni2 + 1], pah, vh + 2);
                MMA_BF16(o[2 * ni2 + 1], pah, vl + 2);
                MMA_BF16(o[2 * ni2 + 1], pal, vh + 2);
            }
        }

        __syncthreads();
        if (kt + 2 < N_S / 64)
            attn_load_kv(smb, qkv, mask, bh, b, kt + 2, st, tid);
        CP_COMMIT();
        st ^= 1;
    }

#pragma unroll
    for (int hf = 0; hf < 2; hf++) {
        float inv = 1.0f / l_run[hf];
        int row = qt * 128 + wrow + (lane >> 2) + hf * 8;
        size_t mrow = ((size_t)(b * N_S + row)) * D_EMBED + h * D_HEAD;
#pragma unroll
        for (int ni = 0; ni < 8; ni++) {
            int d = ni * 8 + 2 * (lane & 3);
            float a = o[ni][2 * hf] * inv;
            float bb2 = o[ni][2 * hf + 1] * inv;
            uint32_t h2 = pk2(a, bb2);
            uint32_t l2 = pk2lo(a, bb2, h2);
            *(uint32_t*)(chi + mrow + d) = h2;
            *(uint32_t*)(clo + mrow + d) = l2;
        }
    }
}

// ---------------- LayerNorm ----------------------------------------------------
__global__ __launch_bounds__(256) void ln_kernel(
    const float* __restrict__ X, const float* __restrict__ g,
    const float* __restrict__ be, float* __restrict__ out)
{
    __shared__ float red[8];
    const int row = blockIdx.x;
    const int tid = threadIdx.x;
    const float* xr = X + (size_t)row * D_EMBED;
    float4 v = *(const float4*)(xr + tid * 4);
    float s = (v.x + v.y) + (v.z + v.w);
#pragma unroll
    for (int o = 16; o >= 1; o >>= 1) s += __shfl_xor_sync(0xffffffffu, s, o);
    if ((tid & 31) == 0) red[tid >> 5] = s;
    __syncthreads();
    float tot = red[0] + red[1] + red[2] + red[3] +
                red[4] + red[5] + red[6] + red[7];
    float mu = tot * (1.0f / D_EMBED);
    float d0 = v.x - mu, d1 = v.y - mu, d2 = v.z - mu, d3 = v.w - mu;
    float sq = d0 * d0 + d1 * d1 + d2 * d2 + d3 * d3;
#pragma unroll
    for (int o = 16; o >= 1; o >>= 1) sq += __shfl_xor_sync(0xffffffffu, sq, o);
    __syncthreads();
    if ((tid & 31) == 0) red[tid >> 5] = sq;
    __syncthreads();
    float var = (red[0] + red[1] + red[2] + red[3] +
                 red[4] + red[5] + red[6] + red[7]) * (1.0f / D_EMBED);
    float r = rsqrtf(var + 1e-12f);
    float4 gv = *(const float4*)(g + tid * 4);
    float4 bv = *(const float4*)(be + tid * 4);
    float4 o;
    o.x = d0 * r * gv.x + bv.x;
    o.y = d1 * r * gv.y + bv.y;
    o.z = d2 * r * gv.z + bv.z;
    o.w = d3 * r * gv.w + bv.w;
    *(float4*)(out + (size_t)row * D_EMBED + tid * 4) = o;
}

// ---------------- launch --------------------------------------------------------
extern "C" void kernel_launch(void* const* d_in, const int* in_sizes, int n_in,
                              void* d_out, int out_size)
{
    const float* X     = (const float*)d_in[0];
    const float* mask  = (const float*)d_in[1];
    const float* Wq    = (const float*)d_in[2];
    const float* bq    = (const float*)d_in[3];
    const float* Wk    = (const float*)d_in[4];
    const float* bk    = (const float*)d_in[5];
    const float* Wv    = (const float*)d_in[6];
    const float* bv    = (const float*)d_in[7];
    const float* Wo    = (const float*)d_in[8];
    const float* bo    = (const float*)d_in[9];
    const float* gamma = (const float*)d_in[10];
    const float* beta  = (const float*)d_in[11];
    float* out = (float*)d_out;

    float *x;
    __nv_bfloat16 *xhi, *xlo, *chi, *clo, *whi, *wlo, *qkv;
    cudaGetSymbolAddress((void**)&x, g_x);
    cudaGetSymbolAddress((void**)&xhi, g_xhi);
    cudaGetSymbolAddress((void**)&xlo, g_xlo);
    cudaGetSymbolAddress((void**)&chi, g_chi);
    cudaGetSymbolAddress((void**)&clo, g_clo);
    cudaGetSymbolAddress((void**)&whi, g_whi);
    cudaGetSymbolAddress((void**)&wlo, g_wlo);
    cudaGetSymbolAddress((void**)&qkv, g_qkv);

    cudaFuncSetAttribute(attn_mma, cudaFuncAttributeMaxDynamicSharedMemorySize,
                         ATTN_SMEM);
    cudaFuncSetAttribute(gemm_qkv, cudaFuncAttributeMaxDynamicSharedMemorySize,
                         GEMM_SMEM);
    cudaFuncSetAttribute(gemm_oproj, cudaFuncAttributeMaxDynamicSharedMemorySize,
                         GEMM_SMEM);

    const size_t WSZ = (size_t)D_EMBED * D_EMBED;
    split_bf16<<<(N_M * D_EMBED / 4 + 255) / 256, 256>>>(X, xhi, xlo, N_M * D_EMBED / 4);
    split_w4<<<dim3(WSZ / 4 / 256, 4), 256>>>(Wq, Wk, Wv, Wo, whi, wlo);

    gemm_qkv<<<dim3(D_EMBED / 128, N_M / 128, 3), 256, GEMM_SMEM>>>(
        xhi, xlo, whi, wlo, bq, bk, bv, qkv);
    attn_mma<<<dim3(N_B * N_HEADS, N_S / 128), 256, ATTN_SMEM>>>(
        qkv, mask, chi, clo);
    gemm_oproj<<<dim3(D_EMBED / 128, N_M / 128), 256, GEMM_SMEM>>>(
        chi, clo, whi + 3 * WSZ, wlo + 3 * WSZ, bo, X, x);
    ln_kernel<<<N_M, 256>>>(x, gamma, beta, out);
}

// round 7
// speedup vs baseline: 2.8416x; 1.0819x over previous
#include <cuda_runtime.h>
#include <cuda_bf16.h>
#include <cstdint>
#include <math.h>

#define D_EMBED 1024
#define N_HEADS 16
#define D_HEAD  64
#define N_B     2
#define N_S     2048
#define N_M     (N_B * N_S)   // 4096 rows
#define SZ      ((size_t)N_B * N_HEADS * N_S * D_HEAD)   // 4M elems per buffer

// ---------------- scratch -----------------------------------------------------
__device__ __align__(16) float g_x[(size_t)N_M * D_EMBED];
__device__ __align__(16) __nv_bfloat16 g_xhi[(size_t)N_M * D_EMBED];
__device__ __align__(16) __nv_bfloat16 g_xlo[(size_t)N_M * D_EMBED];
__device__ __align__(16) __nv_bfloat16 g_chi[(size_t)N_M * D_EMBED];
__device__ __align__(16) __nv_bfloat16 g_clo[(size_t)N_M * D_EMBED];
__device__ __align__(16) __nv_bfloat16 g_whi[4 * D_EMBED * D_EMBED];
__device__ __align__(16) __nv_bfloat16 g_wlo[4 * D_EMBED * D_EMBED];
// [qhi | qlo | khi | klo | vhi | vlo], each SZ elements
__device__ __align__(16) __nv_bfloat16 g_qkv[6 * SZ];

// ---------------- helpers -----------------------------------------------------
__device__ __forceinline__ uint32_t s2u(const void* p) {
    uint32_t a;
    asm("{ .reg .u64 t; cvta.to.shared.u64 t, %1; cvt.u32.u64 %0, t; }"
        : "=r"(a) : "l"(p));
    return a;
}
__device__ __forceinline__ void cp16(uint32_t dst, const void* src) {
    asm volatile("cp.async.cg.shared.global [%0], [%1], 16;"
                 :: "r"(dst), "l"(src) : "memory");
}
#define CP_COMMIT() asm volatile("cp.async.commit_group;" ::: "memory")
#define CP_WAIT1()  asm volatile("cp.async.wait_group 1;" ::: "memory")

#define LDM_X4(r0, r1, r2, r3, addr) \
    asm volatile("ldmatrix.sync.aligned.m8n8.x4.shared.b16 {%0,%1,%2,%3}, [%4];" \
                 : "=r"(r0), "=r"(r1), "=r"(r2), "=r"(r3) : "r"(addr))
#define LDM_X4_T(r0, r1, r2, r3, addr) \
    asm volatile("ldmatrix.sync.aligned.m8n8.x4.trans.shared.b16 {%0,%1,%2,%3}, [%4];" \
                 : "=r"(r0), "=r"(r1), "=r"(r2), "=r"(r3) : "r"(addr))

#define MMA_BF16(c, a, b) \
    asm volatile( \
        "mma.sync.aligned.m16n8k16.row.col.f32.bf16.bf16.f32 " \
        "{%0,%1,%2,%3}, {%4,%5,%6,%7}, {%8,%9}, {%0,%1,%2,%3};" \
        : "+f"((c)[0]), "+f"((c)[1]), "+f"((c)[2]), "+f"((c)[3]) \
        : "r"((a)[0]), "r"((a)[1]), "r"((a)[2]), "r"((a)[3]), \
          "r"((b)[0]), "r"((b)[1]))

__device__ __forceinline__ uint32_t pk2(float a, float b) {
    __nv_bfloat162 t;
    t.x = __float2bfloat16(a);
    t.y = __float2bfloat16(b);
    return *(uint32_t*)&t;
}
__device__ __forceinline__ uint32_t pk2lo(float a, float b, uint32_t hi) {
    __nv_bfloat162 t = *(__nv_bfloat162*)&hi;
    return pk2(a - __bfloat162float(t.x), b - __bfloat162float(t.y));
}

// ---------------- splits --------------------------------------------------------
__global__ __launch_bounds__(256) void split_bf16(
    const float* __restrict__ src, __nv_bfloat16* __restrict__ hi,
    __nv_bfloat16* __restrict__ lo, int n4)
{
    int i = blockIdx.x * blockDim.x + threadIdx.x;
    if (i >= n4) return;
    float4 v = ((const float4*)src)[i];
    uint32_t h0 = pk2(v.x, v.y), h1 = pk2(v.z, v.w);
    uint32_t l0 = pk2lo(v.x, v.y, h0), l1 = pk2lo(v.z, v.w, h1);
    ((uint32_t*)hi)[2 * i + 0] = h0;
    ((uint32_t*)hi)[2 * i + 1] = h1;
    ((uint32_t*)lo)[2 * i + 0] = l0;
    ((uint32_t*)lo)[2 * i + 1] = l1;
}

__global__ __launch_bounds__(256) void split_w4(
    const float* __restrict__ w0, const float* __restrict__ w1,
    const float* __restrict__ w2, const float* __restrict__ w3,
    __nv_bfloat16* __restrict__ hi, __nv_bfloat16* __restrict__ lo)
{
    const int z = blockIdx.y;
    const float* src = (z == 0) ? w0 : (z == 1) ? w1 : (z == 2) ? w2 : w3;
    size_t off = (size_t)z * D_EMBED * D_EMBED;
    int i = blockIdx.x * blockDim.x + threadIdx.x;
    float4 v = ((const float4*)src)[i];
    uint32_t h0 = pk2(v.x, v.y), h1 = pk2(v.z, v.w);
    uint32_t l0 = pk2lo(v.x, v.y, h0), l1 = pk2lo(v.z, v.w, h1);
    ((uint32_t*)(hi + off))[2 * i + 0] = h0;
    ((uint32_t*)(hi + off))[2 * i + 1] = h1;
    ((uint32_t*)(lo + off))[2 * i + 0] = l0;
    ((uint32_t*)(lo + off))[2 * i + 1] = l1;
}

// ---------------- bf16-split tensor GEMM core ------------------------------------
#define BUF_B  (128 * 80)
#define STAGE_B (4 * BUF_B)
#define GSTAGES 2
#define GEMM_SMEM (GSTAGES * STAGE_B)   // 81920

__device__ __forceinline__ void load_stage(
    uint32_t st, const __nv_bfloat16* Ahi, const __nv_bfloat16* Alo,
    const __nv_bfloat16* Bhi, const __nv_bfloat16* Blo,
    int bm, int bn, int kb, int tid)
{
    const __nv_bfloat16* srcs[4] = {Ahi, Alo, Bhi, Blo};
    const int rowoff[4] = {bm, bm, bn, bn};
#pragma unroll
    for (int bf = 0; bf < 4; bf++) {
        const __nv_bfloat16* sb = srcs[bf] + (size_t)rowoff[bf] * D_EMBED + kb * 32;
        uint32_t db = st + bf * BUF_B;
#pragma unroll
        for (int i = 0; i < 2; i++) {
            int c = tid + i * 256;
            int row = c >> 2, kc = c & 3;
            cp16(db + row * 80 + kc * 16, sb + (size_t)row * D_EMBED + kc * 8);
        }
    }
}

__device__ __forceinline__ void gemm_core(
    const __nv_bfloat16* Ahi, const __nv_bfloat16* Alo,
    const __nv_bfloat16* Bhi, const __nv_bfloat16* Blo,
    const float* bias, const float* res, float* out,
    __nv_bfloat16* out_hi, int qkv, int bm, int bn)
{
    extern __shared__ char smraw[];
    const uint32_t smb = s2u(smraw);
    const int tid = threadIdx.x;
    const int lane = tid & 31;
    const int wid = tid >> 5;
    const int warp_m = (wid >> 2) * 64;
    const int warp_n = (wid & 3) * 32;

    float c[4][4][4];
#pragma unroll
    for (int mi = 0; mi < 4; mi++)
#pragma unroll
        for (int ni = 0; ni < 4; ni++)
#pragma unroll
            for (int e = 0; e < 4; e++) c[mi][ni][e] = 0.0f;

#pragma unroll
    for (int p = 0; p < GSTAGES; p++) {
        load_stage(smb + p * STAGE_B, Ahi, Alo, Bhi, Blo, bm, bn, p, tid);
        CP_COMMIT();
    }

    const uint32_t a_row = lane & 15;
    const uint32_t a_coff = (lane >> 4) * 16;
    const uint32_t b_row = (lane & 7) + ((lane >> 4) << 3);
    const uint32_t b_coff = ((lane >> 3) & 1) * 16;

    int s = 0;
    for (int kb = 0; kb < D_EMBED / 32; kb++) {
        CP_WAIT1();
        __syncthreads();
        uint32_t st = smb + s * STAGE_B;
        uint32_t ah_b = st, al_b = st + BUF_B;
        uint32_t bh_b = st + 2 * BUF_B, bl_b = st + 3 * BUF_B;

#pragma unroll
        for (int k16 = 0; k16 < 2; k16++) {
            uint32_t akoff = k16 * 32 + a_coff;
            uint32_t bkoff = k16 * 32 + b_coff;
            uint32_t ah[4][4], al[4][4], bh[4][2], bl[4][2];
#pragma unroll
            for (int mi = 0; mi < 4; mi++) {
                uint32_t ro = (warp_m + mi * 16 + a_row) * 80 + akoff;
                LDM_X4(ah[mi][0], ah[mi][1], ah[mi][2], ah[mi][3], ah_b + ro);
                LDM_X4(al[mi][0], al[mi][1], al[mi][2], al[mi][3], al_b + ro);
            }
#pragma unroll
            for (int ni2 = 0; ni2 < 2; ni2++) {
                uint32_t ro = (warp_n + ni2 * 16 + b_row) * 80 + bkoff;
                LDM_X4(bh[ni2 * 2][0], bh[ni2 * 2][1],
                       bh[ni2 * 2 + 1][0], bh[ni2 * 2 + 1][1], bh_b + ro);
                LDM_X4(bl[ni2 * 2][0], bl[ni2 * 2][1],
                       bl[ni2 * 2 + 1][0], bl[ni2 * 2 + 1][1], bl_b + ro);
            }
#pragma unroll
            for (int mi = 0; mi < 4; mi++)
#pragma unroll
                for (int ni = 0; ni < 4; ni++) {
                    MMA_BF16(c[mi][ni], ah[mi], bh[ni]);
                    MMA_BF16(c[mi][ni], ah[mi], bl[ni]);
                    MMA_BF16(c[mi][ni], al[mi], bh[ni]);
                }
        }
        __syncthreads();
        if (kb + GSTAGES < D_EMBED / 32)
            load_stage(st, Ahi, Alo, Bhi, Blo, bm, bn, kb + GSTAGES, tid);
        CP_COMMIT();
        s ^= 1;
    }

#pragma unroll
    for (int mi = 0; mi < 4; mi++) {
#pragma unroll
        for (int half = 0; half < 2; half++) {
            int m = bm + warp_m + mi * 16 + (lane >> 2) + half * 8;
            int bb = m >> 11, sdx = m & (N_S - 1);
#pragma unroll
            for (int ni = 0; ni < 4; ni++) {
                int n = bn + warp_n + ni * 8 + 2 * (lane & 3);
                float2 o;
                o.x = c[mi][ni][half * 2 + 0] + bias[n];
                o.y = c[mi][ni][half * 2 + 1] + bias[n + 1];
                if (res) {
                    float2 rv = *(const float2*)(res + (size_t)m * D_EMBED + n);
                    o.x += rv.x; o.y += rv.y;
                }
                if (qkv) {
                    int h = n >> 6, d = n & 63;
                    size_t off = (((size_t)(bb * N_HEADS + h)) * N_S + sdx) * D_HEAD + d;
                    uint32_t h2 = pk2(o.x, o.y);
                    uint32_t l2 = pk2lo(o.x, o.y, h2);
                    *(uint32_t*)(out_hi + off) = h2;
                    *(uint32_t*)(out_hi + SZ + off) = l2;
                } else {
                    *(float2*)(out + (size_t)m * D_EMBED + n) = o;
                }
            }
        }
    }
}

// merged QKV: grid (8, 32, 3); z selects weight/bias/output pair
__global__ __launch_bounds__(256, 2) void gemm_qkv(
    const __nv_bfloat16* __restrict__ Ahi, const __nv_bfloat16* __restrict__ Alo,
    const __nv_bfloat16* __restrict__ whi, const __nv_bfloat16* __restrict__ wlo,
    const float* __restrict__ bq, const float* __restrict__ bk,
    const float* __restrict__ bv, __nv_bfloat16* __restrict__ qkv)
{
    const int z = blockIdx.z;
    const size_t WSZ = (size_t)D_EMBED * D_EMBED;
    const float* bias = (z == 0) ? bq : (z == 1) ? bk : bv;
    gemm_core(Ahi, Alo, whi + z * WSZ, wlo + z * WSZ, bias, nullptr,
              nullptr, qkv + (size_t)(2 * z) * SZ, 1,
              blockIdx.y * 128, blockIdx.x * 128);
}

__global__ __launch_bounds__(256, 2) void gemm_oproj(
    const __nv_bfloat16* __restrict__ Ahi, const __nv_bfloat16* __restrict__ Alo,
    const __nv_bfloat16* __restrict__ Bhi, const __nv_bfloat16* __restrict__ Blo,
    const float* __restrict__ bias, const float* __restrict__ res,
    float* __restrict__ out)
{
    gemm_core(Ahi, Alo, Bhi, Blo, bias, res, out, nullptr, 0,
              blockIdx.y * 128, blockIdx.x * 128);
}

// ---------------- tensor-core flash attention ----------------------------------
#define ROWB 144
#define AKV_OFF (2 * 128 * ROWB)
#define AKV_STAGE (4 * 64 * ROWB)
#define AMSK_OFF (AKV_OFF + 2 * AKV_STAGE)
#define ATTN_SMEM (AMSK_OFF + 512)

__device__ __forceinline__ void attn_load_kv(
    uint32_t smb, const __nv_bfloat16* qkv,
    const float* mask, int bh, int b, int kt, int st, int tid)
{
    size_t goff = ((size_t)bh * N_S + kt * 64) * D_HEAD;
    uint32_t base = smb + AKV_OFF + st * AKV_STAGE;
#pragma unroll
    for (int bf = 0; bf < 4; bf++) {
        const __nv_bfloat16* sp = qkv + (size_t)(2 + bf) * SZ + goff;
        uint32_t db = base + bf * (64 * ROWB);
#pragma unroll
        for (int rep = 0; rep < 2; rep++) {
            int idx = tid + rep * 256;
            int r = idx >> 3, cq = idx & 7;
            cp16(db + r * ROWB + cq * 16, sp + (size_t)r * D_HEAD + cq * 8);
        }
    }
    if (tid < 16)
        cp16(smb + AMSK_OFF + st * 256 + tid * 16, mask + (size_t)b * N_S + kt * 64 + tid * 4);
}

__global__ __launch_bounds__(256, 2) void attn_mma(
    const __nv_bfloat16* __restrict__ qkv, const float* __restrict__ mask,
    __nv_bfloat16* __restrict__ chi, __nv_bfloat16* __restrict__ clo)
{
    extern __shared__ char smraw[];
    const uint32_t smb = s2u(smraw);
    const int bh = blockIdx.x;
    const int qt = blockIdx.y;
    const int b = bh >> 4;
    const int h = bh & 15;
    const int tid = threadIdx.x;
    const int lane = tid & 31;
    const int wid = tid >> 5;
    const int wrow = wid * 16;

    {
        size_t qoff = ((size_t)bh * N_S + qt * 128) * D_HEAD;
#pragma unroll
        for (int buf = 0; buf < 2; buf++) {
            const __nv_bfloat16* sp = qkv + (size_t)buf * SZ + qoff;
            uint32_t db = smb + buf * (128 * ROWB);
#pragma unroll
            for (int rep = 0; rep < 4; rep++) {
                int idx = tid + rep * 256;
                int r = idx >> 3, cq = idx & 7;
                cp16(db + r * ROWB + cq * 16, sp + (size_t)r * D_HEAD + cq * 8);
            }
        }
        attn_load_kv(smb, qkv, mask, bh, b, 0, 0, tid);
        CP_COMMIT();
        attn_load_kv(smb, qkv, mask, bh, b, 1, 1, tid);
        CP_COMMIT();
    }

    float o[8][4];
#pragma unroll
    for (int ni = 0; ni < 8; ni++)
#pragma unroll
        for (int e = 0; e < 4; e++) o[ni][e] = 0.0f;
    float m_run[2] = {-3.0e38f, -3.0e38f};
    float l_run[2] = {0.0f, 0.0f};

    uint32_t qh[4][4], ql[4][4];
    const uint32_t a_row = lane & 15;
    const uint32_t a_coff = (lane >> 4) * 16;
    const uint32_t b_row = (lane & 7) + ((lane >> 4) << 3);
    const uint32_t b_coff = ((lane >> 3) & 1) * 16;
    const uint32_t v_row = (lane & 7) + ((lane >> 3) & 1) * 8;
    const uint32_t v_coff = (lane >> 4) * 16;
    const float scale = 0.125f;

    int st = 0;
    for (int kt = 0; kt < N_S / 64; kt++) {
        CP_WAIT1();
        __syncthreads();
        if (kt == 0) {
#pragma unroll
            for (int kk = 0; kk < 4; kk++) {
                uint32_t ad = smb + (wrow + a_row) * ROWB + kk * 32 + a_coff;
                LDM_X4(qh[kk][0], qh[kk][1], qh[kk][2], qh[kk][3], ad);
                LDM_X4(ql[kk][0], ql[kk][1], ql[kk][2], ql[kk][3], ad + 128 * ROWB);
            }
        }
        uint32_t kvb = smb + AKV_OFF + st * AKV_STAGE;

        float s[8][4];
#pragma unroll
        for (int ni = 0; ni < 8; ni++)
#pragma unroll
            for (int e = 0; e < 4; e++) s[ni][e] = 0.0f;

#pragma unroll
        for (int kk = 0; kk < 4; kk++) {
#pragma unroll
            for (int ni2 = 0; ni2 < 4; ni2++) {
                uint32_t ro = (ni2 * 16 + b_row) * ROWB + kk * 32 + b_coff;
                uint32_t kh[4], kl[4];
                LDM_X4(kh[0], kh[1], kh[2], kh[3], kvb + ro);
                LDM_X4(kl[0], kl[1], kl[2], kl[3], kvb + 64 * ROWB + ro);
                MMA_BF16(s[2 * ni2], qh[kk], kh);
                MMA_BF16(s[2 * ni2], qh[kk], kl);
                MMA_BF16(s[2 * ni2], ql[kk], kh);
                MMA_BF16(s[2 * ni2 + 1], qh[kk], kh + 2);
                MMA_BF16(s[2 * ni2 + 1], qh[kk], kl + 2);
                MMA_BF16(s[2 * ni2 + 1], ql[kk], kh + 2);
            }
        }

        // ---- online softmax; mask read per-use from smem (no persistent regs) ----
#pragma unroll
        for (int hf = 0; hf < 2; hf++) {
            float mx = -3.0e38f;
#pragma unroll
            for (int ni = 0; ni < 8; ni++) {
                float2 mvv = *(float2*)(smraw + AMSK_OFF + st * 256 +
                                        (ni * 8 + 2 * (lane & 3)) * 4);
                float v0 = s[ni][2 * hf] * scale + mvv.x;
                float v1 = s[ni][2 * hf + 1] * scale + mvv.y;
                s[ni][2 * hf] = v0; s[ni][2 * hf + 1] = v1;
                mx = fmaxf(mx, fmaxf(v0, v1));
            }
            mx = fmaxf(mx, __shfl_xor_sync(0xffffffffu, mx, 1));
            mx = fmaxf(mx, __shfl_xor_sync(0xffffffffu, mx, 2));
            float mnew = fmaxf(m_run[hf], mx);
            float alpha = __expf(m_run[hf] - mnew);
            float sum = 0.0f;
#pragma unroll
            for (int ni = 0; ni < 8; ni++) {
                float p0 = __expf(s[ni][2 * hf] - mnew);
                float p1 = __expf(s[ni][2 * hf + 1] - mnew);
                s[ni][2 * hf] = p0; s[ni][2 * hf + 1] = p1;
                sum += p0 + p1;
            }
            sum += __shfl_xor_sync(0xffffffffu, sum, 1);
            sum += __shfl_xor_sync(0xffffffffu, sum, 2);
            l_run[hf] = l_run[hf] * alpha + sum;
            m_run[hf] = mnew;
#pragma unroll
            for (int ni = 0; ni < 8; ni++) {
                o[ni][2 * hf] *= alpha;
                o[ni][2 * hf + 1] *= alpha;
            }
        }

        // ---- O += P V : 2-term (pah·vh + pah·vl); pal term dropped (~2^-9) ----
        uint32_t vbb = kvb + 2 * 64 * ROWB;
#pragma unroll
        for (int kk = 0; kk < 4; kk++) {
            uint32_t pah[4];
            pah[0] = pk2(s[2 * kk][0], s[2 * kk][1]);
            pah[1] = pk2(s[2 * kk][2], s[2 * kk][3]);
            pah[2] = pk2(s[2 * kk + 1][0], s[2 * kk + 1][1]);
            pah[3] = pk2(s[2 * kk + 1][2], s[2 * kk + 1][3]);
#pragma unroll
            for (int ni2 = 0; ni2 < 4; ni2++) {
                uint32_t ro = (kk * 16 + v_row) * ROWB + ni2 * 32 + v_coff;
                uint32_t vh[4], vl[4];
                LDM_X4_T(vh[0], vh[1], vh[2], vh[3], vbb + ro);
                LDM_X4_T(vl[0], vl[1], vl[2], vl[3], vbb + 64 * ROWB + ro);
                MMA_BF16(o[2 * ni2], pah, vh);
                MMA_BF16(o[2 * ni2], pah, vl);
                MMA_BF16(o[2 * ni2 + 1], pah, vh + 2);
                MMA_BF16(o[2 * ni2 + 1], pah, vl + 2);
            }
        }

        __syncthreads();
        if (kt + 2 < N_S / 64)
            attn_load_kv(smb, qkv, mask, bh, b, kt + 2, st, tid);
        CP_COMMIT();
        st ^= 1;
    }

#pragma unroll
    for (int hf = 0; hf < 2; hf++) {
        float inv = 1.0f / l_run[hf];
        int row = qt * 128 + wrow + (lane >> 2) + hf * 8;
        size_t mrow = ((size_t)(b * N_S + row)) * D_EMBED + h * D_HEAD;
#pragma unroll
        for (int ni = 0; ni < 8; ni++) {
            int d = ni * 8 + 2 * (lane & 3);
            float a = o[ni][2 * hf] * inv;
            float bb2 = o[ni][2 * hf + 1] * inv;
            uint32_t h2 = pk2(a, bb2);
            uint32_t l2 = pk2lo(a, bb2, h2);
            *(uint32_t*)(chi + mrow + d) = h2;
            *(uint32_t*)(clo + mrow + d) = l2;
        }
    }
}

// ---------------- LayerNorm ----------------------------------------------------
__global__ __launch_bounds__(256) void ln_kernel(
    const float* __restrict__ X, const float* __restrict__ g,
    const float* __restrict__ be, float* __restrict__ out)
{
    __shared__ float red[8];
    const int row = blockIdx.x;
    const int tid = threadIdx.x;
    const float* xr = X + (size_t)row * D_EMBED;
    float4 v = *(const float4*)(xr + tid * 4);
    float s = (v.x + v.y) + (v.z + v.w);
#pragma unroll
    for (int o = 16; o >= 1; o >>= 1) s += __shfl_xor_sync(0xffffffffu, s, o);
    if ((tid & 31) == 0) red[tid >> 5] = s;
    __syncthreads();
    float tot = red[0] + red[1] + red[2] + red[3] +
                red[4] + red[5] + red[6] + red[7];
    float mu = tot * (1.0f / D_EMBED);
    float d0 = v.x - mu, d1 = v.y - mu, d2 = v.z - mu, d3 = v.w - mu;
    float sq = d0 * d0 + d1 * d1 + d2 * d2 + d3 * d3;
#pragma unroll
    for (int o = 16; o >= 1; o >>= 1) sq += __shfl_xor_sync(0xffffffffu, sq, o);
    __syncthreads();
    if ((tid & 31) == 0) red[tid >> 5] = sq;
    __syncthreads();
    float var = (red[0] + red[1] + red[2] + red[3] +
                 red[4] + red[5] + red[6] + red[7]) * (1.0f / D_EMBED);
    float r = rsqrtf(var + 1e-12f);
    float4 gv = *(const float4*)(g + tid * 4);
    float4 bv = *(const float4*)(be + tid * 4);
    float4 o;
    o.x = d0 * r * gv.x + bv.x;
    o.y = d1 * r * gv.y + bv.y;
    o.z = d2 * r * gv.z + bv.z;
    o.w = d3 * r * gv.w + bv.w;
    *(float4*)(out + (size_t)row * D_EMBED + tid * 4) = o;
}

// ---------------- launch --------------------------------------------------------
extern "C" void kernel_launch(void* const* d_in, const int* in_sizes, int n_in,
                              void* d_out, int out_size)
{
    const float* X     = (const float*)d_in[0];
    const float* mask  = (const float*)d_in[1];
    const float* Wq    = (const float*)d_in[2];
    const float* bq    = (const float*)d_in[3];
    const float* Wk    = (const float*)d_in[4];
    const float* bk    = (const float*)d_in[5];
    const float* Wv    = (const float*)d_in[6];
    const float* bv    = (const float*)d_in[7];
    const float* Wo    = (const float*)d_in[8];
    const float* bo    = (const float*)d_in[9];
    const float* gamma = (const float*)d_in[10];
    const float* beta  = (const float*)d_in[11];
    float* out = (float*)d_out;

    float *x;
    __nv_bfloat16 *xhi, *xlo, *chi, *clo, *whi, *wlo, *qkv;
    cudaGetSymbolAddress((void**)&x, g_x);
    cudaGetSymbolAddress((void**)&xhi, g_xhi);
    cudaGetSymbolAddress((void**)&xlo, g_xlo);
    cudaGetSymbolAddress((void**)&chi, g_chi);
    cudaGetSymbolAddress((void**)&clo, g_clo);
    cudaGetSymbolAddress((void**)&whi, g_whi);
    cudaGetSymbolAddress((void**)&wlo, g_wlo);
    cudaGetSymbolAddress((void**)&qkv, g_qkv);

    cudaFuncSetAttribute(attn_mma, cudaFuncAttributeMaxDynamicSharedMemorySize,
                         ATTN_SMEM);
    cudaFuncSetAttribute(gemm_qkv, cudaFuncAttributeMaxDynamicSharedMemorySize,
                         GEMM_SMEM);
    cudaFuncSetAttribute(gemm_oproj, cudaFuncAttributeMaxDynamicSharedMemorySize,
                         GEMM_SMEM);

    const size_t WSZ = (size_t)D_EMBED * D_EMBED;
    split_bf16<<<(N_M * D_EMBED / 4 + 255) / 256, 256>>>(X, xhi, xlo, N_M * D_EMBED / 4);
    split_w4<<<dim3(WSZ / 4 / 256, 4), 256>>>(Wq, Wk, Wv, Wo, whi, wlo);

    gemm_qkv<<<dim3(D_EMBED / 128, N_M / 128, 3), 256, GEMM_SMEM>>>(
        xhi, xlo, whi, wlo, bq, bk, bv, qkv);
    attn_mma<<<dim3(N_B * N_HEADS, N_S / 128), 256, ATTN_SMEM>>>(
        qkv, mask, chi, clo);
    gemm_oproj<<<dim3(D_EMBED / 128, N_M / 128), 256, GEMM_SMEM>>>(
        chi, clo, whi + 3 * WSZ, wlo + 3 * WSZ, bo, X, x);
    ln_kernel<<<N_M, 256>>>(x, gamma, beta, out);
}

// round 8
// speedup vs baseline: 3.0066x; 1.0581x over previous
#include <cuda_runtime.h>
#include <cuda_bf16.h>
#include <cstdint>
#include <math.h>

#define D_EMBED 1024
#define N_HEADS 16
#define D_HEAD  64
#define N_B     2
#define N_S     2048
#define N_M     (N_B * N_S)   // 4096 rows
#define SZ      ((size_t)N_B * N_HEADS * N_S * D_HEAD)   // 4M elems per buffer

// ---------------- scratch -----------------------------------------------------
__device__ __align__(16) float g_x[(size_t)N_M * D_EMBED];
__device__ __align__(16) __nv_bfloat16 g_xhi[(size_t)N_M * D_EMBED];
__device__ __align__(16) __nv_bfloat16 g_xlo[(size_t)N_M * D_EMBED];
__device__ __align__(16) __nv_bfloat16 g_chi[(size_t)N_M * D_EMBED];
__device__ __align__(16) __nv_bfloat16 g_clo[(size_t)N_M * D_EMBED];
__device__ __align__(16) __nv_bfloat16 g_whi[4 * D_EMBED * D_EMBED];
__device__ __align__(16) __nv_bfloat16 g_wlo[4 * D_EMBED * D_EMBED];
// [qhi | qlo | khi | klo | vhi | vlo], each SZ elements
__device__ __align__(16) __nv_bfloat16 g_qkv[6 * SZ];

// ---------------- helpers -----------------------------------------------------
__device__ __forceinline__ uint32_t s2u(const void* p) {
    uint32_t a;
    asm("{ .reg .u64 t; cvta.to.shared.u64 t, %1; cvt.u32.u64 %0, t; }"
        : "=r"(a) : "l"(p));
    return a;
}
__device__ __forceinline__ void cp16(uint32_t dst, const void* src) {
    asm volatile("cp.async.cg.shared.global [%0], [%1], 16;"
                 :: "r"(dst), "l"(src) : "memory");
}
#define CP_COMMIT() asm volatile("cp.async.commit_group;" ::: "memory")
#define CP_WAIT1()  asm volatile("cp.async.wait_group 1;" ::: "memory")

#define LDM_X4(r0, r1, r2, r3, addr) \
    asm volatile("ldmatrix.sync.aligned.m8n8.x4.shared.b16 {%0,%1,%2,%3}, [%4];" \
                 : "=r"(r0), "=r"(r1), "=r"(r2), "=r"(r3) : "r"(addr))
#define LDM_X4_T(r0, r1, r2, r3, addr) \
    asm volatile("ldmatrix.sync.aligned.m8n8.x4.trans.shared.b16 {%0,%1,%2,%3}, [%4];" \
                 : "=r"(r0), "=r"(r1), "=r"(r2), "=r"(r3) : "r"(addr))

#define MMA_BF16(c, a, b) \
    asm volatile( \
        "mma.sync.aligned.m16n8k16.row.col.f32.bf16.bf16.f32 " \
        "{%0,%1,%2,%3}, {%4,%5,%6,%7}, {%8,%9}, {%0,%1,%2,%3};" \
        : "+f"((c)[0]), "+f"((c)[1]), "+f"((c)[2]), "+f"((c)[3]) \
        : "r"((a)[0]), "r"((a)[1]), "r"((a)[2]), "r"((a)[3]), \
          "r"((b)[0]), "r"((b)[1]))

__device__ __forceinline__ uint32_t pk2(float a, float b) {
    __nv_bfloat162 t;
    t.x = __float2bfloat16(a);
    t.y = __float2bfloat16(b);
    return *(uint32_t*)&t;
}
__device__ __forceinline__ uint32_t pk2lo(float a, float b, uint32_t hi) {
    __nv_bfloat162 t = *(__nv_bfloat162*)&hi;
    return pk2(a - __bfloat162float(t.x), b - __bfloat162float(t.y));
}

// ---------------- splits --------------------------------------------------------
__global__ __launch_bounds__(256) void split_bf16(
    const float* __restrict__ src, __nv_bfloat16* __restrict__ hi,
    __nv_bfloat16* __restrict__ lo, int n4)
{
    int i = blockIdx.x * blockDim.x + threadIdx.x;
    if (i >= n4) return;
    float4 v = ((const float4*)src)[i];
    uint32_t h0 = pk2(v.x, v.y), h1 = pk2(v.z, v.w);
    uint32_t l0 = pk2lo(v.x, v.y, h0), l1 = pk2lo(v.z, v.w, h1);
    ((uint32_t*)hi)[2 * i + 0] = h0;
    ((uint32_t*)hi)[2 * i + 1] = h1;
    ((uint32_t*)lo)[2 * i + 0] = l0;
    ((uint32_t*)lo)[2 * i + 1] = l1;
}

__global__ __launch_bounds__(256) void split_w4(
    const float* __restrict__ w0, const float* __restrict__ w1,
    const float* __restrict__ w2, const float* __restrict__ w3,
    __nv_bfloat16* __restrict__ hi, __nv_bfloat16* __restrict__ lo)
{
    const int z = blockIdx.y;
    const float* src = (z == 0) ? w0 : (z == 1) ? w1 : (z == 2) ? w2 : w3;
    size_t off = (size_t)z * D_EMBED * D_EMBED;
    int i = blockIdx.x * blockDim.x + threadIdx.x;
    float4 v = ((const float4*)src)[i];
    uint32_t h0 = pk2(v.x, v.y), h1 = pk2(v.z, v.w);
    uint32_t l0 = pk2lo(v.x, v.y, h0), l1 = pk2lo(v.z, v.w, h1);
    ((uint32_t*)(hi + off))[2 * i + 0] = h0;
    ((uint32_t*)(hi + off))[2 * i + 1] = h1;
    ((uint32_t*)(lo + off))[2 * i + 0] = l0;
    ((uint32_t*)(lo + off))[2 * i + 1] = l1;
}

// ---------------- bf16-split tensor GEMM core ------------------------------------
#define BUF_B  (128 * 80)
#define STAGE_B (4 * BUF_B)
#define GSTAGES 2
#define GEMM_SMEM (GSTAGES * STAGE_B)   // 81920

__device__ __forceinline__ void load_stage(
    uint32_t st, const __nv_bfloat16* Ahi, const __nv_bfloat16* Alo,
    const __nv_bfloat16* Bhi, const __nv_bfloat16* Blo,
    int bm, int bn, int kb, int tid)
{
    const __nv_bfloat16* srcs[4] = {Ahi, Alo, Bhi, Blo};
    const int rowoff[4] = {bm, bm, bn, bn};
#pragma unroll
    for (int bf = 0; bf < 4; bf++) {
        const __nv_bfloat16* sb = srcs[bf] + (size_t)rowoff[bf] * D_EMBED + kb * 32;
        uint32_t db = st + bf * BUF_B;
#pragma unroll
        for (int i = 0; i < 2; i++) {
            int c = tid + i * 256;
            int row = c >> 2, kc = c & 3;
            cp16(db + row * 80 + kc * 16, sb + (size_t)row * D_EMBED + kc * 8);
        }
    }
}

__device__ __forceinline__ void gemm_core(
    const __nv_bfloat16* Ahi, const __nv_bfloat16* Alo,
    const __nv_bfloat16* Bhi, const __nv_bfloat16* Blo,
    const float* bias, const float* res, float* out,
    __nv_bfloat16* out_hi, int qkv, int bm, int bn)
{
    extern __shared__ char smraw[];
    const uint32_t smb = s2u(smraw);
    const int tid = threadIdx.x;
    const int lane = tid & 31;
    const int wid = tid >> 5;
    const int warp_m = (wid >> 2) * 64;
    const int warp_n = (wid & 3) * 32;

    float c[4][4][4];
#pragma unroll
    for (int mi = 0; mi < 4; mi++)
#pragma unroll
        for (int ni = 0; ni < 4; ni++)
#pragma unroll
            for (int e = 0; e < 4; e++) c[mi][ni][e] = 0.0f;

#pragma unroll
    for (int p = 0; p < GSTAGES; p++) {
        load_stage(smb + p * STAGE_B, Ahi, Alo, Bhi, Blo, bm, bn, p, tid);
        CP_COMMIT();
    }

    const uint32_t a_row = lane & 15;
    const uint32_t a_coff = (lane >> 4) * 16;
    const uint32_t b_row = (lane & 7) + ((lane >> 4) << 3);
    const uint32_t b_coff = ((lane >> 3) & 1) * 16;

    int s = 0;
    for (int kb = 0; kb < D_EMBED / 32; kb++) {
        CP_WAIT1();
        __syncthreads();
        uint32_t st = smb + s * STAGE_B;
        uint32_t ah_b = st, al_b = st + BUF_B;
        uint32_t bh_b = st + 2 * BUF_B, bl_b = st + 3 * BUF_B;

#pragma unroll
        for (int k16 = 0; k16 < 2; k16++) {
            uint32_t akoff = k16 * 32 + a_coff;
            uint32_t bkoff = k16 * 32 + b_coff;
            uint32_t ah[4][4], al[4][4], bh[4][2], bl[4][2];
#pragma unroll
            for (int mi = 0; mi < 4; mi++) {
                uint32_t ro = (warp_m + mi * 16 + a_row) * 80 + akoff;
                LDM_X4(ah[mi][0], ah[mi][1], ah[mi][2], ah[mi][3], ah_b + ro);
                LDM_X4(al[mi][0], al[mi][1], al[mi][2], al[mi][3], al_b + ro);
            }
#pragma unroll
            for (int ni2 = 0; ni2 < 2; ni2++) {
                uint32_t ro = (warp_n + ni2 * 16 + b_row) * 80 + bkoff;
                LDM_X4(bh[ni2 * 2][0], bh[ni2 * 2][1],
                       bh[ni2 * 2 + 1][0], bh[ni2 * 2 + 1][1], bh_b + ro);
                LDM_X4(bl[ni2 * 2][0], bl[ni2 * 2][1],
                       bl[ni2 * 2 + 1][0], bl[ni2 * 2 + 1][1], bl_b + ro);
            }
#pragma unroll
            for (int mi = 0; mi < 4; mi++)
#pragma unroll
                for (int ni = 0; ni < 4; ni++) {
                    MMA_BF16(c[mi][ni], ah[mi], bh[ni]);
                    MMA_BF16(c[mi][ni], ah[mi], bl[ni]);
                    MMA_BF16(c[mi][ni], al[mi], bh[ni]);
                }
        }
        __syncthreads();
        if (kb + GSTAGES < D_EMBED / 32)
            load_stage(st, Ahi, Alo, Bhi, Blo, bm, bn, kb + GSTAGES, tid);
        CP_COMMIT();
        s ^= 1;
    }

#pragma unroll
    for (int mi = 0; mi < 4; mi++) {
#pragma unroll
        for (int half = 0; half < 2; half++) {
            int m = bm + warp_m + mi * 16 + (lane >> 2) + half * 8;
            int bb = m >> 11, sdx = m & (N_S - 1);
#pragma unroll
            for (int ni = 0; ni < 4; ni++) {
                int n = bn + warp_n + ni * 8 + 2 * (lane & 3);
                float2 o;
                o.x = c[mi][ni][half * 2 + 0] + bias[n];
                o.y = c[mi][ni][half * 2 + 1] + bias[n + 1];
                if (res) {
                    float2 rv = *(const float2*)(res + (size_t)m * D_EMBED + n);
                    o.x += rv.x; o.y += rv.y;
                }
                if (qkv) {
                    int h = n >> 6, d = n & 63;
                    size_t off = (((size_t)(bb * N_HEADS + h)) * N_S + sdx) * D_HEAD + d;
                    uint32_t h2 = pk2(o.x, o.y);
                    uint32_t l2 = pk2lo(o.x, o.y, h2);
                    *(uint32_t*)(out_hi + off) = h2;
                    *(uint32_t*)(out_hi + SZ + off) = l2;
                } else {
                    *(float2*)(out + (size_t)m * D_EMBED + n) = o;
                }
            }
        }
    }
}

// merged QKV: grid (8, 32, 3); z selects weight/bias/output pair
__global__ __launch_bounds__(256, 2) void gemm_qkv(
    const __nv_bfloat16* __restrict__ Ahi, const __nv_bfloat16* __restrict__ Alo,
    const __nv_bfloat16* __restrict__ whi, const __nv_bfloat16* __restrict__ wlo,
    const float* __restrict__ bq, const float* __restrict__ bk,
    const float* __restrict__ bv, __nv_bfloat16* __restrict__ qkv)
{
    const int z = blockIdx.z;
    const size_t WSZ = (size_t)D_EMBED * D_EMBED;
    const float* bias = (z == 0) ? bq : (z == 1) ? bk : bv;
    gemm_core(Ahi, Alo, whi + z * WSZ, wlo + z * WSZ, bias, nullptr,
              nullptr, qkv + (size_t)(2 * z) * SZ, 1,
              blockIdx.y * 128, blockIdx.x * 128);
}

__global__ __launch_bounds__(256, 2) void gemm_oproj(
    const __nv_bfloat16* __restrict__ Ahi, const __nv_bfloat16* __restrict__ Alo,
    const __nv_bfloat16* __restrict__ Bhi, const __nv_bfloat16* __restrict__ Blo,
    const float* __restrict__ bias, const float* __restrict__ res,
    float* __restrict__ out)
{
    gemm_core(Ahi, Alo, Bhi, Blo, bias, res, out, nullptr, 0,
              blockIdx.y * 128, blockIdx.x * 128);
}

// ---------------- tensor-core flash attention ----------------------------------
// Q kept as bf16-hi only in smem (Q-lo term dropped; ~2^-9-scale correction,
// calibrated cost ~5e-5 rel_err per R7 measurement of the symmetric PV drop).
#define ROWB 144
#define AKV_OFF (128 * ROWB)                 // 18432 (Q hi only)
#define AKV_STAGE (4 * 64 * ROWB)            // 36864
#define AMSK_OFF (AKV_OFF + 2 * AKV_STAGE)   // 92160
#define ATTN_SMEM (AMSK_OFF + 512)           // 92672

__device__ __forceinline__ void attn_load_kv(
    uint32_t smb, const __nv_bfloat16* qkv,
    const float* mask, int bh, int b, int kt, int st, int tid)
{
    size_t goff = ((size_t)bh * N_S + kt * 64) * D_HEAD;
    uint32_t base = smb + AKV_OFF + st * AKV_STAGE;
#pragma unroll
    for (int bf = 0; bf < 4; bf++) {
        const __nv_bfloat16* sp = qkv + (size_t)(2 + bf) * SZ + goff;
        uint32_t db = base + bf * (64 * ROWB);
#pragma unroll
        for (int rep = 0; rep < 2; rep++) {
            int idx = tid + rep * 256;
            int r = idx >> 3, cq = idx & 7;
            cp16(db + r * ROWB + cq * 16, sp + (size_t)r * D_HEAD + cq * 8);
        }
    }
    if (tid < 16)
        cp16(smb + AMSK_OFF + st * 256 + tid * 16, mask + (size_t)b * N_S + kt * 64 + tid * 4);
}

__global__ __launch_bounds__(256, 2) void attn_mma(
    const __nv_bfloat16* __restrict__ qkv, const float* __restrict__ mask,
    __nv_bfloat16* __restrict__ chi, __nv_bfloat16* __restrict__ clo)
{
    extern __shared__ char smraw[];
    const uint32_t smb = s2u(smraw);
    const int bh = blockIdx.x;
    const int qt = blockIdx.y;
    const int b = bh >> 4;
    const int h = bh & 15;
    const int tid = threadIdx.x;
    const int lane = tid & 31;
    const int wid = tid >> 5;
    const int wrow = wid * 16;

    {
        size_t qoff = ((size_t)bh * N_S + qt * 128) * D_HEAD;
        const __nv_bfloat16* sp = qkv + qoff;    // q-hi only
#pragma unroll
        for (int rep = 0; rep < 4; rep++) {
            int idx = tid + rep * 256;
            int r = idx >> 3, cq = idx & 7;
            cp16(smb + r * ROWB + cq * 16, sp + (size_t)r * D_HEAD + cq * 8);
        }
        attn_load_kv(smb, qkv, mask, bh, b, 0, 0, tid);
        CP_COMMIT();
        attn_load_kv(smb, qkv, mask, bh, b, 1, 1, tid);
        CP_COMMIT();
    }

    float o[8][4];
#pragma unroll
    for (int ni = 0; ni < 8; ni++)
#pragma unroll
        for (int e = 0; e < 4; e++) o[ni][e] = 0.0f;
    float m_run[2] = {-3.0e38f, -3.0e38f};
    float l_run[2] = {0.0f, 0.0f};

    uint32_t qh[4][4];
    const uint32_t a_row = lane & 15;
    const uint32_t a_coff = (lane >> 4) * 16;
    const uint32_t b_row = (lane & 7) + ((lane >> 4) << 3);
    const uint32_t b_coff = ((lane >> 3) & 1) * 16;
    const uint32_t v_row = (lane & 7) + ((lane >> 3) & 1) * 8;
    const uint32_t v_coff = (lane >> 4) * 16;
    const float scale = 0.125f;

    int st = 0;
    for (int kt = 0; kt < N_S / 64; kt++) {
        CP_WAIT1();
        __syncthreads();
        if (kt == 0) {
#pragma unroll
            for (int kk = 0; kk < 4; kk++) {
                uint32_t ad = smb + (wrow + a_row) * ROWB + kk * 32 + a_coff;
                LDM_X4(qh[kk][0], qh[kk][1], qh[kk][2], qh[kk][3], ad);
            }
        }
        uint32_t kvb = smb + AKV_OFF + st * AKV_STAGE;

        // ---- S = Q K^T : 2-term (qh·kh + qh·kl) ----
        float s[8][4];
#pragma unroll
        for (int ni = 0; ni < 8; ni++)
#pragma unroll
            for (int e = 0; e < 4; e++) s[ni][e] = 0.0f;

#pragma unroll
        for (int kk = 0; kk < 4; kk++) {
#pragma unroll
            for (int ni2 = 0; ni2 < 4; ni2++) {
                uint32_t ro = (ni2 * 16 + b_row) * ROWB + kk * 32 + b_coff;
                uint32_t kh[4], kl[4];
                LDM_X4(kh[0], kh[1], kh[2], kh[3], kvb + ro);
                LDM_X4(kl[0], kl[1], kl[2], kl[3], kvb + 64 * ROWB + ro);
                MMA_BF16(s[2 * ni2], qh[kk], kh);
                MMA_BF16(s[2 * ni2], qh[kk], kl);
                MMA_BF16(s[2 * ni2 + 1], qh[kk], kh + 2);
                MMA_BF16(s[2 * ni2 + 1], qh[kk], kl + 2);
            }
        }

        // ---- online softmax; mask read per-use from smem ----
#pragma unroll
        for (int hf = 0; hf < 2; hf++) {
            float mx = -3.0e38f;
#pragma unroll
            for (int ni = 0; ni < 8; ni++) {
                float2 mvv = *(float2*)(smraw + AMSK_OFF + st * 256 +
                                        (ni * 8 + 2 * (lane & 3)) * 4);
                float v0 = s[ni][2 * hf] * scale + mvv.x;
                float v1 = s[ni][2 * hf + 1] * scale + mvv.y;
                s[ni][2 * hf] = v0; s[ni][2 * hf + 1] = v1;
                mx = fmaxf(mx, fmaxf(v0, v1));
            }
            mx = fmaxf(mx, __shfl_xor_sync(0xffffffffu, mx, 1));
            mx = fmaxf(mx, __shfl_xor_sync(0xffffffffu, mx, 2));
            float mnew = fmaxf(m_run[hf], mx);
            float alpha = __expf(m_run[hf] - mnew);
            float sum = 0.0f;
#pragma unroll
            for (int ni = 0; ni < 8; ni++) {
                float p0 = __expf(s[ni][2 * hf] - mnew);
                float p1 = __expf(s[ni][2 * hf + 1] - mnew);
                s[ni][2 * hf] = p0; s[ni][2 * hf + 1] = p1;
                sum += p0 + p1;
            }
            sum += __shfl_xor_sync(0xffffffffu, sum, 1);
            sum += __shfl_xor_sync(0xffffffffu, sum, 2);
            l_run[hf] = l_run[hf] * alpha + sum;
            m_run[hf] = mnew;
#pragma unroll
            for (int ni = 0; ni < 8; ni++) {
                o[ni][2 * hf] *= alpha;
                o[ni][2 * hf + 1] *= alpha;
            }
        }

        // ---- O += P V : 2-term (pah·vh + pah·vl) ----
        uint32_t vbb = kvb + 2 * 64 * ROWB;
#pragma unroll
        for (int kk = 0; kk < 4; kk++) {
            uint32_t pah[4];
            pah[0] = pk2(s[2 * kk][0], s[2 * kk][1]);
            pah[1] = pk2(s[2 * kk][2], s[2 * kk][3]);
            pah[2] = pk2(s[2 * kk + 1][0], s[2 * kk + 1][1]);
            pah[3] = pk2(s[2 * kk + 1][2], s[2 * kk + 1][3]);
#pragma unroll
            for (int ni2 = 0; ni2 < 4; ni2++) {
                uint32_t ro = (kk * 16 + v_row) * ROWB + ni2 * 32 + v_coff;
                uint32_t vh[4], vl[4];
                LDM_X4_T(vh[0], vh[1], vh[2], vh[3], vbb + ro);
                LDM_X4_T(vl[0], vl[1], vl[2], vl[3], vbb + 64 * ROWB + ro);
                MMA_BF16(o[2 * ni2], pah, vh);
                MMA_BF16(o[2 * ni2], pah, vl);
                MMA_BF16(o[2 * ni2 + 1], pah, vh + 2);
                MMA_BF16(o[2 * ni2 + 1], pah, vl + 2);
            }
        }

        __syncthreads();
        if (kt + 2 < N_S / 64)
            attn_load_kv(smb, qkv, mask, bh, b, kt + 2, st, tid);
        CP_COMMIT();
        st ^= 1;
    }

#pragma unroll
    for (int hf = 0; hf < 2; hf++) {
        float inv = 1.0f / l_run[hf];
        int row = qt * 128 + wrow + (lane >> 2) + hf * 8;
        size_t mrow = ((size_t)(b * N_S + row)) * D_EMBED + h * D_HEAD;
#pragma unroll
        for (int ni = 0; ni < 8; ni++) {
            int d = ni * 8 + 2 * (lane & 3);
            float a = o[ni][2 * hf] * inv;
            float bb2 = o[ni][2 * hf + 1] * inv;
            uint32_t h2 = pk2(a, bb2);
            uint32_t l2 = pk2lo(a, bb2, h2);
            *(uint32_t*)(chi + mrow + d) = h2;
            *(uint32_t*)(clo + mrow + d) = l2;
        }
    }
}

// ---------------- LayerNorm ----------------------------------------------------
__global__ __launch_bounds__(256) void ln_kernel(
    const float* __restrict__ X, const float* __restrict__ g,
    const float* __restrict__ be, float* __restrict__ out)
{
    __shared__ float red[8];
    const int row = blockIdx.x;
    const int tid = threadIdx.x;
    const float* xr = X + (size_t)row * D_EMBED;
    float4 v = *(const float4*)(xr + tid * 4);
    float s = (v.x + v.y) + (v.z + v.w);
#pragma unroll
    for (int o = 16; o >= 1; o >>= 1) s += __shfl_xor_sync(0xffffffffu, s, o);
    if ((tid & 31) == 0) red[tid >> 5] = s;
    __syncthreads();
    float tot = red[0] + red[1] + red[2] + red[3] +
                red[4] + red[5] + red[6] + red[7];
    float mu = tot * (1.0f / D_EMBED);
    float d0 = v.x - mu, d1 = v.y - mu, d2 = v.z - mu, d3 = v.w - mu;
    float sq = d0 * d0 + d1 * d1 + d2 * d2 + d3 * d3;
#pragma unroll
    for (int o = 16; o >= 1; o >>= 1) sq += __shfl_xor_sync(0xffffffffu, sq, o);
    __syncthreads();
    if ((tid & 31) == 0) red[tid >> 5] = sq;
    __syncthreads();
    float var = (red[0] + red[1] + red[2] + red[3] +
                 red[4] + red[5] + red[6] + red[7]) * (1.0f / D_EMBED);
    float r = rsqrtf(var + 1e-12f);
    float4 gv = *(const float4*)(g + tid * 4);
    float4 bv = *(const float4*)(be + tid * 4);
    float4 o;
    o.x = d0 * r * gv.x + bv.x;
    o.y = d1 * r * gv.y + bv.y;
    o.z = d2 * r * gv.z + bv.z;
    o.w = d3 * r * gv.w + bv.w;
    *(float4*)(out + (size_t)row * D_EMBED + tid * 4) = o;
}

// ---------------- launch --------------------------------------------------------
extern "C" void kernel_launch(void* const* d_in, const int* in_sizes, int n_in,
                              void* d_out, int out_size)
{
    const float* X     = (const float*)d_in[0];
    const float* mask  = (const float*)d_in[1];
    const float* Wq    = (const float*)d_in[2];
    const float* bq    = (const float*)d_in[3];
    const float* Wk    = (const float*)d_in[4];
    const float* bk    = (const float*)d_in[5];
    const float* Wv    = (const float*)d_in[6];
    const float* bv    = (const float*)d_in[7];
    const float* Wo    = (const float*)d_in[8];
    const float* bo    = (const float*)d_in[9];
    const float* gamma = (const float*)d_in[10];
    const float* beta  = (const float*)d_in[11];
    float* out = (float*)d_out;

    float *x;
    __nv_bfloat16 *xhi, *xlo, *chi, *clo, *whi, *wlo, *qkv;
    cudaGetSymbolAddress((void**)&x, g_x);
    cudaGetSymbolAddress((void**)&xhi, g_xhi);
    cudaGetSymbolAddress((void**)&xlo, g_xlo);
    cudaGetSymbolAddress((void**)&chi, g_chi);
    cudaGetSymbolAddress((void**)&clo, g_clo);
    cudaGetSymbolAddress((void**)&whi, g_whi);
    cudaGetSymbolAddress((void**)&wlo, g_wlo);
    cudaGetSymbolAddress((void**)&qkv, g_qkv);

    cudaFuncSetAttribute(attn_mma, cudaFuncAttributeMaxDynamicSharedMemorySize,
                         ATTN_SMEM);
    cudaFuncSetAttribute(gemm_qkv, cudaFuncAttributeMaxDynamicSharedMemorySize,
                         GEMM_SMEM);
    cudaFuncSetAttribute(gemm_oproj, cudaFuncAttributeMaxDynamicSharedMemorySize,
                         GEMM_SMEM);

    const size_t WSZ = (size_t)D_EMBED * D_EMBED;
    split_bf16<<<(N_M * D_EMBED / 4 + 255) / 256, 256>>>(X, xhi, xlo, N_M * D_EMBED / 4);
    split_w4<<<dim3(WSZ / 4 / 256, 4), 256>>>(Wq, Wk, Wv, Wo, whi, wlo);

    gemm_qkv<<<dim3(D_EMBED / 128, N_M / 128, 3), 256, GEMM_SMEM>>>(
        xhi, xlo, whi, wlo, bq, bk, bv, qkv);
    attn_mma<<<dim3(N_B * N_HEADS, N_S / 128), 256, ATTN_SMEM>>>(
        qkv, mask, chi, clo);
    gemm_oproj<<<dim3(D_EMBED / 128, N_M / 128), 256, GEMM_SMEM>>>(
        chi, clo, whi + 3 * WSZ, wlo + 3 * WSZ, bo, X, x);
    ln_kernel<<<N_M, 256>>>(x, gamma, beta, out);
}

// round 9
// speedup vs baseline: 3.5799x; 1.1907x over previous
#include <cuda_runtime.h>
#include <cuda_bf16.h>
#include <cstdint>
#include <math.h>

#define D_EMBED 1024
#define N_HEADS 16
#define D_HEAD  64
#define N_B     2
#define N_S     2048
#define N_M     (N_B * N_S)   // 4096 rows
#define SZ      ((size_t)N_B * N_HEADS * N_S * D_HEAD)   // 4M elems per buffer

// ---------------- scratch -----------------------------------------------------
__device__ __align__(16) float g_x[(size_t)N_M * D_EMBED];
__device__ __align__(16) __nv_bfloat16 g_xhi[(size_t)N_M * D_EMBED];
__device__ __align__(16) __nv_bfloat16 g_xlo[(size_t)N_M * D_EMBED];
__device__ __align__(16) __nv_bfloat16 g_chi[(size_t)N_M * D_EMBED];
__device__ __align__(16) __nv_bfloat16 g_clo[(size_t)N_M * D_EMBED];
__device__ __align__(16) __nv_bfloat16 g_whi[4 * D_EMBED * D_EMBED];
__device__ __align__(16) __nv_bfloat16 g_wlo[4 * D_EMBED * D_EMBED];
// [qhi | khi | vhi], each SZ elements (attention is bf16-hi only)
__device__ __align__(16) __nv_bfloat16 g_qkv[3 * SZ];

// ---------------- helpers -----------------------------------------------------
__device__ __forceinline__ uint32_t s2u(const void* p) {
    uint32_t a;
    asm("{ .reg .u64 t; cvta.to.shared.u64 t, %1; cvt.u32.u64 %0, t; }"
        : "=r"(a) : "l"(p));
    return a;
}
__device__ __forceinline__ void cp16(uint32_t dst, const void* src) {
    asm volatile("cp.async.cg.shared.global [%0], [%1], 16;"
                 :: "r"(dst), "l"(src) : "memory");
}
#define CP_COMMIT() asm volatile("cp.async.commit_group;" ::: "memory")
#define CP_WAIT1()  asm volatile("cp.async.wait_group 1;" ::: "memory")

#define LDM_X4(r0, r1, r2, r3, addr) \
    asm volatile("ldmatrix.sync.aligned.m8n8.x4.shared.b16 {%0,%1,%2,%3}, [%4];" \
                 : "=r"(r0), "=r"(r1), "=r"(r2), "=r"(r3) : "r"(addr))
#define LDM_X4_T(r0, r1, r2, r3, addr) \
    asm volatile("ldmatrix.sync.aligned.m8n8.x4.trans.shared.b16 {%0,%1,%2,%3}, [%4];" \
                 : "=r"(r0), "=r"(r1), "=r"(r2), "=r"(r3) : "r"(addr))

#define MMA_BF16(c, a, b) \
    asm volatile( \
        "mma.sync.aligned.m16n8k16.row.col.f32.bf16.bf16.f32 " \
        "{%0,%1,%2,%3}, {%4,%5,%6,%7}, {%8,%9}, {%0,%1,%2,%3};" \
        : "+f"((c)[0]), "+f"((c)[1]), "+f"((c)[2]), "+f"((c)[3]) \
        : "r"((a)[0]), "r"((a)[1]), "r"((a)[2]), "r"((a)[3]), \
          "r"((b)[0]), "r"((b)[1]))

__device__ __forceinline__ uint32_t pk2(float a, float b) {
    __nv_bfloat162 t;
    t.x = __float2bfloat16(a);
    t.y = __float2bfloat16(b);
    return *(uint32_t*)&t;
}
__device__ __forceinline__ uint32_t pk2lo(float a, float b, uint32_t hi) {
    __nv_bfloat162 t = *(__nv_bfloat162*)&hi;
    return pk2(a - __bfloat162float(t.x), b - __bfloat162float(t.y));
}

// ---------------- splits --------------------------------------------------------
__global__ __launch_bounds__(256) void split_bf16(
    const float* __restrict__ src, __nv_bfloat16* __restrict__ hi,
    __nv_bfloat16* __restrict__ lo, int n4)
{
    int i = blockIdx.x * blockDim.x + threadIdx.x;
    if (i >= n4) return;
    float4 v = ((const float4*)src)[i];
    uint32_t h0 = pk2(v.x, v.y), h1 = pk2(v.z, v.w);
    uint32_t l0 = pk2lo(v.x, v.y, h0), l1 = pk2lo(v.z, v.w, h1);
    ((uint32_t*)hi)[2 * i + 0] = h0;
    ((uint32_t*)hi)[2 * i + 1] = h1;
    ((uint32_t*)lo)[2 * i + 0] = l0;
    ((uint32_t*)lo)[2 * i + 1] = l1;
}

__global__ __launch_bounds__(256) void split_w4(
    const float* __restrict__ w0, const float* __restrict__ w1,
    const float* __restrict__ w2, const float* __restrict__ w3,
    __nv_bfloat16* __restrict__ hi, __nv_bfloat16* __restrict__ lo)
{
    const int z = blockIdx.y;
    const float* src = (z == 0) ? w0 : (z == 1) ? w1 : (z == 2) ? w2 : w3;
    size_t off = (size_t)z * D_EMBED * D_EMBED;
    int i = blockIdx.x * blockDim.x + threadIdx.x;
    float4 v = ((const float4*)src)[i];
    uint32_t h0 = pk2(v.x, v.y), h1 = pk2(v.z, v.w);
    uint32_t l0 = pk2lo(v.x, v.y, h0), l1 = pk2lo(v.z, v.w, h1);
    ((uint32_t*)(hi + off))[2 * i + 0] = h0;
    ((uint32_t*)(hi + off))[2 * i + 1] = h1;
    ((uint32_t*)(lo + off))[2 * i + 0] = l0;
    ((uint32_t*)(lo + off))[2 * i + 1] = l1;
}

// ---------------- bf16-split tensor GEMM core ------------------------------------
#define BUF_B  (128 * 80)
#define STAGE_B (4 * BUF_B)
#define GSTAGES 2
#define GEMM_SMEM (GSTAGES * STAGE_B)   // 81920

__device__ __forceinline__ void load_stage(
    uint32_t st, const __nv_bfloat16* Ahi, const __nv_bfloat16* Alo,
    const __nv_bfloat16* Bhi, const __nv_bfloat16* Blo,
    int bm, int bn, int kb, int tid)
{
    const __nv_bfloat16* srcs[4] = {Ahi, Alo, Bhi, Blo};
    const int rowoff[4] = {bm, bm, bn, bn};
#pragma unroll
    for (int bf = 0; bf < 4; bf++) {
        const __nv_bfloat16* sb = srcs[bf] + (size_t)rowoff[bf] * D_EMBED + kb * 32;
        uint32_t db = st + bf * BUF_B;
#pragma unroll
        for (int i = 0; i < 2; i++) {
            int c = tid + i * 256;
            int row = c >> 2, kc = c & 3;
            cp16(db + row * 80 + kc * 16, sb + (size_t)row * D_EMBED + kc * 8);
        }
    }
}

__device__ __forceinline__ void gemm_core(
    const __nv_bfloat16* Ahi, const __nv_bfloat16* Alo,
    const __nv_bfloat16* Bhi, const __nv_bfloat16* Blo,
    const float* bias, const float* res, float* out,
    __nv_bfloat16* out_hi, int qkv, int bm, int bn)
{
    extern __shared__ char smraw[];
    const uint32_t smb = s2u(smraw);
    const int tid = threadIdx.x;
    const int lane = tid & 31;
    const int wid = tid >> 5;
    const int warp_m = (wid >> 2) * 64;
    const int warp_n = (wid & 3) * 32;

    float c[4][4][4];
#pragma unroll
    for (int mi = 0; mi < 4; mi++)
#pragma unroll
        for (int ni = 0; ni < 4; ni++)
#pragma unroll
            for (int e = 0; e < 4; e++) c[mi][ni][e] = 0.0f;

#pragma unroll
    for (int p = 0; p < GSTAGES; p++) {
        load_stage(smb + p * STAGE_B, Ahi, Alo, Bhi, Blo, bm, bn, p, tid);
        CP_COMMIT();
    }

    const uint32_t a_row = lane & 15;
    const uint32_t a_coff = (lane >> 4) * 16;
    const uint32_t b_row = (lane & 7) + ((lane >> 4) << 3);
    const uint32_t b_coff = ((lane >> 3) & 1) * 16;

    int s = 0;
    for (int kb = 0; kb < D_EMBED / 32; kb++) {
        CP_WAIT1();
        __syncthreads();
        uint32_t st = smb + s * STAGE_B;
        uint32_t ah_b = st, al_b = st + BUF_B;
        uint32_t bh_b = st + 2 * BUF_B, bl_b = st + 3 * BUF_B;

#pragma unroll
        for (int k16 = 0; k16 < 2; k16++) {
            uint32_t akoff = k16 * 32 + a_coff;
            uint32_t bkoff = k16 * 32 + b_coff;
            uint32_t ah[4][4], al[4][4], bh[4][2], bl[4][2];
#pragma unroll
            for (int mi = 0; mi < 4; mi++) {
                uint32_t ro = (warp_m + mi * 16 + a_row) * 80 + akoff;
                LDM_X4(ah[mi][0], ah[mi][1], ah[mi][2], ah[mi][3], ah_b + ro);
                LDM_X4(al[mi][0], al[mi][1], al[mi][2], al[mi][3], al_b + ro);
            }
#pragma unroll
            for (int ni2 = 0; ni2 < 2; ni2++) {
                uint32_t ro = (warp_n + ni2 * 16 + b_row) * 80 + bkoff;
                LDM_X4(bh[ni2 * 2][0], bh[ni2 * 2][1],
                       bh[ni2 * 2 + 1][0], bh[ni2 * 2 + 1][1], bh_b + ro);
                LDM_X4(bl[ni2 * 2][0], bl[ni2 * 2][1],
                       bl[ni2 * 2 + 1][0], bl[ni2 * 2 + 1][1], bl_b + ro);
            }
#pragma unroll
            for (int mi = 0; mi < 4; mi++)
#pragma unroll
                for (int ni = 0; ni < 4; ni++) {
                    MMA_BF16(c[mi][ni], ah[mi], bh[ni]);
                    MMA_BF16(c[mi][ni], ah[mi], bl[ni]);
                    MMA_BF16(c[mi][ni], al[mi], bh[ni]);
                }
        }
        __syncthreads();
        if (kb + GSTAGES < D_EMBED / 32)
            load_stage(st, Ahi, Alo, Bhi, Blo, bm, bn, kb + GSTAGES, tid);
        CP_COMMIT();
        s ^= 1;
    }

#pragma unroll
    for (int mi = 0; mi < 4; mi++) {
#pragma unroll
        for (int half = 0; half < 2; half++) {
            int m = bm + warp_m + mi * 16 + (lane >> 2) + half * 8;
            int bb = m >> 11, sdx = m & (N_S - 1);
#pragma unroll
            for (int ni = 0; ni < 4; ni++) {
                int n = bn + warp_n + ni * 8 + 2 * (lane & 3);
                float2 o;
                o.x = c[mi][ni][half * 2 + 0] + bias[n];
                o.y = c[mi][ni][half * 2 + 1] + bias[n + 1];
                if (res) {
                    float2 rv = *(const float2*)(res + (size_t)m * D_EMBED + n);
                    o.x += rv.x; o.y += rv.y;
                }
                if (qkv) {
                    int h = n >> 6, d = n & 63;
                    size_t off = (((size_t)(bb * N_HEADS + h)) * N_S + sdx) * D_HEAD + d;
                    *(uint32_t*)(out_hi + off) = pk2(o.x, o.y);   // hi only
                } else {
                    *(float2*)(out + (size_t)m * D_EMBED + n) = o;
                }
            }
        }
    }
}

// merged QKV: grid (8, 32, 3); z selects weight/bias/output
__global__ __launch_bounds__(256, 2) void gemm_qkv(
    const __nv_bfloat16* __restrict__ Ahi, const __nv_bfloat16* __restrict__ Alo,
    const __nv_bfloat16* __restrict__ whi, const __nv_bfloat16* __restrict__ wlo,
    const float* __restrict__ bq, const float* __restrict__ bk,
    const float* __restrict__ bv, __nv_bfloat16* __restrict__ qkv)
{
    const int z = blockIdx.z;
    const size_t WSZ = (size_t)D_EMBED * D_EMBED;
    const float* bias = (z == 0) ? bq : (z == 1) ? bk : bv;
    gemm_core(Ahi, Alo, whi + z * WSZ, wlo + z * WSZ, bias, nullptr,
              nullptr, qkv + (size_t)z * SZ, 1,
              blockIdx.y * 128, blockIdx.x * 128);
}

__global__ __launch_bounds__(256, 2) void gemm_oproj(
    const __nv_bfloat16* __restrict__ Ahi, const __nv_bfloat16* __restrict__ Alo,
    const __nv_bfloat16* __restrict__ Bhi, const __nv_bfloat16* __restrict__ Blo,
    const float* __restrict__ bias, const float* __restrict__ res,
    float* __restrict__ out)
{
    gemm_core(Ahi, Alo, Bhi, Blo, bias, res, out, nullptr, 0,
              blockIdx.y * 128, blockIdx.x * 128);
}

// ---------------- tensor-core flash attention (pure bf16 MMA) -------------------
// Q/K/V bf16-hi only; S and softmax in fp32; P bf16-hi. Calibrated error law:
// each dropped 2^-9 hi/lo term ~ +5e-5 final rel_err (4 drops total ~ 2e-4).
#define ROWB 144
#define AKV_OFF (128 * ROWB)                 // 18432 (Q)
#define AKV_STAGE (2 * 64 * ROWB)            // 18432 (K,V)
#define AMSK_OFF (AKV_OFF + 2 * AKV_STAGE)   // 55296
#define ATTN_SMEM (AMSK_OFF + 512)           // 55808

__device__ __forceinline__ void attn_load_kv(
    uint32_t smb, const __nv_bfloat16* qkv,
    const float* mask, int bh, int b, int kt, int st, int tid)
{
    size_t goff = ((size_t)bh * N_S + kt * 64) * D_HEAD;
    uint32_t base = smb + AKV_OFF + st * AKV_STAGE;
#pragma unroll
    for (int bf = 0; bf < 2; bf++) {             // K, V
        const __nv_bfloat16* sp = qkv + (size_t)(1 + bf) * SZ + goff;
        uint32_t db = base + bf * (64 * ROWB);
#pragma unroll
        for (int rep = 0; rep < 2; rep++) {
            int idx = tid + rep * 256;
            int r = idx >> 3, cq = idx & 7;
            cp16(db + r * ROWB + cq * 16, sp + (size_t)r * D_HEAD + cq * 8);
        }
    }
    if (tid < 16)
        cp16(smb + AMSK_OFF + st * 256 + tid * 16, mask + (size_t)b * N_S + kt * 64 + tid * 4);
}

__global__ __launch_bounds__(256, 2) void attn_mma(
    const __nv_bfloat16* __restrict__ qkv, const float* __restrict__ mask,
    __nv_bfloat16* __restrict__ chi, __nv_bfloat16* __restrict__ clo)
{
    extern __shared__ char smraw[];
    const uint32_t smb = s2u(smraw);
    const int bh = blockIdx.x;
    const int qt = blockIdx.y;
    const int b = bh >> 4;
    const int h = bh & 15;
    const int tid = threadIdx.x;
    const int lane = tid & 31;
    const int wid = tid >> 5;
    const int wrow = wid * 16;

    {
        size_t qoff = ((size_t)bh * N_S + qt * 128) * D_HEAD;
        const __nv_bfloat16* sp = qkv + qoff;    // q hi
#pragma unroll
        for (int rep = 0; rep < 4; rep++) {
            int idx = tid + rep * 256;
            int r = idx >> 3, cq = idx & 7;
            cp16(smb + r * ROWB + cq * 16, sp + (size_t)r * D_HEAD + cq * 8);
        }
        attn_load_kv(smb, qkv, mask, bh, b, 0, 0, tid);
        CP_COMMIT();
        attn_load_kv(smb, qkv, mask, bh, b, 1, 1, tid);
        CP_COMMIT();
    }

    float o[8][4];
#pragma unroll
    for (int ni = 0; ni < 8; ni++)
#pragma unroll
        for (int e = 0; e < 4; e++) o[ni][e] = 0.0f;
    float m_run[2] = {-3.0e38f, -3.0e38f};
    float l_run[2] = {0.0f, 0.0f};

    uint32_t qh[4][4];
    const uint32_t a_row = lane & 15;
    const uint32_t a_coff = (lane >> 4) * 16;
    const uint32_t b_row = (lane & 7) + ((lane >> 4) << 3);
    const uint32_t b_coff = ((lane >> 3) & 1) * 16;
    const uint32_t v_row = (lane & 7) + ((lane >> 3) & 1) * 8;
    const uint32_t v_coff = (lane >> 4) * 16;
    const float scale = 0.125f;

    int st = 0;
    for (int kt = 0; kt < N_S / 64; kt++) {
        CP_WAIT1();
        __syncthreads();
        if (kt == 0) {
#pragma unroll
            for (int kk = 0; kk < 4; kk++) {
                uint32_t ad = smb + (wrow + a_row) * ROWB + kk * 32 + a_coff;
                LDM_X4(qh[kk][0], qh[kk][1], qh[kk][2], qh[kk][3], ad);
            }
        }
        uint32_t kvb = smb + AKV_OFF + st * AKV_STAGE;

        // ---- S = Q K^T : pure bf16 ----
        float s[8][4];
#pragma unroll
        for (int ni = 0; ni < 8; ni++)
#pragma unroll
            for (int e = 0; e < 4; e++) s[ni][e] = 0.0f;

#pragma unroll
        for (int kk = 0; kk < 4; kk++) {
#pragma unroll
            for (int ni2 = 0; ni2 < 4; ni2++) {
                uint32_t ro = (ni2 * 16 + b_row) * ROWB + kk * 32 + b_coff;
                uint32_t kh[4];
                LDM_X4(kh[0], kh[1], kh[2], kh[3], kvb + ro);
                MMA_BF16(s[2 * ni2], qh[kk], kh);
                MMA_BF16(s[2 * ni2 + 1], qh[kk], kh + 2);
            }
        }

        // ---- online softmax; mask read per-use from smem ----
#pragma unroll
        for (int hf = 0; hf < 2; hf++) {
            float mx = -3.0e38f;
#pragma unroll
            for (int ni = 0; ni < 8; ni++) {
                float2 mvv = *(float2*)(smraw + AMSK_OFF + st * 256 +
                                        (ni * 8 + 2 * (lane & 3)) * 4);
                float v0 = s[ni][2 * hf] * scale + mvv.x;
                float v1 = s[ni][2 * hf + 1] * scale + mvv.y;
                s[ni][2 * hf] = v0; s[ni][2 * hf + 1] = v1;
                mx = fmaxf(mx, fmaxf(v0, v1));
            }
            mx = fmaxf(mx, __shfl_xor_sync(0xffffffffu, mx, 1));
            mx = fmaxf(mx, __shfl_xor_sync(0xffffffffu, mx, 2));
            float mnew = fmaxf(m_run[hf], mx);
            float alpha = __expf(m_run[hf] - mnew);
            float sum = 0.0f;
#pragma unroll
            for (int ni = 0; ni < 8; ni++) {
                float p0 = __expf(s[ni][2 * hf] - mnew);
                float p1 = __expf(s[ni][2 * hf + 1] - mnew);
                s[ni][2 * hf] = p0; s[ni][2 * hf + 1] = p1;
                sum += p0 + p1;
            }
            sum += __shfl_xor_sync(0xffffffffu, sum, 1);
            sum += __shfl_xor_sync(0xffffffffu, sum, 2);
            l_run[hf] = l_run[hf] * alpha + sum;
            m_run[hf] = mnew;
#pragma unroll
            for (int ni = 0; ni < 8; ni++) {
                o[ni][2 * hf] *= alpha;
                o[ni][2 * hf + 1] *= alpha;
            }
        }

        // ---- O += P V : pure bf16 ----
        uint32_t vbb = kvb + 64 * ROWB;
#pragma unroll
        for (int kk = 0; kk < 4; kk++) {
            uint32_t pah[4];
            pah[0] = pk2(s[2 * kk][0], s[2 * kk][1]);
            pah[1] = pk2(s[2 * kk][2], s[2 * kk][3]);
            pah[2] = pk2(s[2 * kk + 1][0], s[2 * kk + 1][1]);
            pah[3] = pk2(s[2 * kk + 1][2], s[2 * kk + 1][3]);
#pragma unroll
            for (int ni2 = 0; ni2 < 4; ni2++) {
                uint32_t ro = (kk * 16 + v_row) * ROWB + ni2 * 32 + v_coff;
                uint32_t vh[4];
                LDM_X4_T(vh[0], vh[1], vh[2], vh[3], vbb + ro);
                MMA_BF16(o[2 * ni2], pah, vh);
                MMA_BF16(o[2 * ni2 + 1], pah, vh + 2);
            }
        }

        __syncthreads();
        if (kt + 2 < N_S / 64)
            attn_load_kv(smb, qkv, mask, bh, b, kt + 2, st, tid);
        CP_COMMIT();
        st ^= 1;
    }

#pragma unroll
    for (int hf = 0; hf < 2; hf++) {
        float inv = 1.0f / l_run[hf];
        int row = qt * 128 + wrow + (lane >> 2) + hf * 8;
        size_t mrow = ((size_t)(b * N_S + row)) * D_EMBED + h * D_HEAD;
#pragma unroll
        for (int ni = 0; ni < 8; ni++) {
            int d = ni * 8 + 2 * (lane & 3);
            float a = o[ni][2 * hf] * inv;
            float bb2 = o[ni][2 * hf + 1] * inv;
            uint32_t h2 = pk2(a, bb2);
            uint32_t l2 = pk2lo(a, bb2, h2);
            *(uint32_t*)(chi + mrow + d) = h2;
            *(uint32_t*)(clo + mrow + d) = l2;
        }
    }
}

// ---------------- LayerNorm ----------------------------------------------------
__global__ __launch_bounds__(256) void ln_kernel(
    const float* __restrict__ X, const float* __restrict__ g,
    const float* __restrict__ be, float* __restrict__ out)
{
    __shared__ float red[8];
    const int row = blockIdx.x;
    const int tid = threadIdx.x;
    const float* xr = X + (size_t)row * D_EMBED;
    float4 v = *(const float4*)(xr + tid * 4);
    float s = (v.x + v.y) + (v.z + v.w);
#pragma unroll
    for (int o = 16; o >= 1; o >>= 1) s += __shfl_xor_sync(0xffffffffu, s, o);
    if ((tid & 31) == 0) red[tid >> 5] = s;
    __syncthreads();
    float tot = red[0] + red[1] + red[2] + red[3] +
                red[4] + red[5] + red[6] + red[7];
    float mu = tot * (1.0f / D_EMBED);
    float d0 = v.x - mu, d1 = v.y - mu, d2 = v.z - mu, d3 = v.w - mu;
    float sq = d0 * d0 + d1 * d1 + d2 * d2 + d3 * d3;
#pragma unroll
    for (int o = 16; o >= 1; o >>= 1) sq += __shfl_xor_sync(0xffffffffu, sq, o);
    __syncthreads();
    if ((tid & 31) == 0) red[tid >> 5] = sq;
    __syncthreads();
    float var = (red[0] + red[1] + red[2] + red[3] +
                 red[4] + red[5] + red[6] + red[7]) * (1.0f / D_EMBED);
    float r = rsqrtf(var + 1e-12f);
    float4 gv = *(const float4*)(g + tid * 4);
    float4 bv = *(const float4*)(be + tid * 4);
    float4 o;
    o.x = d0 * r * gv.x + bv.x;
    o.y = d1 * r * gv.y + bv.y;
    o.z = d2 * r * gv.z + bv.z;
    o.w = d3 * r * gv.w + bv.w;
    *(float4*)(out + (size_t)row * D_EMBED + tid * 4) = o;
}

// ---------------- launch --------------------------------------------------------
extern "C" void kernel_launch(void* const* d_in, const int* in_sizes, int n_in,
                              void* d_out, int out_size)
{
    const float* X     = (const float*)d_in[0];
    const float* mask  = (const float*)d_in[1];
    const float* Wq    = (const float*)d_in[2];
    const float* bq    = (const float*)d_in[3];
    const float* Wk    = (const float*)d_in[4];
    const float* bk    = (const float*)d_in[5];
    const float* Wv    = (const float*)d_in[6];
    const float* bv    = (const float*)d_in[7];
    const float* Wo    = (const float*)d_in[8];
    const float* bo    = (const float*)d_in[9];
    const float* gamma = (const float*)d_in[10];
    const float* beta  = (const float*)d_in[11];
    float* out = (float*)d_out;

    float *x;
    __nv_bfloat16 *xhi, *xlo, *chi, *clo, *whi, *wlo, *qkv;
    cudaGetSymbolAddress((void**)&x, g_x);
    cudaGetSymbolAddress((void**)&xhi, g_xhi);
    cudaGetSymbolAddress((void**)&xlo, g_xlo);
    cudaGetSymbolAddress((void**)&chi, g_chi);
    cudaGetSymbolAddress((void**)&clo, g_clo);
    cudaGetSymbolAddress((void**)&whi, g_whi);
    cudaGetSymbolAddress((void**)&wlo, g_wlo);
    cudaGetSymbolAddress((void**)&qkv, g_qkv);

    cudaFuncSetAttribute(attn_mma, cudaFuncAttributeMaxDynamicSharedMemorySize,
                         ATTN_SMEM);
    cudaFuncSetAttribute(gemm_qkv, cudaFuncAttributeMaxDynamicSharedMemorySize,
                         GEMM_SMEM);
    cudaFuncSetAttribute(gemm_oproj, cudaFuncAttributeMaxDynamicSharedMemorySize,
                         GEMM_SMEM);

    const size_t WSZ = (size_t)D_EMBED * D_EMBED;
    split_bf16<<<(N_M * D_EMBED / 4 + 255) / 256, 256>>>(X, xhi, xlo, N_M * D_EMBED / 4);
    split_w4<<<dim3(WSZ / 4 / 256, 4), 256>>>(Wq, Wk, Wv, Wo, whi, wlo);

    gemm_qkv<<<dim3(D_EMBED / 128, N_M / 128, 3), 256, GEMM_SMEM>>>(
        xhi, xlo, whi, wlo, bq, bk, bv, qkv);
    attn_mma<<<dim3(N_B * N_HEADS, N_S / 128), 256, ATTN_SMEM>>>(
        qkv, mask, chi, clo);
    gemm_oproj<<<dim3(D_EMBED / 128, N_M / 128), 256, GEMM_SMEM>>>(
        chi, clo, whi + 3 * WSZ, wlo + 3 * WSZ, bo, X, x);
    ln_kernel<<<N_M, 256>>>(x, gamma, beta, out);
}

// round 10
// speedup vs baseline: 4.3172x; 1.2059x over previous
#include <cuda_runtime.h>
#include <cuda_bf16.h>
#include <cstdint>
#include <math.h>

#define D_EMBED 1024
#define N_HEADS 16
#define D_HEAD  64
#define N_B     2
#define N_S     2048
#define N_M     (N_B * N_S)   // 4096 rows
#define SZ      ((size_t)N_B * N_HEADS * N_S * D_HEAD)   // 4M elems per buffer

// ---------------- scratch -----------------------------------------------------
__device__ __align__(16) float g_x[(size_t)N_M * D_EMBED];
__device__ __align__(16) __nv_bfloat16 g_xhi[(size_t)N_M * D_EMBED];
__device__ __align__(16) __nv_bfloat16 g_xlo[(size_t)N_M * D_EMBED];
__device__ __align__(16) __nv_bfloat16 g_chi[(size_t)N_M * D_EMBED];
__device__ __align__(16) __nv_bfloat16 g_clo[(size_t)N_M * D_EMBED];
__device__ __align__(16) __nv_bfloat16 g_whi[4 * D_EMBED * D_EMBED];
__device__ __align__(16) __nv_bfloat16 g_wlo[4 * D_EMBED * D_EMBED];
// [qhi | khi | vhi], each SZ elements (attention is bf16-hi only; q pre-scaled)
__device__ __align__(16) __nv_bfloat16 g_qkv[3 * SZ];

// ---------------- helpers -----------------------------------------------------
__device__ __forceinline__ uint32_t s2u(const void* p) {
    uint32_t a;
    asm("{ .reg .u64 t; cvta.to.shared.u64 t, %1; cvt.u32.u64 %0, t; }"
        : "=r"(a) : "l"(p));
    return a;
}
__device__ __forceinline__ void cp16(uint32_t dst, const void* src) {
    asm volatile("cp.async.cg.shared.global [%0], [%1], 16;"
                 :: "r"(dst), "l"(src) : "memory");
}
#define CP_COMMIT() asm volatile("cp.async.commit_group;" ::: "memory")
#define CP_WAIT1()  asm volatile("cp.async.wait_group 1;" ::: "memory")

#define LDM_X4(r0, r1, r2, r3, addr) \
    asm volatile("ldmatrix.sync.aligned.m8n8.x4.shared.b16 {%0,%1,%2,%3}, [%4];" \
                 : "=r"(r0), "=r"(r1), "=r"(r2), "=r"(r3) : "r"(addr))
#define LDM_X4_T(r0, r1, r2, r3, addr) \
    asm volatile("ldmatrix.sync.aligned.m8n8.x4.trans.shared.b16 {%0,%1,%2,%3}, [%4];" \
                 : "=r"(r0), "=r"(r1), "=r"(r2), "=r"(r3) : "r"(addr))

#define MMA_BF16(c, a, b) \
    asm volatile( \
        "mma.sync.aligned.m16n8k16.row.col.f32.bf16.bf16.f32 " \
        "{%0,%1,%2,%3}, {%4,%5,%6,%7}, {%8,%9}, {%0,%1,%2,%3};" \
        : "+f"((c)[0]), "+f"((c)[1]), "+f"((c)[2]), "+f"((c)[3]) \
        : "r"((a)[0]), "r"((a)[1]), "r"((a)[2]), "r"((a)[3]), \
          "r"((b)[0]), "r"((b)[1]))

__device__ __forceinline__ uint32_t pk2(float a, float b) {
    __nv_bfloat162 t;
    t.x = __float2bfloat16(a);
    t.y = __float2bfloat16(b);
    return *(uint32_t*)&t;
}
__device__ __forceinline__ uint32_t pk2lo(float a, float b, uint32_t hi) {
    __nv_bfloat162 t = *(__nv_bfloat162*)&hi;
    return pk2(a - __bfloat162float(t.x), b - __bfloat162float(t.y));
}

// ---------------- splits --------------------------------------------------------
__global__ __launch_bounds__(256) void split_bf16(
    const float* __restrict__ src, __nv_bfloat16* __restrict__ hi,
    __nv_bfloat16* __restrict__ lo, int n4)
{
    int i = blockIdx.x * blockDim.x + threadIdx.x;
    if (i >= n4) return;
    float4 v = ((const float4*)src)[i];
    uint32_t h0 = pk2(v.x, v.y), h1 = pk2(v.z, v.w);
    uint32_t l0 = pk2lo(v.x, v.y, h0), l1 = pk2lo(v.z, v.w, h1);
    ((uint32_t*)hi)[2 * i + 0] = h0;
    ((uint32_t*)hi)[2 * i + 1] = h1;
    ((uint32_t*)lo)[2 * i + 0] = l0;
    ((uint32_t*)lo)[2 * i + 1] = l1;
}

__global__ __launch_bounds__(256) void split_w4(
    const float* __restrict__ w0, const float* __restrict__ w1,
    const float* __restrict__ w2, const float* __restrict__ w3,
    __nv_bfloat16* __restrict__ hi, __nv_bfloat16* __restrict__ lo)
{
    const int z = blockIdx.y;
    const float* src = (z == 0) ? w0 : (z == 1) ? w1 : (z == 2) ? w2 : w3;
    size_t off = (size_t)z * D_EMBED * D_EMBED;
    int i = blockIdx.x * blockDim.x + threadIdx.x;
    float4 v = ((const float4*)src)[i];
    uint32_t h0 = pk2(v.x, v.y), h1 = pk2(v.z, v.w);
    uint32_t l0 = pk2lo(v.x, v.y, h0), l1 = pk2lo(v.z, v.w, h1);
    ((uint32_t*)(hi + off))[2 * i + 0] = h0;
    ((uint32_t*)(hi + off))[2 * i + 1] = h1;
    ((uint32_t*)(lo + off))[2 * i + 0] = l0;
    ((uint32_t*)(lo + off))[2 * i + 1] = l1;
}

// ---------------- bf16-split tensor GEMM core ------------------------------------
// THREE=true: ah·bh + ah·bl + al·bh (O-proj). THREE=false: ah·bh + ah·bl (QKV;
// A-lo never loaded — its 2^-9 correction is below the bf16 output rounding).
#define BUF_B  (128 * 80)
#define STAGE_B (4 * BUF_B)
#define GSTAGES 2
#define GEMM_SMEM (GSTAGES * STAGE_B)   // 81920

template<bool THREE>
__device__ __forceinline__ void load_stage(
    uint32_t st, const __nv_bfloat16* Ahi, const __nv_bfloat16* Alo,
    const __nv_bfloat16* Bhi, const __nv_bfloat16* Blo,
    int bm, int bn, int kb, int tid)
{
    const __nv_bfloat16* srcs[4] = {Ahi, Alo, Bhi, Blo};
    const int rowoff[4] = {bm, bm, bn, bn};
#pragma unroll
    for (int bf = 0; bf < 4; bf++) {
        if (!THREE && bf == 1) continue;   // skip A-lo
        const __nv_bfloat16* sb = srcs[bf] + (size_t)rowoff[bf] * D_EMBED + kb * 32;
        uint32_t db = st + bf * BUF_B;
#pragma unroll
        for (int i = 0; i < 2; i++) {
            int c = tid + i * 256;
            int row = c >> 2, kc = c & 3;
            cp16(db + row * 80 + kc * 16, sb + (size_t)row * D_EMBED + kc * 8);
        }
    }
}

template<bool THREE>
__device__ __forceinline__ void gemm_core(
    const __nv_bfloat16* Ahi, const __nv_bfloat16* Alo,
    const __nv_bfloat16* Bhi, const __nv_bfloat16* Blo,
    const float* bias, const float* res, float* out,
    __nv_bfloat16* out_hi, int qkv, float oscale, int bm, int bn)
{
    extern __shared__ char smraw[];
    const uint32_t smb = s2u(smraw);
    const int tid = threadIdx.x;
    const int lane = tid & 31;
    const int wid = tid >> 5;
    const int warp_m = (wid >> 2) * 64;
    const int warp_n = (wid & 3) * 32;

    float c[4][4][4];
#pragma unroll
    for (int mi = 0; mi < 4; mi++)
#pragma unroll
        for (int ni = 0; ni < 4; ni++)
#pragma unroll
            for (int e = 0; e < 4; e++) c[mi][ni][e] = 0.0f;

#pragma unroll
    for (int p = 0; p < GSTAGES; p++) {
        load_stage<THREE>(smb + p * STAGE_B, Ahi, Alo, Bhi, Blo, bm, bn, p, tid);
        CP_COMMIT();
    }

    const uint32_t a_row = lane & 15;
    const uint32_t a_coff = (lane >> 4) * 16;
    const uint32_t b_row = (lane & 7) + ((lane >> 4) << 3);
    const uint32_t b_coff = ((lane >> 3) & 1) * 16;

    int s = 0;
    for (int kb = 0; kb < D_EMBED / 32; kb++) {
        CP_WAIT1();
        __syncthreads();
        uint32_t st = smb + s * STAGE_B;
        uint32_t ah_b = st, al_b = st + BUF_B;
        uint32_t bh_b = st + 2 * BUF_B, bl_b = st + 3 * BUF_B;

#pragma unroll
        for (int k16 = 0; k16 < 2; k16++) {
            uint32_t akoff = k16 * 32 + a_coff;
            uint32_t bkoff = k16 * 32 + b_coff;
            uint32_t ah[4][4], al[4][4], bh[4][2], bl[4][2];
#pragma unroll
            for (int mi = 0; mi < 4; mi++) {
                uint32_t ro = (warp_m + mi * 16 + a_row) * 80 + akoff;
                LDM_X4(ah[mi][0], ah[mi][1], ah[mi][2], ah[mi][3], ah_b + ro);
                if (THREE)
                    LDM_X4(al[mi][0], al[mi][1], al[mi][2], al[mi][3], al_b + ro);
            }
#pragma unroll
            for (int ni2 = 0; ni2 < 2; ni2++) {
                uint32_t ro = (warp_n + ni2 * 16 + b_row) * 80 + bkoff;
                LDM_X4(bh[ni2 * 2][0], bh[ni2 * 2][1],
                       bh[ni2 * 2 + 1][0], bh[ni2 * 2 + 1][1], bh_b + ro);
                LDM_X4(bl[ni2 * 2][0], bl[ni2 * 2][1],
                       bl[ni2 * 2 + 1][0], bl[ni2 * 2 + 1][1], bl_b + ro);
            }
#pragma unroll
            for (int mi = 0; mi < 4; mi++)
#pragma unroll
                for (int ni = 0; ni < 4; ni++) {
                    MMA_BF16(c[mi][ni], ah[mi], bh[ni]);
                    MMA_BF16(c[mi][ni], ah[mi], bl[ni]);
                    if (THREE)
                        MMA_BF16(c[mi][ni], al[mi], bh[ni]);
                }
        }
        __syncthreads();
        if (kb + GSTAGES < D_EMBED / 32)
            load_stage<THREE>(st, Ahi, Alo, Bhi, Blo, bm, bn, kb + GSTAGES, tid);
        CP_COMMIT();
        s ^= 1;
    }

#pragma unroll
    for (int mi = 0; mi < 4; mi++) {
#pragma unroll
        for (int half = 0; half < 2; half++) {
            int m = bm + warp_m + mi * 16 + (lane >> 2) + half * 8;
            int bb = m >> 11, sdx = m & (N_S - 1);
#pragma unroll
            for (int ni = 0; ni < 4; ni++) {
                int n = bn + warp_n + ni * 8 + 2 * (lane & 3);
                float2 o;
                o.x = (c[mi][ni][half * 2 + 0] + bias[n]) * oscale;
                o.y = (c[mi][ni][half * 2 + 1] + bias[n + 1]) * oscale;
                if (res) {
                    float2 rv = *(const float2*)(res + (size_t)m * D_EMBED + n);
                    o.x += rv.x; o.y += rv.y;
                }
                if (qkv) {
                    int h = n >> 6, d = n & 63;
                    size_t off = (((size_t)(bb * N_HEADS + h)) * N_S + sdx) * D_HEAD + d;
                    *(uint32_t*)(out_hi + off) = pk2(o.x, o.y);
                } else {
                    *(float2*)(out + (size_t)m * D_EMBED + n) = o;
                }
            }
        }
    }
}

// merged QKV: grid (8, 32, 3); z selects weight/bias/output. Q pre-scaled by 1/8.
__global__ __launch_bounds__(256, 2) void gemm_qkv(
    const __nv_bfloat16* __restrict__ Ahi, const __nv_bfloat16* __restrict__ Alo,
    const __nv_bfloat16* __restrict__ whi, const __nv_bfloat16* __restrict__ wlo,
    const float* __restrict__ bq, const float* __restrict__ bk,
    const float* __restrict__ bv, __nv_bfloat16* __restrict__ qkv)
{
    const int z = blockIdx.z;
    const size_t WSZ = (size_t)D_EMBED * D_EMBED;
    const float* bias = (z == 0) ? bq : (z == 1) ? bk : bv;
    const float sc = (z == 0) ? 0.125f : 1.0f;
    gemm_core<false>(Ahi, Alo, whi + z * WSZ, wlo + z * WSZ, bias, nullptr,
                     nullptr, qkv + (size_t)z * SZ, 1, sc,
                     blockIdx.y * 128, blockIdx.x * 128);
}

__global__ __launch_bounds__(256, 2) void gemm_oproj(
    const __nv_bfloat16* __restrict__ Ahi, const __nv_bfloat16* __restrict__ Alo,
    const __nv_bfloat16* __restrict__ Bhi, const __nv_bfloat16* __restrict__ Blo,
    const float* __restrict__ bias, const float* __restrict__ res,
    float* __restrict__ out)
{
    gemm_core<true>(Ahi, Alo, Bhi, Blo, bias, res, out, nullptr, 0, 1.0f,
                    blockIdx.y * 128, blockIdx.x * 128);
}

// ---------------- tensor-core flash attention (pure bf16 MMA) -------------------
#define ROWB 144
#define AKV_OFF (128 * ROWB)                 // 18432 (Q)
#define AKV_STAGE (2 * 64 * ROWB)            // 18432 (K,V)
#define AMSK_OFF (AKV_OFF + 2 * AKV_STAGE)   // 55296
#define ATTN_SMEM (AMSK_OFF + 512)           // 55808

__device__ __forceinline__ void attn_load_kv(
    uint32_t smb, const __nv_bfloat16* qkv,
    const float* mask, int bh, int b, int kt, int st, int tid)
{
    size_t goff = ((size_t)bh * N_S + kt * 64) * D_HEAD;
    uint32_t base = smb + AKV_OFF + st * AKV_STAGE;
#pragma unroll
    for (int bf = 0; bf < 2; bf++) {             // K, V
        const __nv_bfloat16* sp = qkv + (size_t)(1 + bf) * SZ + goff;
        uint32_t db = base + bf * (64 * ROWB);
#pragma unroll
        for (int rep = 0; rep < 2; rep++) {
            int idx = tid + rep * 256;
            int r = idx >> 3, cq = idx & 7;
            cp16(db + r * ROWB + cq * 16, sp + (size_t)r * D_HEAD + cq * 8);
        }
    }
    if (tid < 16)
        cp16(smb + AMSK_OFF + st * 256 + tid * 16, mask + (size_t)b * N_S + kt * 64 + tid * 4);
}

__global__ __launch_bounds__(256, 2) void attn_mma(
    const __nv_bfloat16* __restrict__ qkv, const float* __restrict__ mask,
    __nv_bfloat16* __restrict__ chi, __nv_bfloat16* __restrict__ clo)
{
    extern __shared__ char smraw[];
    const uint32_t smb = s2u(smraw);
    const int bh = blockIdx.x;
    const int qt = blockIdx.y;
    const int b = bh >> 4;
    const int h = bh & 15;
    const int tid = threadIdx.x;
    const int lane = tid & 31;
    const int wid = tid >> 5;
    const int wrow = wid * 16;

    {
        size_t qoff = ((size_t)bh * N_S + qt * 128) * D_HEAD;
        const __nv_bfloat16* sp = qkv + qoff;    // q (pre-scaled)
#pragma unroll
        for (int rep = 0; rep < 4; rep++) {
            int idx = tid + rep * 256;
            int r = idx >> 3, cq = idx & 7;
            cp16(smb + r * ROWB + cq * 16, sp + (size_t)r * D_HEAD + cq * 8);
        }
        attn_load_kv(smb, qkv, mask, bh, b, 0, 0, tid);
        CP_COMMIT();
        attn_load_kv(smb, qkv, mask, bh, b, 1, 1, tid);
        CP_COMMIT();
    }

    float o[8][4];
#pragma unroll
    for (int ni = 0; ni < 8; ni++)
#pragma unroll
        for (int e = 0; e < 4; e++) o[ni][e] = 0.0f;
    float m_run[2] = {-3.0e38f, -3.0e38f};
    float l_run[2] = {0.0f, 0.0f};

    uint32_t qh[4][4];
    const uint32_t a_row = lane & 15;
    const uint32_t a_coff = (lane >> 4) * 16;
    const uint32_t b_row = (lane & 7) + ((lane >> 4) << 3);
    const uint32_t b_coff = ((lane >> 3) & 1) * 16;
    const uint32_t v_row = (lane & 7) + ((lane >> 3) & 1) * 8;
    const uint32_t v_coff = (lane >> 4) * 16;

    int st = 0;
    for (int kt = 0; kt < N_S / 64; kt++) {
        CP_WAIT1();
        __syncthreads();
        if (kt == 0) {
#pragma unroll
            for (int kk = 0; kk < 4; kk++) {
                uint32_t ad = smb + (wrow + a_row) * ROWB + kk * 32 + a_coff;
                LDM_X4(qh[kk][0], qh[kk][1], qh[kk][2], qh[kk][3], ad);
            }
        }
        uint32_t kvb = smb + AKV_OFF + st * AKV_STAGE;

        // ---- S = Q K^T : pure bf16 (scale folded into Q) ----
        float s[8][4];
#pragma unroll
        for (int ni = 0; ni < 8; ni++)
#pragma unroll
            for (int e = 0; e < 4; e++) s[ni][e] = 0.0f;

#pragma unroll
        for (int kk = 0; kk < 4; kk++) {
#pragma unroll
            for (int ni2 = 0; ni2 < 4; ni2++) {
                uint32_t ro = (ni2 * 16 + b_row) * ROWB + kk * 32 + b_coff;
                uint32_t kh[4];
                LDM_X4(kh[0], kh[1], kh[2], kh[3], kvb + ro);
                MMA_BF16(s[2 * ni2], qh[kk], kh);
                MMA_BF16(s[2 * ni2 + 1], qh[kk], kh + 2);
            }
        }

        // ---- online softmax; mask read per-use from smem ----
#pragma unroll
        for (int hf = 0; hf < 2; hf++) {
            float mx = -3.0e38f;
#pragma unroll
            for (int ni = 0; ni < 8; ni++) {
                float2 mvv = *(float2*)(smraw + AMSK_OFF + st * 256 +
                                        (ni * 8 + 2 * (lane & 3)) * 4);
                float v0 = s[ni][2 * hf] + mvv.x;
                float v1 = s[ni][2 * hf + 1] + mvv.y;
                s[ni][2 * hf] = v0; s[ni][2 * hf + 1] = v1;
                mx = fmaxf(mx, fmaxf(v0, v1));
            }
            mx = fmaxf(mx, __shfl_xor_sync(0xffffffffu, mx, 1));
            mx = fmaxf(mx, __shfl_xor_sync(0xffffffffu, mx, 2));
            float mnew = fmaxf(m_run[hf], mx);
            float alpha = __expf(m_run[hf] - mnew);
            float sum = 0.0f;
#pragma unroll
            for (int ni = 0; ni < 8; ni++) {
                float p0 = __expf(s[ni][2 * hf] - mnew);
                float p1 = __expf(s[ni][2 * hf + 1] - mnew);
                s[ni][2 * hf] = p0; s[ni][2 * hf + 1] = p1;
                sum += p0 + p1;
            }
            sum += __shfl_xor_sync(0xffffffffu, sum, 1);
            sum += __shfl_xor_sync(0xffffffffu, sum, 2);
            l_run[hf] = l_run[hf] * alpha + sum;
            m_run[hf] = mnew;
#pragma unroll
            for (int ni = 0; ni < 8; ni++) {
                o[ni][2 * hf] *= alpha;
                o[ni][2 * hf + 1] *= alpha;
            }
        }

        // ---- O += P V : pure bf16 ----
        uint32_t vbb = kvb + 64 * ROWB;
#pragma unroll
        for (int kk = 0; kk < 4; kk++) {
            uint32_t pah[4];
            pah[0] = pk2(s[2 * kk][0], s[2 * kk][1]);
            pah[1] = pk2(s[2 * kk][2], s[2 * kk][3]);
            pah[2] = pk2(s[2 * kk + 1][0], s[2 * kk + 1][1]);
            pah[3] = pk2(s[2 * kk + 1][2], s[2 * kk + 1][3]);
#pragma unroll
            for (int ni2 = 0; ni2 < 4; ni2++) {
                uint32_t ro = (kk * 16 + v_row) * ROWB + ni2 * 32 + v_coff;
                uint32_t vh[4];
                LDM_X4_T(vh[0], vh[1], vh[2], vh[3], vbb + ro);
                MMA_BF16(o[2 * ni2], pah, vh);
                MMA_BF16(o[2 * ni2 + 1], pah, vh + 2);
            }
        }

        __syncthreads();
        if (kt + 2 < N_S / 64)
            attn_load_kv(smb, qkv, mask, bh, b, kt + 2, st, tid);
        CP_COMMIT();
        st ^= 1;
    }

#pragma unroll
    for (int hf = 0; hf < 2; hf++) {
        float inv = 1.0f / l_run[hf];
        int row = qt * 128 + wrow + (lane >> 2) + hf * 8;
        size_t mrow = ((size_t)(b * N_S + row)) * D_EMBED + h * D_HEAD;
#pragma unroll
        for (int ni = 0; ni < 8; ni++) {
            int d = ni * 8 + 2 * (lane & 3);
            float a = o[ni][2 * hf] * inv;
            float bb2 = o[ni][2 * hf + 1] * inv;
            uint32_t h2 = pk2(a, bb2);
            uint32_t l2 = pk2lo(a, bb2, h2);
            *(uint32_t*)(chi + mrow + d) = h2;
            *(uint32_t*)(clo + mrow + d) = l2;
        }
    }
}

// ---------------- LayerNorm ----------------------------------------------------
__global__ __launch_bounds__(256) void ln_kernel(
    const float* __restrict__ X, const float* __restrict__ g,
    const float* __restrict__ be, float* __restrict__ out)
{
    __shared__ float red[8];
    const int row = blockIdx.x;
    const int tid = threadIdx.x;
    const float* xr = X + (size_t)row * D_EMBED;
    float4 v = *(const float4*)(xr + tid * 4);
    float s = (v.x + v.y) + (v.z + v.w);
#pragma unroll
    for (int o = 16; o >= 1; o >>= 1) s += __shfl_xor_sync(0xffffffffu, s, o);
    if ((tid & 31) == 0) red[tid >> 5] = s;
    __syncthreads();
    float tot = red[0] + red[1] + red[2] + red[3] +
                red[4] + red[5] + red[6] + red[7];
    float mu = tot * (1.0f / D_EMBED);
    float d0 = v.x - mu, d1 = v.y - mu, d2 = v.z - mu, d3 = v.w - mu;
    float sq = d0 * d0 + d1 * d1 + d2 * d2 + d3 * d3;
#pragma unroll
    for (int o = 16; o >= 1; o >>= 1) sq += __shfl_xor_sync(0xffffffffu, sq, o);
    __syncthreads();
    if ((tid & 31) == 0) red[tid >> 5] = sq;
    __syncthreads();
    float var = (red[0] + red[1] + red[2] + red[3] +
                 red[4] + red[5] + red[6] + red[7]) * (1.0f / D_EMBED);
    float r = rsqrtf(var + 1e-12f);
    float4 gv = *(const float4*)(g + tid * 4);
    float4 bv = *(const float4*)(be + tid * 4);
    float4 o;
    o.x = d0 * r * gv.x + bv.x;
    o.y = d1 * r * gv.y + bv.y;
    o.z = d2 * r * gv.z + bv.z;
    o.w = d3 * r * gv.w + bv.w;
    *(float4*)(out + (size_t)row * D_EMBED + tid * 4) = o;
}

// ---------------- launch --------------------------------------------------------
extern "C" void kernel_launch(void* const* d_in, const int* in_sizes, int n_in,
                              void* d_out, int out_size)
{
    const float* X     = (const float*)d_in[0];
    const float* mask  = (const float*)d_in[1];
    const float* Wq    = (const float*)d_in[2];
    const float* bq    = (const float*)d_in[3];
    const float* Wk    = (const float*)d_in[4];
    const float* bk    = (const float*)d_in[5];
    const float* Wv    = (const float*)d_in[6];
    const float* bv    = (const float*)d_in[7];
    const float* Wo    = (const float*)d_in[8];
    const float* bo    = (const float*)d_in[9];
    const float* gamma = (const float*)d_in[10];
    const float* beta  = (const float*)d_in[11];
    float* out = (float*)d_out;

    float *x;
    __nv_bfloat16 *xhi, *xlo, *chi, *clo, *whi, *wlo, *qkv;
    cudaGetSymbolAddress((void**)&x, g_x);
    cudaGetSymbolAddress((void**)&xhi, g_xhi);
    cudaGetSymbolAddress((void**)&xlo, g_xlo);
    cudaGetSymbolAddress((void**)&chi, g_chi);
    cudaGetSymbolAddress((void**)&clo, g_clo);
    cudaGetSymbolAddress((void**)&whi, g_whi);
    cudaGetSymbolAddress((void**)&wlo, g_wlo);
    cudaGetSymbolAddress((void**)&qkv, g_qkv);

    cudaFuncSetAttribute(attn_mma, cudaFuncAttributeMaxDynamicSharedMemorySize,
                         ATTN_SMEM);
    cudaFuncSetAttribute(gemm_qkv, cudaFuncAttributeMaxDynamicSharedMemorySize,
                         GEMM_SMEM);
    cudaFuncSetAttribute(gemm_oproj, cudaFuncAttributeMaxDynamicSharedMemorySize,
                         GEMM_SMEM);

    const size_t WSZ = (size_t)D_EMBED * D_EMBED;
    split_bf16<<<(N_M * D_EMBED / 4 + 255) / 256, 256>>>(X, xhi, xlo, N_M * D_EMBED / 4);
    split_w4<<<dim3(WSZ / 4 / 256, 4), 256>>>(Wq, Wk, Wv, Wo, whi, wlo);

    gemm_qkv<<<dim3(D_EMBED / 128, N_M / 128, 3), 256, GEMM_SMEM>>>(
        xhi, xlo, whi, wlo, bq, bk, bv, qkv);
    attn_mma<<<dim3(N_B * N_HEADS, N_S / 128), 256, ATTN_SMEM>>>(
        qkv, mask, chi, clo);
    gemm_oproj<<<dim3(D_EMBED / 128, N_M / 128), 256, GEMM_SMEM>>>(
        chi, clo, whi + 3 * WSZ, wlo + 3 * WSZ, bo, X, x);
    ln_kernel<<<N_M, 256>>>(x, gamma, beta, out);
}